// round 8
// baseline (speedup 1.0000x reference)
#include <cuda_runtime.h>
#include <cuda_bf16.h>
#include <math_constants.h>
#include <cstdint>

#define B_ 2
#define T_ 2048
#define C_ 2048
#define H_ 16
#define D_ 128
#define M_ (B_*T_)   // 4096 rows

// ---------------- scratch (static device globals) ----------------
__device__ __nv_bfloat16 g_xh[(size_t)M_ * C_];
__device__ __nv_bfloat16 g_xl[(size_t)M_ * C_];
__device__ __nv_bfloat16 g_qh[(size_t)M_ * C_];
__device__ __nv_bfloat16 g_ql[(size_t)M_ * C_];
__device__ __nv_bfloat16 g_kh[(size_t)M_ * C_];
__device__ __nv_bfloat16 g_kl[(size_t)M_ * C_];
__device__ __nv_bfloat16 g_vh[(size_t)M_ * C_];
__device__ __nv_bfloat16 g_vl[(size_t)M_ * C_];
__device__ __nv_bfloat16 g_oh[(size_t)M_ * C_];
__device__ __nv_bfloat16 g_ol[(size_t)M_ * C_];
__device__ __nv_bfloat16 g_wh[4][(size_t)C_ * C_];
__device__ __nv_bfloat16 g_wl[4][(size_t)C_ * C_];

union BU { __nv_bfloat162 b; uint32_t u; };

__device__ __forceinline__ uint32_t pack_hi(float x, float y) {
    BU u; u.b = __floats2bfloat162_rn(x, y); return u.u;
}
__device__ __forceinline__ uint32_t pack_lo(float x, float y, uint32_t hi) {
    BU h; h.u = hi;
    BU u; u.b = __floats2bfloat162_rn(x - __bfloat162float(h.b.x),
                                      y - __bfloat162float(h.b.y));
    return u.u;
}

// ---------------------------------------------------------------------------
// fp32 -> bf16 hi/lo split, all 5 tensors in one launch
// ---------------------------------------------------------------------------
#define NX4 ((M_*C_)/4)
#define NW4 ((C_*C_)/4)

__global__ __launch_bounds__(256) void split_all(
    const float4* __restrict__ x,
    const float4* __restrict__ w0, const float4* __restrict__ w1,
    const float4* __restrict__ w2, const float4* __restrict__ w3,
    uint2* __restrict__ xh, uint2* __restrict__ xl,
    uint2* __restrict__ wh, uint2* __restrict__ wl)
{
    int i = blockIdx.x * blockDim.x + threadIdx.x;
    const float4* src;
    uint2 *ph, *pl;
    int off;
    if (i < NX4) {
        src = x; off = i; ph = xh; pl = xl;
    } else {
        int j = i - NX4;
        int w = j / NW4;
        off = j - w * NW4;
        src = (w == 0) ? w0 : (w == 1) ? w1 : (w == 2) ? w2 : w3;
        ph = wh + (size_t)w * NW4;
        pl = wl + (size_t)w * NW4;
    }
    float4 v = src[off];
    uint32_t h0 = pack_hi(v.x, v.y), h1 = pack_hi(v.z, v.w);
    uint32_t l0 = pack_lo(v.x, v.y, h0), l1 = pack_lo(v.z, v.w, h1);
    ph[off] = make_uint2(h0, h1);
    pl[off] = make_uint2(l0, l1);
}

// ---------------------------------------------------------------------------
// primitives
// ---------------------------------------------------------------------------
__device__ __forceinline__ void ldmx4(uint32_t &r0, uint32_t &r1, uint32_t &r2, uint32_t &r3, uint32_t addr) {
    asm volatile("ldmatrix.sync.aligned.m8n8.x4.shared.b16 {%0,%1,%2,%3}, [%4];"
                 : "=r"(r0), "=r"(r1), "=r"(r2), "=r"(r3) : "r"(addr));
}
__device__ __forceinline__ void ldmx4t(uint32_t &r0, uint32_t &r1, uint32_t &r2, uint32_t &r3, uint32_t addr) {
    asm volatile("ldmatrix.sync.aligned.m8n8.x4.trans.shared.b16 {%0,%1,%2,%3}, [%4];"
                 : "=r"(r0), "=r"(r1), "=r"(r2), "=r"(r3) : "r"(addr));
}
__device__ __forceinline__ void mma16816(float* d, const uint32_t* a, const uint32_t* b) {
    asm volatile("mma.sync.aligned.m16n8k16.row.col.f32.bf16.bf16.f32 "
                 "{%0,%1,%2,%3},{%4,%5,%6,%7},{%8,%9},{%0,%1,%2,%3};"
                 : "+f"(d[0]), "+f"(d[1]), "+f"(d[2]), "+f"(d[3])
                 : "r"(a[0]), "r"(a[1]), "r"(a[2]), "r"(a[3]), "r"(b[0]), "r"(b[1]));
}
__device__ __forceinline__ void cp16(uint32_t saddr, const void* g) {
    asm volatile("cp.async.cg.shared.global [%0], [%1], 16;" :: "r"(saddr), "l"(g));
}
__device__ __forceinline__ uint32_t swz64(uint32_t off) { return off ^ ((off >> 3) & 0x30); }

// ---------------------------------------------------------------------------
// GEMM core geometry: CTA tile 128x128, BK=32, 8 warps (32x64), 3 stages.
// ---------------------------------------------------------------------------
#define G3_SUB 8192
#define G3_STAGE (4*G3_SUB)              // 32768 B
#define G3_SMEM (3*G3_STAGE)             // 98304 B
#define FTS 133                          // fp32 staging stride (epilogue)

// One kk=16 step of the 3-term compute. B-lo ldsm placed after hh-mmas.
#define GEMM_KK_BODY(st, kk)                                                          \
    {                                                                                 \
        uint32_t ah[2][4], al[2][4], b[8][2];                                         \
        _Pragma("unroll")                                                             \
        for (int t = 0; t < 2; t++) {                                                 \
            uint32_t rb = (uint32_t)((warp_m * 32 + t * 16 + mlane) * 64 + ((kk) + aoff) * 2); \
            ldmx4(ah[t][0], ah[t][1], ah[t][2], ah[t][3], (st) + 0 * G3_SUB + swz64(rb)); \
            ldmx4(al[t][0], al[t][1], al[t][2], al[t][3], (st) + 1 * G3_SUB + swz64(rb)); \
        }                                                                             \
        _Pragma("unroll")                                                             \
        for (int jt = 0; jt < 4; jt++) {                                              \
            uint32_t rb = (uint32_t)((warp_n * 64 + jt * 16 + nlane) * 64 + ((kk) + klBo) * 2); \
            ldmx4(b[2*jt][0], b[2*jt][1], b[2*jt+1][0], b[2*jt+1][1], (st) + 2 * G3_SUB + swz64(rb)); \
        }                                                                             \
        _Pragma("unroll")                                                             \
        for (int t = 0; t < 2; t++)                                                   \
            _Pragma("unroll")                                                         \
            for (int j = 0; j < 8; j++) mma16816(acc[t][j], ah[t], b[j]);             \
        {                                                                             \
            uint32_t bl[8][2];                                                        \
            _Pragma("unroll")                                                         \
            for (int jt = 0; jt < 4; jt++) {                                          \
                uint32_t rb = (uint32_t)((warp_n * 64 + jt * 16 + nlane) * 64 + ((kk) + klBo) * 2); \
                ldmx4(bl[2*jt][0], bl[2*jt][1], bl[2*jt+1][0], bl[2*jt+1][1], (st) + 3 * G3_SUB + swz64(rb)); \
            }                                                                         \
            _Pragma("unroll")                                                         \
            for (int t = 0; t < 2; t++)                                               \
                _Pragma("unroll")                                                     \
                for (int j = 0; j < 8; j++) mma16816(acc[t][j], al[t], b[j]);         \
            _Pragma("unroll")                                                         \
            for (int t = 0; t < 2; t++)                                               \
                _Pragma("unroll")                                                     \
                for (int j = 0; j < 8; j++) mma16816(acc[t][j], ah[t], bl[j]);        \
        }                                                                             \
    }

// ---------------------------------------------------------------------------
// Fused QKV GEMM + (rmsnorm+RoPE | v split) epilogue.
// ---------------------------------------------------------------------------
__global__ __launch_bounds__(256, 2) void qkv_gemm(
    const __nv_bfloat16* __restrict__ xh, const __nv_bfloat16* __restrict__ xl,
    const __nv_bfloat16* __restrict__ wh, const __nv_bfloat16* __restrict__ wl,
    const float* __restrict__ cs, const float* __restrict__ sn,
    __nv_bfloat16* __restrict__ qh, __nv_bfloat16* __restrict__ ql,
    __nv_bfloat16* __restrict__ kh, __nv_bfloat16* __restrict__ kl,
    __nv_bfloat16* __restrict__ vh, __nv_bfloat16* __restrict__ vl)
{
    extern __shared__ __align__(1024) char smg[];
    const int tid = threadIdx.x, lane = tid & 31, wid = tid >> 5;
    const int warp_m = wid & 3;
    const int warp_n = wid >> 2;
    const int bm = blockIdx.y;
    const int kind = blockIdx.x >> 4;
    const int lbn  = blockIdx.x & 15;
    const uint32_t sb = (uint32_t)__cvta_generic_to_shared(smg);

    const __nv_bfloat16* Bh = wh + (size_t)kind * C_ * C_;
    const __nv_bfloat16* Bl = wl + (size_t)kind * C_ * C_;

    float acc[2][8][4];
    #pragma unroll
    for (int i = 0; i < 2; i++)
        #pragma unroll
        for (int j = 0; j < 8; j++)
            #pragma unroll
            for (int e = 0; e < 4; e++) acc[i][j][e] = 0.f;

    const __nv_bfloat16* srcs[4] = { xh, xl, Bh, Bl };

    auto issue = [&](int s, int k0) {
        const uint32_t st = sb + s * G3_STAGE;
        #pragma unroll
        for (int it = 0; it < 8; it++) {
            int j   = tid + it * 256;
            int sub = j >> 9;
            int cid = j & 511;
            int r   = cid >> 2;
            int ch  = cid & 3;
            int grow = (sub < 2 ? bm : lbn) * 128 + r;
            const __nv_bfloat16* g = srcs[sub] + (size_t)grow * C_ + k0 + ch * 8;
            cp16(st + sub * G3_SUB + swz64((uint32_t)(r * 64 + ch * 16)), g);
        }
        asm volatile("cp.async.commit_group;");
    };

    const int NS = C_ / 32;
    issue(0, 0);
    issue(1, 32);

    const int mlane = lane & 15;
    const int aoff  = (lane >> 4) << 3;
    const int nlane = (lane & 7) + ((lane >> 4) << 3);
    const int klBo  = ((lane >> 3) & 1) << 3;

    for (int i = 0; i < NS; i++) {
        if (i == NS - 1) { asm volatile("cp.async.wait_group 0;"); }
        else             { asm volatile("cp.async.wait_group 1;"); }
        __syncthreads();
        if (i + 2 < NS) issue((i + 2) % 3, (i + 2) * 32);

        const uint32_t st = sb + (i % 3) * G3_STAGE;
        GEMM_KK_BODY(st, 0)
        GEMM_KK_BODY(st, 16)
    }
    __syncthreads();   // all warps done with smem before epilogue reuses it

    if (kind == 2) {
        #pragma unroll
        for (int t = 0; t < 2; t++) {
            int row = bm * 128 + warp_m * 32 + t * 16 + (lane >> 2);
            #pragma unroll
            for (int j = 0; j < 8; j++) {
                int col = lbn * 128 + warp_n * 64 + j * 8 + ((lane & 3) << 1);
                uint32_t h0 = pack_hi(acc[t][j][0], acc[t][j][1]);
                uint32_t l0 = pack_lo(acc[t][j][0], acc[t][j][1], h0);
                uint32_t h1 = pack_hi(acc[t][j][2], acc[t][j][3]);
                uint32_t l1 = pack_lo(acc[t][j][2], acc[t][j][3], h1);
                *(uint32_t*)&vh[(size_t)row * C_ + col]       = h0;
                *(uint32_t*)&vl[(size_t)row * C_ + col]       = l0;
                *(uint32_t*)&vh[(size_t)(row + 8) * C_ + col] = h1;
                *(uint32_t*)&vl[(size_t)(row + 8) * C_ + col] = l1;
            }
        }
    } else {
        float* ft = (float*)smg;
        #pragma unroll
        for (int t = 0; t < 2; t++) {
            int rl0 = warp_m * 32 + t * 16 + (lane >> 2);
            #pragma unroll
            for (int j = 0; j < 8; j++) {
                int cl = warp_n * 64 + j * 8 + ((lane & 3) << 1);
                ft[rl0 * FTS + cl]           = acc[t][j][0];
                ft[rl0 * FTS + cl + 1]       = acc[t][j][1];
                ft[(rl0 + 8) * FTS + cl]     = acc[t][j][2];
                ft[(rl0 + 8) * FTS + cl + 1] = acc[t][j][3];
            }
        }
        __syncthreads();

        const int r  = tid >> 1;
        const int hh = tid & 1;
        const int cb = hh * 32;
        const float* fr = ft + r * FTS;

        float ss = 0.f;
        #pragma unroll
        for (int i2 = 0; i2 < 32; i2++) {
            float a = fr[cb + i2];
            float b = fr[cb + 64 + i2];
            ss += a * a + b * b;
        }
        ss += __shfl_xor_sync(0xffffffffu, ss, 1);
        float rms = rsqrtf(ss * (1.0f / 128.0f) + 1.1920929e-7f);

        const int grow = bm * 128 + r;
        const int t    = grow & (T_ - 1);
        __nv_bfloat16* Oh = kind ? kh : qh;
        __nv_bfloat16* Ol = kind ? kl : ql;
        const size_t rb = (size_t)grow * C_ + lbn * 128;

        #pragma unroll
        for (int i2 = 0; i2 < 32; i2 += 2) {
            int c0 = cb + i2;
            float a0 = fr[c0] * rms,     b0 = fr[c0 + 64] * rms;
            float a1 = fr[c0 + 1] * rms, b1 = fr[c0 + 65] * rms;
            float co0 = cs[t * 64 + c0], si0 = sn[t * 64 + c0];
            float co1 = cs[t * 64 + c0 + 1], si1 = sn[t * 64 + c0 + 1];
            float y10 =  a0 * co0 + b0 * si0;
            float y11 =  a1 * co1 + b1 * si1;
            float y20 = -a0 * si0 + b0 * co0;
            float y21 = -a1 * si1 + b1 * co1;
            uint32_t h1p = pack_hi(y10, y11);
            uint32_t h2p = pack_hi(y20, y21);
            *(uint32_t*)&Oh[rb + c0]      = h1p;
            *(uint32_t*)&Ol[rb + c0]      = pack_lo(y10, y11, h1p);
            *(uint32_t*)&Oh[rb + c0 + 64] = h2p;
            *(uint32_t*)&Ol[rb + c0 + 64] = pack_lo(y20, y21, h2p);
        }
    }
}

// ---------------------------------------------------------------------------
// Output-projection GEMM (fp32 out)
// ---------------------------------------------------------------------------
__global__ __launch_bounds__(256, 2) void bgemm3(
    const __nv_bfloat16* __restrict__ Ah, const __nv_bfloat16* __restrict__ Al,
    const __nv_bfloat16* __restrict__ Bh, const __nv_bfloat16* __restrict__ Bl,
    float* __restrict__ Cc, int Mm, int Nn, int K)
{
    extern __shared__ __align__(1024) char smg[];
    const int tid = threadIdx.x, lane = tid & 31, wid = tid >> 5;
    const int warp_m = wid & 3;
    const int warp_n = wid >> 2;
    const int bm = blockIdx.y, bn = blockIdx.x;
    const uint32_t sb = (uint32_t)__cvta_generic_to_shared(smg);

    float acc[2][8][4];
    #pragma unroll
    for (int i = 0; i < 2; i++)
        #pragma unroll
        for (int j = 0; j < 8; j++)
            #pragma unroll
            for (int e = 0; e < 4; e++) acc[i][j][e] = 0.f;

    const __nv_bfloat16* srcs[4] = { Ah, Al, Bh, Bl };

    auto issue = [&](int s, int k0) {
        const uint32_t st = sb + s * G3_STAGE;
        #pragma unroll
        for (int it = 0; it < 8; it++) {
            int j   = tid + it * 256;
            int sub = j >> 9;
            int cid = j & 511;
            int r   = cid >> 2;
            int ch  = cid & 3;
            int grow = (sub < 2 ? bm : bn) * 128 + r;
            const __nv_bfloat16* g = srcs[sub] + (size_t)grow * K + k0 + ch * 8;
            cp16(st + sub * G3_SUB + swz64((uint32_t)(r * 64 + ch * 16)), g);
        }
        asm volatile("cp.async.commit_group;");
    };

    const int NS = K / 32;
    issue(0, 0);
    issue(1, 32);

    const int mlane = lane & 15;
    const int aoff  = (lane >> 4) << 3;
    const int nlane = (lane & 7) + ((lane >> 4) << 3);
    const int klBo  = ((lane >> 3) & 1) << 3;

    for (int i = 0; i < NS; i++) {
        if (i == NS - 1) { asm volatile("cp.async.wait_group 0;"); }
        else             { asm volatile("cp.async.wait_group 1;"); }
        __syncthreads();
        if (i + 2 < NS) issue((i + 2) % 3, (i + 2) * 32);

        const uint32_t st = sb + (i % 3) * G3_STAGE;
        GEMM_KK_BODY(st, 0)
        GEMM_KK_BODY(st, 16)
    }

    #pragma unroll
    for (int t = 0; t < 2; t++) {
        int row = bm * 128 + warp_m * 32 + t * 16 + (lane >> 2);
        #pragma unroll
        for (int j = 0; j < 8; j++) {
            int col = bn * 128 + warp_n * 64 + j * 8 + ((lane & 3) << 1);
            *(float2*)&Cc[(size_t)row * Nn + col]       = make_float2(acc[t][j][0], acc[t][j][1]);
            *(float2*)&Cc[(size_t)(row + 8) * Nn + col] = make_float2(acc[t][j][2], acc[t][j][3]);
        }
    }
}

// ---------------------------------------------------------------------------
// Tensor-core flash attention (causal), bf16 hi/lo 3-term, fp32 accum.
// Q fragments in registers; KV 3-stage pipeline, single barrier/iter.
// ---------------------------------------------------------------------------
#define SQ 136
#define FL_STAGE (4*64*SQ)               // elems per stage
#define FL_KH 0
#define FL_KL (64*SQ)
#define FL_VH (128*SQ)
#define FL_VL (192*SQ)
#define FLASH_SMEM (3*FL_STAGE*2)        // 208896 bytes

__global__ __launch_bounds__(256, 1) void flash_bf16(
    const __nv_bfloat16* __restrict__ qh, const __nv_bfloat16* __restrict__ ql,
    const __nv_bfloat16* __restrict__ kh, const __nv_bfloat16* __restrict__ kl,
    const __nv_bfloat16* __restrict__ vh, const __nv_bfloat16* __restrict__ vl,
    __nv_bfloat16* __restrict__ oh, __nv_bfloat16* __restrict__ ol)
{
    extern __shared__ __nv_bfloat16 smf[];
    const int tid = threadIdx.x, lane = tid & 31, wid = tid >> 5;
    const int qb = gridDim.x - 1 - blockIdx.x;
    const int b  = blockIdx.y >> 4, h = blockIdx.y & 15;
    const uint32_t sb = (uint32_t)__cvta_generic_to_shared(smf);
    const size_t rowQ = (size_t)b * T_ + (size_t)qb * 128;
    const int colH = h * D_;

    const int wq = wid * 16;
    const int gq0 = qb * 128 + wq;
    const int mlane = lane & 15;
    const int aoff  = (lane >> 4) << 3;
    const int nlane = (lane & 7) + ((lane >> 4) << 3);
    const int klB   = ((lane >> 3) & 1) << 3;

    // ---- stage Q through smem, extract fragments to registers ----
    #pragma unroll
    for (int it = 0; it < 8; it++) {
        int idx = tid + it * 256;
        int r = idx >> 4, c = (idx & 15) << 3;
        size_t g = (rowQ + r) * C_ + colH + c;
        cp16(sb + 2u * (uint32_t)(r * SQ + c), qh + g);
        cp16(sb + 2u * (uint32_t)(128 * SQ + r * SQ + c), ql + g);
    }
    asm volatile("cp.async.commit_group;");
    asm volatile("cp.async.wait_group 0;");
    __syncthreads();

    uint32_t qfh[8][4], qfl[8][4];
    #pragma unroll
    for (int c = 0; c < 8; c++) {
        uint32_t ad = sb + 2u * (uint32_t)((wq + mlane) * SQ + c * 16 + aoff);
        ldmx4(qfh[c][0], qfh[c][1], qfh[c][2], qfh[c][3], ad);
        ldmx4(qfl[c][0], qfl[c][1], qfl[c][2], qfl[c][3], ad + 2u * (uint32_t)(128 * SQ));
    }
    __syncthreads();

    auto issueKV = [&](int s, int kt) {
        uint32_t st = s * FL_STAGE;
        #pragma unroll
        for (int it = 0; it < 4; it++) {
            int idx = tid + it * 256;
            int r = idx >> 4, c = (idx & 15) << 3;
            size_t g = ((size_t)b * T_ + (size_t)kt * 64 + r) * C_ + colH + c;
            uint32_t so = (uint32_t)(st + r * SQ + c);
            cp16(sb + 2u * (so + FL_KH), kh + g);
            cp16(sb + 2u * (so + FL_KL), kl + g);
            cp16(sb + 2u * (so + FL_VH), vh + g);
            cp16(sb + 2u * (so + FL_VL), vl + g);
        }
        asm volatile("cp.async.commit_group;");
    };

    const int nkt = 2 * qb + 2;   // >= 2
    issueKV(0, 0);
    issueKV(1, 1);

    const float scale = 0.088388347648318447f;

    float m0 = -CUDART_INF_F, m1 = -CUDART_INF_F, l0 = 0.f, l1 = 0.f;
    float oacc[16][4];
    #pragma unroll
    for (int j = 0; j < 16; j++)
        #pragma unroll
        for (int e = 0; e < 4; e++) oacc[j][e] = 0.f;

    for (int kt = 0; kt < nkt; kt++) {
        if (kt == nkt - 1) { asm volatile("cp.async.wait_group 0;"); }
        else               { asm volatile("cp.async.wait_group 1;"); }
        __syncthreads();
        if (kt + 2 < nkt) issueKV((kt + 2) % 3, kt + 2);

        const int kb = kt * 64;
        if (kb <= gq0 + 15) {
            const uint32_t st = (kt % 3) * FL_STAGE;

            float sacc[8][4];
            #pragma unroll
            for (int j = 0; j < 8; j++)
                #pragma unroll
                for (int e = 0; e < 4; e++) sacc[j][e] = 0.f;

            #pragma unroll
            for (int c = 0; c < 8; c++) {
                uint32_t bh2[8][2];
                #pragma unroll
                for (int jt = 0; jt < 4; jt++) {
                    uint32_t ad = sb + 2u * (uint32_t)(st + FL_KH + (jt * 16 + nlane) * SQ + c * 16 + klB);
                    ldmx4(bh2[2*jt][0], bh2[2*jt][1], bh2[2*jt+1][0], bh2[2*jt+1][1], ad);
                }
                #pragma unroll
                for (int j = 0; j < 8; j++) mma16816(sacc[j], qfh[c], bh2[j]);
                #pragma unroll
                for (int j = 0; j < 8; j++) mma16816(sacc[j], qfl[c], bh2[j]);
                #pragma unroll
                for (int jt = 0; jt < 4; jt++) {
                    uint32_t ad = sb + 2u * (uint32_t)(st + FL_KL + (jt * 16 + nlane) * SQ + c * 16 + klB);
                    ldmx4(bh2[2*jt][0], bh2[2*jt][1], bh2[2*jt+1][0], bh2[2*jt+1][1], ad);
                }
                #pragma unroll
                for (int j = 0; j < 8; j++) mma16816(sacc[j], qfh[c], bh2[j]);
            }

            const bool diag = (kb + 63 > gq0);
            const int r0 = gq0 + (lane >> 2), r1 = r0 + 8;
            float tm0 = -CUDART_INF_F, tm1 = -CUDART_INF_F;
            #pragma unroll
            for (int j = 0; j < 8; j++) {
                int cc = kb + j * 8 + ((lane & 3) << 1);
                float v0 = sacc[j][0] * scale, v1 = sacc[j][1] * scale;
                float v2 = sacc[j][2] * scale, v3 = sacc[j][3] * scale;
                if (diag) {
                    if (cc     > r0) v0 = -CUDART_INF_F;
                    if (cc + 1 > r0) v1 = -CUDART_INF_F;
                    if (cc     > r1) v2 = -CUDART_INF_F;
                    if (cc + 1 > r1) v3 = -CUDART_INF_F;
                }
                sacc[j][0] = v0; sacc[j][1] = v1; sacc[j][2] = v2; sacc[j][3] = v3;
                tm0 = fmaxf(tm0, fmaxf(v0, v1));
                tm1 = fmaxf(tm1, fmaxf(v2, v3));
            }
            tm0 = fmaxf(tm0, __shfl_xor_sync(0xffffffffu, tm0, 1));
            tm0 = fmaxf(tm0, __shfl_xor_sync(0xffffffffu, tm0, 2));
            tm1 = fmaxf(tm1, __shfl_xor_sync(0xffffffffu, tm1, 1));
            tm1 = fmaxf(tm1, __shfl_xor_sync(0xffffffffu, tm1, 2));
            float mn0 = fmaxf(m0, tm0), mn1 = fmaxf(m1, tm1);
            float a0 = __expf(m0 - mn0), a1 = __expf(m1 - mn1);
            float rs0 = 0.f, rs1 = 0.f;
            #pragma unroll
            for (int j = 0; j < 8; j++) {
                float p0 = __expf(sacc[j][0] - mn0);
                float p1 = __expf(sacc[j][1] - mn0);
                float p2 = __expf(sacc[j][2] - mn1);
                float p3 = __expf(sacc[j][3] - mn1);
                sacc[j][0] = p0; sacc[j][1] = p1; sacc[j][2] = p2; sacc[j][3] = p3;
                rs0 += p0 + p1; rs1 += p2 + p3;
            }
            rs0 += __shfl_xor_sync(0xffffffffu, rs0, 1);
            rs0 += __shfl_xor_sync(0xffffffffu, rs0, 2);
            rs1 += __shfl_xor_sync(0xffffffffu, rs1, 1);
            rs1 += __shfl_xor_sync(0xffffffffu, rs1, 2);
            l0 = l0 * a0 + rs0; l1 = l1 * a1 + rs1;
            m0 = mn0; m1 = mn1;
            #pragma unroll
            for (int j = 0; j < 16; j++) {
                oacc[j][0] *= a0; oacc[j][1] *= a0;
                oacc[j][2] *= a1; oacc[j][3] *= a1;
            }

            uint32_t ph[4][4], pl[4][4];
            #pragma unroll
            for (int c = 0; c < 4; c++) {
                ph[c][0] = pack_hi(sacc[2*c][0],   sacc[2*c][1]);
                pl[c][0] = pack_lo(sacc[2*c][0],   sacc[2*c][1],   ph[c][0]);
                ph[c][1] = pack_hi(sacc[2*c][2],   sacc[2*c][3]);
                pl[c][1] = pack_lo(sacc[2*c][2],   sacc[2*c][3],   ph[c][1]);
                ph[c][2] = pack_hi(sacc[2*c+1][0], sacc[2*c+1][1]);
                pl[c][2] = pack_lo(sacc[2*c+1][0], sacc[2*c+1][1], ph[c][2]);
                ph[c][3] = pack_hi(sacc[2*c+1][2], sacc[2*c+1][3]);
                pl[c][3] = pack_lo(sacc[2*c+1][2], sacc[2*c+1][3], ph[c][3]);
            }

            const int vrow = ((lane >> 3) & 1) * 8 + (lane & 7);
            const int vcol = (lane >> 4) << 3;
            #pragma unroll
            for (int c = 0; c < 4; c++) {
                #pragma unroll
                for (int dt = 0; dt < 8; dt++) {
                    uint32_t bv[4];
                    uint32_t ad = sb + 2u * (uint32_t)(st + FL_VH + (c * 16 + vrow) * SQ + dt * 16 + vcol);
                    ldmx4t(bv[0], bv[1], bv[2], bv[3], ad);
                    mma16816(oacc[2*dt],   ph[c], bv);
                    mma16816(oacc[2*dt+1], ph[c], bv + 2);
                    mma16816(oacc[2*dt],   pl[c], bv);
                    mma16816(oacc[2*dt+1], pl[c], bv + 2);
                }
                #pragma unroll
                for (int dt = 0; dt < 8; dt++) {
                    uint32_t bv[4];
                    uint32_t ad = sb + 2u * (uint32_t)(st + FL_VL + (c * 16 + vrow) * SQ + dt * 16 + vcol);
                    ldmx4t(bv[0], bv[1], bv[2], bv[3], ad);
                    mma16816(oacc[2*dt],   ph[c], bv);
                    mma16816(oacc[2*dt+1], ph[c], bv + 2);
                }
            }
        }
    }

    float inv0 = 1.0f / l0, inv1 = 1.0f / l1;
    size_t grow0 = (rowQ + wq + (lane >> 2)) * C_;
    size_t grow1 = grow0 + 8 * C_;
    #pragma unroll
    for (int j = 0; j < 16; j++) {
        int col = colH + j * 8 + ((lane & 3) << 1);
        float f0 = oacc[j][0] * inv0, f1 = oacc[j][1] * inv0;
        float f2 = oacc[j][2] * inv1, f3 = oacc[j][3] * inv1;
        uint32_t h0 = pack_hi(f0, f1), h1 = pack_hi(f2, f3);
        *(uint32_t*)&oh[grow0 + col] = h0;
        *(uint32_t*)&ol[grow0 + col] = pack_lo(f0, f1, h0);
        *(uint32_t*)&oh[grow1 + col] = h1;
        *(uint32_t*)&ol[grow1 + col] = pack_lo(f2, f3, h1);
    }
}

// ---------------------------------------------------------------------------
extern "C" void kernel_launch(void* const* d_in, const int* in_sizes, int n_in,
                              void* d_out, int out_size)
{
    (void)in_sizes; (void)n_in; (void)out_size;
    const float* x  = (const float*)d_in[0];
    const float* cs = (const float*)d_in[1];
    const float* sn = (const float*)d_in[2];
    float* out = (float*)d_out;

    __nv_bfloat16 *xh, *xl, *qh, *ql, *kh, *kl, *vh, *vl, *oh, *ol, *wh, *wl;
    cudaGetSymbolAddress((void**)&xh, g_xh);
    cudaGetSymbolAddress((void**)&xl, g_xl);
    cudaGetSymbolAddress((void**)&qh, g_qh);
    cudaGetSymbolAddress((void**)&ql, g_ql);
    cudaGetSymbolAddress((void**)&kh, g_kh);
    cudaGetSymbolAddress((void**)&kl, g_kl);
    cudaGetSymbolAddress((void**)&vh, g_vh);
    cudaGetSymbolAddress((void**)&vl, g_vl);
    cudaGetSymbolAddress((void**)&oh, g_oh);
    cudaGetSymbolAddress((void**)&ol, g_ol);
    cudaGetSymbolAddress((void**)&wh, g_wh);
    cudaGetSymbolAddress((void**)&wl, g_wl);

    cudaFuncSetAttribute(qkv_gemm, cudaFuncAttributeMaxDynamicSharedMemorySize, G3_SMEM);
    cudaFuncSetAttribute(bgemm3,   cudaFuncAttributeMaxDynamicSharedMemorySize, G3_SMEM);
    cudaFuncSetAttribute(flash_bf16, cudaFuncAttributeMaxDynamicSharedMemorySize, FLASH_SMEM);

    const int ntot = NX4 + 4 * NW4;
    split_all<<<ntot / 256, 256>>>((const float4*)x,
        (const float4*)d_in[3], (const float4*)d_in[4],
        (const float4*)d_in[5], (const float4*)d_in[6],
        (uint2*)xh, (uint2*)xl, (uint2*)wh, (uint2*)wl);

    qkv_gemm<<<dim3(48, 32), 256, G3_SMEM>>>(xh, xl, wh, wl, cs, sn,
                                             qh, ql, kh, kl, vh, vl);

    flash_bf16<<<dim3(T_/128, B_*H_), 256, FLASH_SMEM>>>(qh, ql, kh, kl, vh, vl, oh, ol);

    bgemm3<<<dim3(16, 32), 256, G3_SMEM>>>(oh, ol, wh + 3*(size_t)C_*C_, wl + 3*(size_t)C_*C_,
                                           out, M_, C_, C_);
}

// round 9
// speedup vs baseline: 1.2605x; 1.2605x over previous
#include <cuda_runtime.h>
#include <cuda_bf16.h>
#include <cuda_fp16.h>
#include <math_constants.h>
#include <cstdint>

#define B_ 2
#define T_ 2048
#define C_ 2048
#define H_ 16
#define D_ 128
#define M_ (B_*T_)   // 4096 rows

// ---------------- scratch (static device globals) ----------------
__device__ __nv_bfloat16 g_xh[(size_t)M_ * C_];
__device__ __nv_bfloat16 g_xl[(size_t)M_ * C_];
__device__ __half        g_xf[(size_t)M_ * C_];
__device__ __nv_bfloat16 g_qh[(size_t)M_ * C_];
__device__ __nv_bfloat16 g_ql[(size_t)M_ * C_];
__device__ __nv_bfloat16 g_kh[(size_t)M_ * C_];
__device__ __nv_bfloat16 g_kl[(size_t)M_ * C_];
__device__ __nv_bfloat16 g_vh[(size_t)M_ * C_];
__device__ __nv_bfloat16 g_vl[(size_t)M_ * C_];
__device__ __half        g_of[(size_t)M_ * C_];
__device__ __nv_bfloat16 g_wh[2][(size_t)C_ * C_];   // Wq, Wk hi
__device__ __nv_bfloat16 g_wl[2][(size_t)C_ * C_];   // Wq, Wk lo
__device__ __half        g_w2f[(size_t)C_ * C_];     // Wv fp16
__device__ __half        g_w3f[(size_t)C_ * C_];     // Wo fp16

union BU { __nv_bfloat162 b; uint32_t u; };
union HU { __half2 h; uint32_t u; };

__device__ __forceinline__ uint32_t pack_hi(float x, float y) {
    BU u; u.b = __floats2bfloat162_rn(x, y); return u.u;
}
__device__ __forceinline__ uint32_t pack_lo(float x, float y, uint32_t hi) {
    BU h; h.u = hi;
    BU u; u.b = __floats2bfloat162_rn(x - __bfloat162float(h.b.x),
                                      y - __bfloat162float(h.b.y));
    return u.u;
}
__device__ __forceinline__ uint32_t pack_f16(float x, float y) {
    HU u; u.h = __floats2half2_rn(x, y); return u.u;
}

// ---------------------------------------------------------------------------
// split kernel: x -> bf16 hi/lo + fp16 ; W0,W1 -> bf16 hi/lo ; W2,W3 -> fp16
// ---------------------------------------------------------------------------
#define NX4 ((M_*C_)/4)
#define NW4 ((C_*C_)/4)

__global__ __launch_bounds__(256) void split_all(
    const float4* __restrict__ x,
    const float4* __restrict__ w0, const float4* __restrict__ w1,
    const float4* __restrict__ w2, const float4* __restrict__ w3,
    uint2* __restrict__ xh, uint2* __restrict__ xl, uint2* __restrict__ xf,
    uint2* __restrict__ wh, uint2* __restrict__ wl,
    uint2* __restrict__ w2f, uint2* __restrict__ w3f)
{
    int i = blockIdx.x * blockDim.x + threadIdx.x;
    if (i < NX4) {
        float4 v = x[i];
        uint32_t h0 = pack_hi(v.x, v.y), h1 = pack_hi(v.z, v.w);
        xh[i] = make_uint2(h0, h1);
        xl[i] = make_uint2(pack_lo(v.x, v.y, h0), pack_lo(v.z, v.w, h1));
        xf[i] = make_uint2(pack_f16(v.x, v.y), pack_f16(v.z, v.w));
        return;
    }
    int j = i - NX4;
    int w = j / NW4;
    int off = j - w * NW4;
    if (w < 2) {
        float4 v = (w == 0 ? w0 : w1)[off];
        uint2* ph = wh + (size_t)w * NW4;
        uint2* pl = wl + (size_t)w * NW4;
        uint32_t h0 = pack_hi(v.x, v.y), h1 = pack_hi(v.z, v.w);
        ph[off] = make_uint2(h0, h1);
        pl[off] = make_uint2(pack_lo(v.x, v.y, h0), pack_lo(v.z, v.w, h1));
    } else {
        float4 v = (w == 2 ? w2 : w3)[off];
        uint2* pf = (w == 2) ? w2f : w3f;
        pf[off] = make_uint2(pack_f16(v.x, v.y), pack_f16(v.z, v.w));
    }
}

// ---------------------------------------------------------------------------
// primitives
// ---------------------------------------------------------------------------
__device__ __forceinline__ void ldmx4(uint32_t &r0, uint32_t &r1, uint32_t &r2, uint32_t &r3, uint32_t addr) {
    asm volatile("ldmatrix.sync.aligned.m8n8.x4.shared.b16 {%0,%1,%2,%3}, [%4];"
                 : "=r"(r0), "=r"(r1), "=r"(r2), "=r"(r3) : "r"(addr));
}
__device__ __forceinline__ void ldmx4t(uint32_t &r0, uint32_t &r1, uint32_t &r2, uint32_t &r3, uint32_t addr) {
    asm volatile("ldmatrix.sync.aligned.m8n8.x4.trans.shared.b16 {%0,%1,%2,%3}, [%4];"
                 : "=r"(r0), "=r"(r1), "=r"(r2), "=r"(r3) : "r"(addr));
}
__device__ __forceinline__ void mma16816(float* d, const uint32_t* a, const uint32_t* b) {
    asm volatile("mma.sync.aligned.m16n8k16.row.col.f32.bf16.bf16.f32 "
                 "{%0,%1,%2,%3},{%4,%5,%6,%7},{%8,%9},{%0,%1,%2,%3};"
                 : "+f"(d[0]), "+f"(d[1]), "+f"(d[2]), "+f"(d[3])
                 : "r"(a[0]), "r"(a[1]), "r"(a[2]), "r"(a[3]), "r"(b[0]), "r"(b[1]));
}
__device__ __forceinline__ void mmah16(float* d, const uint32_t* a, const uint32_t* b) {
    asm volatile("mma.sync.aligned.m16n8k16.row.col.f32.f16.f16.f32 "
                 "{%0,%1,%2,%3},{%4,%5,%6,%7},{%8,%9},{%0,%1,%2,%3};"
                 : "+f"(d[0]), "+f"(d[1]), "+f"(d[2]), "+f"(d[3])
                 : "r"(a[0]), "r"(a[1]), "r"(a[2]), "r"(a[3]), "r"(b[0]), "r"(b[1]));
}
__device__ __forceinline__ void cp16(uint32_t saddr, const void* g) {
    asm volatile("cp.async.cg.shared.global [%0], [%1], 16;" :: "r"(saddr), "l"(g));
}
__device__ __forceinline__ uint32_t swz64(uint32_t off) { return off ^ ((off >> 3) & 0x30); }

// ---------------------------------------------------------------------------
// bf16 3-term GEMM geometry (q,k path): 128x128 tile, BK=32, 3 stages.
// ---------------------------------------------------------------------------
#define G3_SUB 8192
#define G3_STAGE (4*G3_SUB)              // 32768 B
#define G3_SMEM (3*G3_STAGE)             // 98304 B
#define FTS 133

#define GEMM_KK_BODY(st, kk)                                                          \
    {                                                                                 \
        uint32_t ah[2][4], al[2][4], b[8][2];                                         \
        _Pragma("unroll")                                                             \
        for (int t = 0; t < 2; t++) {                                                 \
            uint32_t rb = (uint32_t)((warp_m * 32 + t * 16 + mlane) * 64 + ((kk) + aoff) * 2); \
            ldmx4(ah[t][0], ah[t][1], ah[t][2], ah[t][3], (st) + 0 * G3_SUB + swz64(rb)); \
            ldmx4(al[t][0], al[t][1], al[t][2], al[t][3], (st) + 1 * G3_SUB + swz64(rb)); \
        }                                                                             \
        _Pragma("unroll")                                                             \
        for (int jt = 0; jt < 4; jt++) {                                              \
            uint32_t rb = (uint32_t)((warp_n * 64 + jt * 16 + nlane) * 64 + ((kk) + klBo) * 2); \
            ldmx4(b[2*jt][0], b[2*jt][1], b[2*jt+1][0], b[2*jt+1][1], (st) + 2 * G3_SUB + swz64(rb)); \
        }                                                                             \
        _Pragma("unroll")                                                             \
        for (int t = 0; t < 2; t++)                                                   \
            _Pragma("unroll")                                                         \
            for (int j = 0; j < 8; j++) mma16816(acc[t][j], ah[t], b[j]);             \
        {                                                                             \
            uint32_t bl[8][2];                                                        \
            _Pragma("unroll")                                                         \
            for (int jt = 0; jt < 4; jt++) {                                          \
                uint32_t rb = (uint32_t)((warp_n * 64 + jt * 16 + nlane) * 64 + ((kk) + klBo) * 2); \
                ldmx4(bl[2*jt][0], bl[2*jt][1], bl[2*jt+1][0], bl[2*jt+1][1], (st) + 3 * G3_SUB + swz64(rb)); \
            }                                                                         \
            _Pragma("unroll")                                                         \
            for (int t = 0; t < 2; t++)                                               \
                _Pragma("unroll")                                                     \
                for (int j = 0; j < 8; j++) mma16816(acc[t][j], al[t], b[j]);         \
            _Pragma("unroll")                                                         \
            for (int t = 0; t < 2; t++)                                               \
                _Pragma("unroll")                                                     \
                for (int j = 0; j < 8; j++) mma16816(acc[t][j], ah[t], bl[j]);        \
        }                                                                             \
    }

// ---------------------------------------------------------------------------
// Q/K GEMM (bf16 3-term) + rmsnorm/RoPE epilogue. grid (32, 32).
// ---------------------------------------------------------------------------
__global__ __launch_bounds__(256, 2) void qk_gemm(
    const __nv_bfloat16* __restrict__ xh, const __nv_bfloat16* __restrict__ xl,
    const __nv_bfloat16* __restrict__ wh, const __nv_bfloat16* __restrict__ wl,
    const float* __restrict__ cs, const float* __restrict__ sn,
    __nv_bfloat16* __restrict__ qh, __nv_bfloat16* __restrict__ ql,
    __nv_bfloat16* __restrict__ kh, __nv_bfloat16* __restrict__ kl)
{
    extern __shared__ __align__(1024) char smg[];
    const int tid = threadIdx.x, lane = tid & 31, wid = tid >> 5;
    const int warp_m = wid & 3;
    const int warp_n = wid >> 2;
    const int bm = blockIdx.y;
    const int kind = blockIdx.x >> 4;    // 0=q, 1=k
    const int lbn  = blockIdx.x & 15;    // head
    const uint32_t sb = (uint32_t)__cvta_generic_to_shared(smg);

    const __nv_bfloat16* Bh = wh + (size_t)kind * C_ * C_;
    const __nv_bfloat16* Bl = wl + (size_t)kind * C_ * C_;

    float acc[2][8][4];
    #pragma unroll
    for (int i = 0; i < 2; i++)
        #pragma unroll
        for (int j = 0; j < 8; j++)
            #pragma unroll
            for (int e = 0; e < 4; e++) acc[i][j][e] = 0.f;

    const __nv_bfloat16* srcs[4] = { xh, xl, Bh, Bl };

    auto issue = [&](int s, int k0) {
        const uint32_t st = sb + s * G3_STAGE;
        #pragma unroll
        for (int it = 0; it < 8; it++) {
            int j   = tid + it * 256;
            int sub = j >> 9;
            int cid = j & 511;
            int r   = cid >> 2;
            int ch  = cid & 3;
            int grow = (sub < 2 ? bm : lbn) * 128 + r;
            const __nv_bfloat16* g = srcs[sub] + (size_t)grow * C_ + k0 + ch * 8;
            cp16(st + sub * G3_SUB + swz64((uint32_t)(r * 64 + ch * 16)), g);
        }
        asm volatile("cp.async.commit_group;");
    };

    const int NS = C_ / 32;
    issue(0, 0);
    issue(1, 32);

    const int mlane = lane & 15;
    const int aoff  = (lane >> 4) << 3;
    const int nlane = (lane & 7) + ((lane >> 4) << 3);
    const int klBo  = ((lane >> 3) & 1) << 3;

    for (int i = 0; i < NS; i++) {
        if (i == NS - 1) { asm volatile("cp.async.wait_group 0;"); }
        else             { asm volatile("cp.async.wait_group 1;"); }
        __syncthreads();
        if (i + 2 < NS) issue((i + 2) % 3, (i + 2) * 32);

        const uint32_t st = sb + (i % 3) * G3_STAGE;
        GEMM_KK_BODY(st, 0)
        GEMM_KK_BODY(st, 16)
    }
    __syncthreads();

    // rmsnorm + rope epilogue via smem staging
    float* ft = (float*)smg;
    #pragma unroll
    for (int t = 0; t < 2; t++) {
        int rl0 = warp_m * 32 + t * 16 + (lane >> 2);
        #pragma unroll
        for (int j = 0; j < 8; j++) {
            int cl = warp_n * 64 + j * 8 + ((lane & 3) << 1);
            ft[rl0 * FTS + cl]           = acc[t][j][0];
            ft[rl0 * FTS + cl + 1]       = acc[t][j][1];
            ft[(rl0 + 8) * FTS + cl]     = acc[t][j][2];
            ft[(rl0 + 8) * FTS + cl + 1] = acc[t][j][3];
        }
    }
    __syncthreads();

    const int r  = tid >> 1;
    const int hh = tid & 1;
    const int cb = hh * 32;
    const float* fr = ft + r * FTS;

    float ss = 0.f;
    #pragma unroll
    for (int i2 = 0; i2 < 32; i2++) {
        float a = fr[cb + i2];
        float b = fr[cb + 64 + i2];
        ss += a * a + b * b;
    }
    ss += __shfl_xor_sync(0xffffffffu, ss, 1);
    float rms = rsqrtf(ss * (1.0f / 128.0f) + 1.1920929e-7f);

    const int grow = bm * 128 + r;
    const int t    = grow & (T_ - 1);
    __nv_bfloat16* Oh = kind ? kh : qh;
    __nv_bfloat16* Ol = kind ? kl : ql;
    const size_t rb = (size_t)grow * C_ + lbn * 128;

    #pragma unroll
    for (int i2 = 0; i2 < 32; i2 += 2) {
        int c0 = cb + i2;
        float a0 = fr[c0] * rms,     b0 = fr[c0 + 64] * rms;
        float a1 = fr[c0 + 1] * rms, b1 = fr[c0 + 65] * rms;
        float co0 = cs[t * 64 + c0], si0 = sn[t * 64 + c0];
        float co1 = cs[t * 64 + c0 + 1], si1 = sn[t * 64 + c0 + 1];
        float y10 =  a0 * co0 + b0 * si0;
        float y11 =  a1 * co1 + b1 * si1;
        float y20 = -a0 * si0 + b0 * co0;
        float y21 = -a1 * si1 + b1 * co1;
        uint32_t h1p = pack_hi(y10, y11);
        uint32_t h2p = pack_hi(y20, y21);
        *(uint32_t*)&Oh[rb + c0]      = h1p;
        *(uint32_t*)&Ol[rb + c0]      = pack_lo(y10, y11, h1p);
        *(uint32_t*)&Oh[rb + c0 + 64] = h2p;
        *(uint32_t*)&Ol[rb + c0 + 64] = pack_lo(y20, y21, h2p);
    }
}

// ---------------------------------------------------------------------------
// fp16 single-term GEMM: C[M,N] = A[M,K] @ B[N,K]^T.
// 128x128 tile, BK=32, 4-stage. OMODE 0: fp32 out. OMODE 1: bf16 hi/lo out.
// ---------------------------------------------------------------------------
#define H_SUB 8192
#define H_STAGE (2*H_SUB)                // 16384 B
#define H_SMEM (4*H_STAGE)               // 65536 B

template<int OMODE>
__global__ __launch_bounds__(256, 2) void hgemm(
    const __half* __restrict__ Af, const __half* __restrict__ Bf,
    float* __restrict__ Cc, __nv_bfloat16* __restrict__ Ch, __nv_bfloat16* __restrict__ Cl,
    int Nn, int K)
{
    extern __shared__ __align__(1024) char smg[];
    const int tid = threadIdx.x, lane = tid & 31, wid = tid >> 5;
    const int warp_m = wid & 3;
    const int warp_n = wid >> 2;
    const int bm = blockIdx.y, bn = blockIdx.x;
    const uint32_t sb = (uint32_t)__cvta_generic_to_shared(smg);

    float acc[2][8][4];
    #pragma unroll
    for (int i = 0; i < 2; i++)
        #pragma unroll
        for (int j = 0; j < 8; j++)
            #pragma unroll
            for (int e = 0; e < 4; e++) acc[i][j][e] = 0.f;

    auto issue = [&](int s, int k0) {
        const uint32_t st = sb + s * H_STAGE;
        #pragma unroll
        for (int it = 0; it < 4; it++) {
            int j   = tid + it * 256;
            int sub = j >> 9;            // 0=A, 1=B
            int cid = j & 511;
            int r   = cid >> 2;
            int ch  = cid & 3;
            int grow = (sub ? bn : bm) * 128 + r;
            const __half* g = (sub ? Bf : Af) + (size_t)grow * K + k0 + ch * 8;
            cp16(st + sub * H_SUB + swz64((uint32_t)(r * 64 + ch * 16)), g);
        }
        asm volatile("cp.async.commit_group;");
    };

    const int NS = K / 32;   // 64
    issue(0, 0); issue(1, 32); issue(2, 64);

    const int mlane = lane & 15;
    const int aoff  = (lane >> 4) << 3;
    const int nlane = (lane & 7) + ((lane >> 4) << 3);
    const int klBo  = ((lane >> 3) & 1) << 3;

    for (int i = 0; i < NS; i++) {
        if (i + 3 < NS) { asm volatile("cp.async.wait_group 2;"); }
        else            { asm volatile("cp.async.wait_group 0;"); }
        __syncthreads();
        if (i + 3 < NS) issue((i + 3) & 3, (i + 3) * 32);

        const uint32_t st = sb + (i & 3) * H_STAGE;
        #pragma unroll
        for (int kk = 0; kk < 32; kk += 16) {
            uint32_t a[2][4], b[8][2];
            #pragma unroll
            for (int t = 0; t < 2; t++) {
                uint32_t rb = (uint32_t)((warp_m * 32 + t * 16 + mlane) * 64 + (kk + aoff) * 2);
                ldmx4(a[t][0], a[t][1], a[t][2], a[t][3], st + swz64(rb));
            }
            #pragma unroll
            for (int jt = 0; jt < 4; jt++) {
                uint32_t rb = (uint32_t)((warp_n * 64 + jt * 16 + nlane) * 64 + (kk + klBo) * 2);
                ldmx4(b[2*jt][0], b[2*jt][1], b[2*jt+1][0], b[2*jt+1][1], st + H_SUB + swz64(rb));
            }
            #pragma unroll
            for (int t = 0; t < 2; t++)
                #pragma unroll
                for (int j = 0; j < 8; j++) mmah16(acc[t][j], a[t], b[j]);
        }
        __syncthreads();
    }

    #pragma unroll
    for (int t = 0; t < 2; t++) {
        int row = bm * 128 + warp_m * 32 + t * 16 + (lane >> 2);
        #pragma unroll
        for (int j = 0; j < 8; j++) {
            int col = bn * 128 + warp_n * 64 + j * 8 + ((lane & 3) << 1);
            if (OMODE == 0) {
                *(float2*)&Cc[(size_t)row * Nn + col]       = make_float2(acc[t][j][0], acc[t][j][1]);
                *(float2*)&Cc[(size_t)(row + 8) * Nn + col] = make_float2(acc[t][j][2], acc[t][j][3]);
            } else {
                uint32_t h0 = pack_hi(acc[t][j][0], acc[t][j][1]);
                uint32_t l0 = pack_lo(acc[t][j][0], acc[t][j][1], h0);
                uint32_t h1 = pack_hi(acc[t][j][2], acc[t][j][3]);
                uint32_t l1 = pack_lo(acc[t][j][2], acc[t][j][3], h1);
                *(uint32_t*)&Ch[(size_t)row * Nn + col]       = h0;
                *(uint32_t*)&Cl[(size_t)row * Nn + col]       = l0;
                *(uint32_t*)&Ch[(size_t)(row + 8) * Nn + col] = h1;
                *(uint32_t*)&Cl[(size_t)(row + 8) * Nn + col] = l1;
            }
        }
    }
}

// ---------------------------------------------------------------------------
// Tensor-core flash attention (causal), bf16 hi/lo 3-term, fp32 accum.
// Q fragments in registers; KV 3-stage pipeline. Epilogue writes fp16 o.
// ---------------------------------------------------------------------------
#define SQ 136
#define FL_STAGE (4*64*SQ)
#define FL_KH 0
#define FL_KL (64*SQ)
#define FL_VH (128*SQ)
#define FL_VL (192*SQ)
#define FLASH_SMEM (3*FL_STAGE*2)        // 208896 bytes

__global__ __launch_bounds__(256, 1) void flash_bf16(
    const __nv_bfloat16* __restrict__ qh, const __nv_bfloat16* __restrict__ ql,
    const __nv_bfloat16* __restrict__ kh, const __nv_bfloat16* __restrict__ kl,
    const __nv_bfloat16* __restrict__ vh, const __nv_bfloat16* __restrict__ vl,
    __half* __restrict__ of)
{
    extern __shared__ __nv_bfloat16 smf[];
    const int tid = threadIdx.x, lane = tid & 31, wid = tid >> 5;
    const int qb = gridDim.x - 1 - blockIdx.x;
    const int b  = blockIdx.y >> 4, h = blockIdx.y & 15;
    const uint32_t sb = (uint32_t)__cvta_generic_to_shared(smf);
    const size_t rowQ = (size_t)b * T_ + (size_t)qb * 128;
    const int colH = h * D_;

    const int wq = wid * 16;
    const int gq0 = qb * 128 + wq;
    const int mlane = lane & 15;
    const int aoff  = (lane >> 4) << 3;
    const int nlane = (lane & 7) + ((lane >> 4) << 3);
    const int klB   = ((lane >> 3) & 1) << 3;

    #pragma unroll
    for (int it = 0; it < 8; it++) {
        int idx = tid + it * 256;
        int r = idx >> 4, c = (idx & 15) << 3;
        size_t g = (rowQ + r) * C_ + colH + c;
        cp16(sb + 2u * (uint32_t)(r * SQ + c), qh + g);
        cp16(sb + 2u * (uint32_t)(128 * SQ + r * SQ + c), ql + g);
    }
    asm volatile("cp.async.commit_group;");
    asm volatile("cp.async.wait_group 0;");
    __syncthreads();

    uint32_t qfh[8][4], qfl[8][4];
    #pragma unroll
    for (int c = 0; c < 8; c++) {
        uint32_t ad = sb + 2u * (uint32_t)((wq + mlane) * SQ + c * 16 + aoff);
        ldmx4(qfh[c][0], qfh[c][1], qfh[c][2], qfh[c][3], ad);
        ldmx4(qfl[c][0], qfl[c][1], qfl[c][2], qfl[c][3], ad + 2u * (uint32_t)(128 * SQ));
    }
    __syncthreads();

    auto issueKV = [&](int s, int kt) {
        uint32_t st = s * FL_STAGE;
        #pragma unroll
        for (int it = 0; it < 4; it++) {
            int idx = tid + it * 256;
            int r = idx >> 4, c = (idx & 15) << 3;
            size_t g = ((size_t)b * T_ + (size_t)kt * 64 + r) * C_ + colH + c;
            uint32_t so = (uint32_t)(st + r * SQ + c);
            cp16(sb + 2u * (so + FL_KH), kh + g);
            cp16(sb + 2u * (so + FL_KL), kl + g);
            cp16(sb + 2u * (so + FL_VH), vh + g);
            cp16(sb + 2u * (so + FL_VL), vl + g);
        }
        asm volatile("cp.async.commit_group;");
    };

    const int nkt = 2 * qb + 2;
    issueKV(0, 0);
    issueKV(1, 1);

    const float scale = 0.088388347648318447f;

    float m0 = -CUDART_INF_F, m1 = -CUDART_INF_F, l0 = 0.f, l1 = 0.f;
    float oacc[16][4];
    #pragma unroll
    for (int j = 0; j < 16; j++)
        #pragma unroll
        for (int e = 0; e < 4; e++) oacc[j][e] = 0.f;

    for (int kt = 0; kt < nkt; kt++) {
        if (kt == nkt - 1) { asm volatile("cp.async.wait_group 0;"); }
        else               { asm volatile("cp.async.wait_group 1;"); }
        __syncthreads();
        if (kt + 2 < nkt) issueKV((kt + 2) % 3, kt + 2);

        const int kb = kt * 64;
        if (kb <= gq0 + 15) {
            const uint32_t st = (kt % 3) * FL_STAGE;

            float sacc[8][4];
            #pragma unroll
            for (int j = 0; j < 8; j++)
                #pragma unroll
                for (int e = 0; e < 4; e++) sacc[j][e] = 0.f;

            #pragma unroll
            for (int c = 0; c < 8; c++) {
                uint32_t bh2[8][2];
                #pragma unroll
                for (int jt = 0; jt < 4; jt++) {
                    uint32_t ad = sb + 2u * (uint32_t)(st + FL_KH + (jt * 16 + nlane) * SQ + c * 16 + klB);
                    ldmx4(bh2[2*jt][0], bh2[2*jt][1], bh2[2*jt+1][0], bh2[2*jt+1][1], ad);
                }
                #pragma unroll
                for (int j = 0; j < 8; j++) mma16816(sacc[j], qfh[c], bh2[j]);
                #pragma unroll
                for (int j = 0; j < 8; j++) mma16816(sacc[j], qfl[c], bh2[j]);
                #pragma unroll
                for (int jt = 0; jt < 4; jt++) {
                    uint32_t ad = sb + 2u * (uint32_t)(st + FL_KL + (jt * 16 + nlane) * SQ + c * 16 + klB);
                    ldmx4(bh2[2*jt][0], bh2[2*jt][1], bh2[2*jt+1][0], bh2[2*jt+1][1], ad);
                }
                #pragma unroll
                for (int j = 0; j < 8; j++) mma16816(sacc[j], qfh[c], bh2[j]);
            }

            const bool diag = (kb + 63 > gq0);
            const int r0 = gq0 + (lane >> 2), r1 = r0 + 8;
            float tm0 = -CUDART_INF_F, tm1 = -CUDART_INF_F;
            #pragma unroll
            for (int j = 0; j < 8; j++) {
                int cc = kb + j * 8 + ((lane & 3) << 1);
                float v0 = sacc[j][0] * scale, v1 = sacc[j][1] * scale;
                float v2 = sacc[j][2] * scale, v3 = sacc[j][3] * scale;
                if (diag) {
                    if (cc     > r0) v0 = -CUDART_INF_F;
                    if (cc + 1 > r0) v1 = -CUDART_INF_F;
                    if (cc     > r1) v2 = -CUDART_INF_F;
                    if (cc + 1 > r1) v3 = -CUDART_INF_F;
                }
                sacc[j][0] = v0; sacc[j][1] = v1; sacc[j][2] = v2; sacc[j][3] = v3;
                tm0 = fmaxf(tm0, fmaxf(v0, v1));
                tm1 = fmaxf(tm1, fmaxf(v2, v3));
            }
            tm0 = fmaxf(tm0, __shfl_xor_sync(0xffffffffu, tm0, 1));
            tm0 = fmaxf(tm0, __shfl_xor_sync(0xffffffffu, tm0, 2));
            tm1 = fmaxf(tm1, __shfl_xor_sync(0xffffffffu, tm1, 1));
            tm1 = fmaxf(tm1, __shfl_xor_sync(0xffffffffu, tm1, 2));
            float mn0 = fmaxf(m0, tm0), mn1 = fmaxf(m1, tm1);
            float a0 = __expf(m0 - mn0), a1 = __expf(m1 - mn1);
            float rs0 = 0.f, rs1 = 0.f;
            #pragma unroll
            for (int j = 0; j < 8; j++) {
                float p0 = __expf(sacc[j][0] - mn0);
                float p1 = __expf(sacc[j][1] - mn0);
                float p2 = __expf(sacc[j][2] - mn1);
                float p3 = __expf(sacc[j][3] - mn1);
                sacc[j][0] = p0; sacc[j][1] = p1; sacc[j][2] = p2; sacc[j][3] = p3;
                rs0 += p0 + p1; rs1 += p2 + p3;
            }
            rs0 += __shfl_xor_sync(0xffffffffu, rs0, 1);
            rs0 += __shfl_xor_sync(0xffffffffu, rs0, 2);
            rs1 += __shfl_xor_sync(0xffffffffu, rs1, 1);
            rs1 += __shfl_xor_sync(0xffffffffu, rs1, 2);
            l0 = l0 * a0 + rs0; l1 = l1 * a1 + rs1;
            m0 = mn0; m1 = mn1;
            #pragma unroll
            for (int j = 0; j < 16; j++) {
                oacc[j][0] *= a0; oacc[j][1] *= a0;
                oacc[j][2] *= a1; oacc[j][3] *= a1;
            }

            uint32_t ph[4][4], pl[4][4];
            #pragma unroll
            for (int c = 0; c < 4; c++) {
                ph[c][0] = pack_hi(sacc[2*c][0],   sacc[2*c][1]);
                pl[c][0] = pack_lo(sacc[2*c][0],   sacc[2*c][1],   ph[c][0]);
                ph[c][1] = pack_hi(sacc[2*c][2],   sacc[2*c][3]);
                pl[c][1] = pack_lo(sacc[2*c][2],   sacc[2*c][3],   ph[c][1]);
                ph[c][2] = pack_hi(sacc[2*c+1][0], sacc[2*c+1][1]);
                pl[c][2] = pack_lo(sacc[2*c+1][0], sacc[2*c+1][1], ph[c][2]);
                ph[c][3] = pack_hi(sacc[2*c+1][2], sacc[2*c+1][3]);
                pl[c][3] = pack_lo(sacc[2*c+1][2], sacc[2*c+1][3], ph[c][3]);
            }

            const int vrow = ((lane >> 3) & 1) * 8 + (lane & 7);
            const int vcol = (lane >> 4) << 3;
            #pragma unroll
            for (int c = 0; c < 4; c++) {
                #pragma unroll
                for (int dt = 0; dt < 8; dt++) {
                    uint32_t bv[4];
                    uint32_t ad = sb + 2u * (uint32_t)(st + FL_VH + (c * 16 + vrow) * SQ + dt * 16 + vcol);
                    ldmx4t(bv[0], bv[1], bv[2], bv[3], ad);
                    mma16816(oacc[2*dt],   ph[c], bv);
                    mma16816(oacc[2*dt+1], ph[c], bv + 2);
                    mma16816(oacc[2*dt],   pl[c], bv);
                    mma16816(oacc[2*dt+1], pl[c], bv + 2);
                }
                #pragma unroll
                for (int dt = 0; dt < 8; dt++) {
                    uint32_t bv[4];
                    uint32_t ad = sb + 2u * (uint32_t)(st + FL_VL + (c * 16 + vrow) * SQ + dt * 16 + vcol);
                    ldmx4t(bv[0], bv[1], bv[2], bv[3], ad);
                    mma16816(oacc[2*dt],   ph[c], bv);
                    mma16816(oacc[2*dt+1], ph[c], bv + 2);
                }
            }
        }
    }

    float inv0 = 1.0f / l0, inv1 = 1.0f / l1;
    size_t grow0 = (rowQ + wq + (lane >> 2)) * C_;
    size_t grow1 = grow0 + 8 * C_;
    #pragma unroll
    for (int j = 0; j < 16; j++) {
        int col = colH + j * 8 + ((lane & 3) << 1);
        *(uint32_t*)&of[grow0 + col] = pack_f16(oacc[j][0] * inv0, oacc[j][1] * inv0);
        *(uint32_t*)&of[grow1 + col] = pack_f16(oacc[j][2] * inv1, oacc[j][3] * inv1);
    }
}

// ---------------------------------------------------------------------------
extern "C" void kernel_launch(void* const* d_in, const int* in_sizes, int n_in,
                              void* d_out, int out_size)
{
    (void)in_sizes; (void)n_in; (void)out_size;
    const float* x  = (const float*)d_in[0];
    const float* cs = (const float*)d_in[1];
    const float* sn = (const float*)d_in[2];
    float* out = (float*)d_out;

    __nv_bfloat16 *xh, *xl, *qh, *ql, *kh, *kl, *vh, *vl, *wh, *wl;
    __half *xf, *of, *w2f, *w3f;
    cudaGetSymbolAddress((void**)&xh, g_xh);
    cudaGetSymbolAddress((void**)&xl, g_xl);
    cudaGetSymbolAddress((void**)&xf, g_xf);
    cudaGetSymbolAddress((void**)&qh, g_qh);
    cudaGetSymbolAddress((void**)&ql, g_ql);
    cudaGetSymbolAddress((void**)&kh, g_kh);
    cudaGetSymbolAddress((void**)&kl, g_kl);
    cudaGetSymbolAddress((void**)&vh, g_vh);
    cudaGetSymbolAddress((void**)&vl, g_vl);
    cudaGetSymbolAddress((void**)&of, g_of);
    cudaGetSymbolAddress((void**)&wh, g_wh);
    cudaGetSymbolAddress((void**)&wl, g_wl);
    cudaGetSymbolAddress((void**)&w2f, g_w2f);
    cudaGetSymbolAddress((void**)&w3f, g_w3f);

    cudaFuncSetAttribute(qk_gemm,  cudaFuncAttributeMaxDynamicSharedMemorySize, G3_SMEM);
    cudaFuncSetAttribute(hgemm<0>, cudaFuncAttributeMaxDynamicSharedMemorySize, H_SMEM);
    cudaFuncSetAttribute(hgemm<1>, cudaFuncAttributeMaxDynamicSharedMemorySize, H_SMEM);
    cudaFuncSetAttribute(flash_bf16, cudaFuncAttributeMaxDynamicSharedMemorySize, FLASH_SMEM);

    const int ntot = NX4 + 4 * NW4;
    split_all<<<ntot / 256, 256>>>((const float4*)x,
        (const float4*)d_in[3], (const float4*)d_in[4],
        (const float4*)d_in[5], (const float4*)d_in[6],
        (uint2*)xh, (uint2*)xl, (uint2*)xf,
        (uint2*)wh, (uint2*)wl, (uint2*)w2f, (uint2*)w3f);

    // V projection (fp16 single-term) — independent of q/k, launch first
    hgemm<1><<<dim3(16, 32), 256, H_SMEM>>>(xf, w2f, nullptr, vh, vl, C_, C_);

    // Q/K projections (bf16 3-term) + rmsnorm/rope
    qk_gemm<<<dim3(32, 32), 256, G3_SMEM>>>(xh, xl, wh, wl, cs, sn, qh, ql, kh, kl);

    flash_bf16<<<dim3(T_/128, B_*H_), 256, FLASH_SMEM>>>(qh, ql, kh, kl, vh, vl, of);

    // O projection (fp16 single-term)
    hgemm<0><<<dim3(16, 32), 256, H_SMEM>>>(of, w3f, out, nullptr, nullptr, C_, C_);
}

// round 10
// speedup vs baseline: 1.3848x; 1.0985x over previous
#include <cuda_runtime.h>
#include <cuda_bf16.h>
#include <cuda_fp16.h>
#include <math_constants.h>
#include <cstdint>

#define B_ 2
#define T_ 2048
#define C_ 2048
#define H_ 16
#define D_ 128
#define M_ (B_*T_)   // 4096 rows

// ---------------- scratch (static device globals) ----------------
__device__ __nv_bfloat16 g_xh[(size_t)M_ * C_];
__device__ __nv_bfloat16 g_xl[(size_t)M_ * C_];
__device__ __half        g_xf[(size_t)M_ * C_];
__device__ __nv_bfloat16 g_qh[(size_t)M_ * C_];
__device__ __nv_bfloat16 g_ql[(size_t)M_ * C_];
__device__ __nv_bfloat16 g_kh[(size_t)M_ * C_];
__device__ __nv_bfloat16 g_kl[(size_t)M_ * C_];
__device__ __half        g_vf[(size_t)M_ * C_];
__device__ __half        g_of[(size_t)M_ * C_];
__device__ __nv_bfloat16 g_wh[2][(size_t)C_ * C_];   // Wq, Wk hi
__device__ __nv_bfloat16 g_wl[2][(size_t)C_ * C_];   // Wq, Wk lo
__device__ __half        g_w2f[(size_t)C_ * C_];     // Wv fp16
__device__ __half        g_w3f[(size_t)C_ * C_];     // Wo fp16

union BU { __nv_bfloat162 b; uint32_t u; };
union HU { __half2 h; uint32_t u; };

__device__ __forceinline__ uint32_t pack_hi(float x, float y) {
    BU u; u.b = __floats2bfloat162_rn(x, y); return u.u;
}
__device__ __forceinline__ uint32_t pack_lo(float x, float y, uint32_t hi) {
    BU h; h.u = hi;
    BU u; u.b = __floats2bfloat162_rn(x - __bfloat162float(h.b.x),
                                      y - __bfloat162float(h.b.y));
    return u.u;
}
__device__ __forceinline__ uint32_t pack_f16(float x, float y) {
    HU u; u.h = __floats2half2_rn(x, y); return u.u;
}

// ---------------------------------------------------------------------------
// split kernel: x -> bf16 hi/lo + fp16 ; W0,W1 -> bf16 hi/lo ; W2,W3 -> fp16
// ---------------------------------------------------------------------------
#define NX4 ((M_*C_)/4)
#define NW4 ((C_*C_)/4)

__global__ __launch_bounds__(256) void split_all(
    const float4* __restrict__ x,
    const float4* __restrict__ w0, const float4* __restrict__ w1,
    const float4* __restrict__ w2, const float4* __restrict__ w3,
    uint2* __restrict__ xh, uint2* __restrict__ xl, uint2* __restrict__ xf,
    uint2* __restrict__ wh, uint2* __restrict__ wl,
    uint2* __restrict__ w2f, uint2* __restrict__ w3f)
{
    int i = blockIdx.x * blockDim.x + threadIdx.x;
    if (i < NX4) {
        float4 v = x[i];
        uint32_t h0 = pack_hi(v.x, v.y), h1 = pack_hi(v.z, v.w);
        xh[i] = make_uint2(h0, h1);
        xl[i] = make_uint2(pack_lo(v.x, v.y, h0), pack_lo(v.z, v.w, h1));
        xf[i] = make_uint2(pack_f16(v.x, v.y), pack_f16(v.z, v.w));
        return;
    }
    int j = i - NX4;
    int w = j / NW4;
    int off = j - w * NW4;
    if (w < 2) {
        float4 v = (w == 0 ? w0 : w1)[off];
        uint2* ph = wh + (size_t)w * NW4;
        uint2* pl = wl + (size_t)w * NW4;
        uint32_t h0 = pack_hi(v.x, v.y), h1 = pack_hi(v.z, v.w);
        ph[off] = make_uint2(h0, h1);
        pl[off] = make_uint2(pack_lo(v.x, v.y, h0), pack_lo(v.z, v.w, h1));
    } else {
        float4 v = (w == 2 ? w2 : w3)[off];
        uint2* pf = (w == 2) ? w2f : w3f;
        pf[off] = make_uint2(pack_f16(v.x, v.y), pack_f16(v.z, v.w));
    }
}

// ---------------------------------------------------------------------------
// primitives
// ---------------------------------------------------------------------------
__device__ __forceinline__ void ldmx4(uint32_t &r0, uint32_t &r1, uint32_t &r2, uint32_t &r3, uint32_t addr) {
    asm volatile("ldmatrix.sync.aligned.m8n8.x4.shared.b16 {%0,%1,%2,%3}, [%4];"
                 : "=r"(r0), "=r"(r1), "=r"(r2), "=r"(r3) : "r"(addr));
}
__device__ __forceinline__ void ldmx4t(uint32_t &r0, uint32_t &r1, uint32_t &r2, uint32_t &r3, uint32_t addr) {
    asm volatile("ldmatrix.sync.aligned.m8n8.x4.trans.shared.b16 {%0,%1,%2,%3}, [%4];"
                 : "=r"(r0), "=r"(r1), "=r"(r2), "=r"(r3) : "r"(addr));
}
__device__ __forceinline__ void mma16816(float* d, const uint32_t* a, const uint32_t* b) {
    asm volatile("mma.sync.aligned.m16n8k16.row.col.f32.bf16.bf16.f32 "
                 "{%0,%1,%2,%3},{%4,%5,%6,%7},{%8,%9},{%0,%1,%2,%3};"
                 : "+f"(d[0]), "+f"(d[1]), "+f"(d[2]), "+f"(d[3])
                 : "r"(a[0]), "r"(a[1]), "r"(a[2]), "r"(a[3]), "r"(b[0]), "r"(b[1]));
}
__device__ __forceinline__ void mmah16(float* d, const uint32_t* a, const uint32_t* b) {
    asm volatile("mma.sync.aligned.m16n8k16.row.col.f32.f16.f16.f32 "
                 "{%0,%1,%2,%3},{%4,%5,%6,%7},{%8,%9},{%0,%1,%2,%3};"
                 : "+f"(d[0]), "+f"(d[1]), "+f"(d[2]), "+f"(d[3])
                 : "r"(a[0]), "r"(a[1]), "r"(a[2]), "r"(a[3]), "r"(b[0]), "r"(b[1]));
}
__device__ __forceinline__ void cp16(uint32_t saddr, const void* g) {
    asm volatile("cp.async.cg.shared.global [%0], [%1], 16;" :: "r"(saddr), "l"(g));
}
__device__ __forceinline__ uint32_t swz64(uint32_t off) { return off ^ ((off >> 3) & 0x30); }

// ---------------------------------------------------------------------------
// bf16 3-term GEMM geometry (q,k path): 128x128 tile, BK=32, 3 stages.
// ---------------------------------------------------------------------------
#define G3_SUB 8192
#define G3_STAGE (4*G3_SUB)              // 32768 B
#define G3_SMEM (3*G3_STAGE)             // 98304 B
#define FTS 133

#define GEMM_KK_BODY(st, kk)                                                          \
    {                                                                                 \
        uint32_t ah[2][4], al[2][4], b[8][2];                                         \
        _Pragma("unroll")                                                             \
        for (int t = 0; t < 2; t++) {                                                 \
            uint32_t rb = (uint32_t)((warp_m * 32 + t * 16 + mlane) * 64 + ((kk) + aoff) * 2); \
            ldmx4(ah[t][0], ah[t][1], ah[t][2], ah[t][3], (st) + 0 * G3_SUB + swz64(rb)); \
            ldmx4(al[t][0], al[t][1], al[t][2], al[t][3], (st) + 1 * G3_SUB + swz64(rb)); \
        }                                                                             \
        _Pragma("unroll")                                                             \
        for (int jt = 0; jt < 4; jt++) {                                              \
            uint32_t rb = (uint32_t)((warp_n * 64 + jt * 16 + nlane) * 64 + ((kk) + klBo) * 2); \
            ldmx4(b[2*jt][0], b[2*jt][1], b[2*jt+1][0], b[2*jt+1][1], (st) + 2 * G3_SUB + swz64(rb)); \
        }                                                                             \
        _Pragma("unroll")                                                             \
        for (int t = 0; t < 2; t++)                                                   \
            _Pragma("unroll")                                                         \
            for (int j = 0; j < 8; j++) mma16816(acc[t][j], ah[t], b[j]);             \
        {                                                                             \
            uint32_t bl[8][2];                                                        \
            _Pragma("unroll")                                                         \
            for (int jt = 0; jt < 4; jt++) {                                          \
                uint32_t rb = (uint32_t)((warp_n * 64 + jt * 16 + nlane) * 64 + ((kk) + klBo) * 2); \
                ldmx4(bl[2*jt][0], bl[2*jt][1], bl[2*jt+1][0], bl[2*jt+1][1], (st) + 3 * G3_SUB + swz64(rb)); \
            }                                                                         \
            _Pragma("unroll")                                                         \
            for (int t = 0; t < 2; t++)                                               \
                _Pragma("unroll")                                                     \
                for (int j = 0; j < 8; j++) mma16816(acc[t][j], al[t], b[j]);         \
            _Pragma("unroll")                                                         \
            for (int t = 0; t < 2; t++)                                               \
                _Pragma("unroll")                                                     \
                for (int j = 0; j < 8; j++) mma16816(acc[t][j], ah[t], bl[j]);        \
        }                                                                             \
    }

// ---------------------------------------------------------------------------
// Q/K GEMM (bf16 3-term) + rmsnorm/RoPE epilogue. grid (32, 32).
// ---------------------------------------------------------------------------
__global__ __launch_bounds__(256, 2) void qk_gemm(
    const __nv_bfloat16* __restrict__ xh, const __nv_bfloat16* __restrict__ xl,
    const __nv_bfloat16* __restrict__ wh, const __nv_bfloat16* __restrict__ wl,
    const float* __restrict__ cs, const float* __restrict__ sn,
    __nv_bfloat16* __restrict__ qh, __nv_bfloat16* __restrict__ ql,
    __nv_bfloat16* __restrict__ kh, __nv_bfloat16* __restrict__ kl)
{
    extern __shared__ __align__(1024) char smg[];
    const int tid = threadIdx.x, lane = tid & 31, wid = tid >> 5;
    const int warp_m = wid & 3;
    const int warp_n = wid >> 2;
    const int bm = blockIdx.y;
    const int kind = blockIdx.x >> 4;    // 0=q, 1=k
    const int lbn  = blockIdx.x & 15;    // head
    const uint32_t sb = (uint32_t)__cvta_generic_to_shared(smg);

    const __nv_bfloat16* Bh = wh + (size_t)kind * C_ * C_;
    const __nv_bfloat16* Bl = wl + (size_t)kind * C_ * C_;

    float acc[2][8][4];
    #pragma unroll
    for (int i = 0; i < 2; i++)
        #pragma unroll
        for (int j = 0; j < 8; j++)
            #pragma unroll
            for (int e = 0; e < 4; e++) acc[i][j][e] = 0.f;

    const __nv_bfloat16* srcs[4] = { xh, xl, Bh, Bl };

    auto issue = [&](int s, int k0) {
        const uint32_t st = sb + s * G3_STAGE;
        #pragma unroll
        for (int it = 0; it < 8; it++) {
            int j   = tid + it * 256;
            int sub = j >> 9;
            int cid = j & 511;
            int r   = cid >> 2;
            int ch  = cid & 3;
            int grow = (sub < 2 ? bm : lbn) * 128 + r;
            const __nv_bfloat16* g = srcs[sub] + (size_t)grow * C_ + k0 + ch * 8;
            cp16(st + sub * G3_SUB + swz64((uint32_t)(r * 64 + ch * 16)), g);
        }
        asm volatile("cp.async.commit_group;");
    };

    const int NS = C_ / 32;
    issue(0, 0);
    issue(1, 32);

    const int mlane = lane & 15;
    const int aoff  = (lane >> 4) << 3;
    const int nlane = (lane & 7) + ((lane >> 4) << 3);
    const int klBo  = ((lane >> 3) & 1) << 3;

    for (int i = 0; i < NS; i++) {
        if (i == NS - 1) { asm volatile("cp.async.wait_group 0;"); }
        else             { asm volatile("cp.async.wait_group 1;"); }
        __syncthreads();
        if (i + 2 < NS) issue((i + 2) % 3, (i + 2) * 32);

        const uint32_t st = sb + (i % 3) * G3_STAGE;
        GEMM_KK_BODY(st, 0)
        GEMM_KK_BODY(st, 16)
    }
    __syncthreads();

    // rmsnorm + rope epilogue via smem staging
    float* ft = (float*)smg;
    #pragma unroll
    for (int t = 0; t < 2; t++) {
        int rl0 = warp_m * 32 + t * 16 + (lane >> 2);
        #pragma unroll
        for (int j = 0; j < 8; j++) {
            int cl = warp_n * 64 + j * 8 + ((lane & 3) << 1);
            ft[rl0 * FTS + cl]           = acc[t][j][0];
            ft[rl0 * FTS + cl + 1]       = acc[t][j][1];
            ft[(rl0 + 8) * FTS + cl]     = acc[t][j][2];
            ft[(rl0 + 8) * FTS + cl + 1] = acc[t][j][3];
        }
    }
    __syncthreads();

    const int r  = tid >> 1;
    const int hh = tid & 1;
    const int cb = hh * 32;
    const float* fr = ft + r * FTS;

    float ss = 0.f;
    #pragma unroll
    for (int i2 = 0; i2 < 32; i2++) {
        float a = fr[cb + i2];
        float b = fr[cb + 64 + i2];
        ss += a * a + b * b;
    }
    ss += __shfl_xor_sync(0xffffffffu, ss, 1);
    float rms = rsqrtf(ss * (1.0f / 128.0f) + 1.1920929e-7f);

    const int grow = bm * 128 + r;
    const int t    = grow & (T_ - 1);
    __nv_bfloat16* Oh = kind ? kh : qh;
    __nv_bfloat16* Ol = kind ? kl : ql;
    const size_t rb = (size_t)grow * C_ + lbn * 128;

    #pragma unroll
    for (int i2 = 0; i2 < 32; i2 += 2) {
        int c0 = cb + i2;
        float a0 = fr[c0] * rms,     b0 = fr[c0 + 64] * rms;
        float a1 = fr[c0 + 1] * rms, b1 = fr[c0 + 65] * rms;
        float co0 = cs[t * 64 + c0], si0 = sn[t * 64 + c0];
        float co1 = cs[t * 64 + c0 + 1], si1 = sn[t * 64 + c0 + 1];
        float y10 =  a0 * co0 + b0 * si0;
        float y11 =  a1 * co1 + b1 * si1;
        float y20 = -a0 * si0 + b0 * co0;
        float y21 = -a1 * si1 + b1 * co1;
        uint32_t h1p = pack_hi(y10, y11);
        uint32_t h2p = pack_hi(y20, y21);
        *(uint32_t*)&Oh[rb + c0]      = h1p;
        *(uint32_t*)&Ol[rb + c0]      = pack_lo(y10, y11, h1p);
        *(uint32_t*)&Oh[rb + c0 + 64] = h2p;
        *(uint32_t*)&Ol[rb + c0 + 64] = pack_lo(y20, y21, h2p);
    }
}

// ---------------------------------------------------------------------------
// fp16 single-term GEMM: C[M,N] = A[M,K] @ B[N,K]^T.
// 128x128 tile, BK=32, 4-stage. OMODE 0: fp32 out. OMODE 1: fp16 out.
// ---------------------------------------------------------------------------
#define H_SUB 8192
#define H_STAGE (2*H_SUB)                // 16384 B
#define H_SMEM (4*H_STAGE)               // 65536 B

template<int OMODE>
__global__ __launch_bounds__(256, 2) void hgemm(
    const __half* __restrict__ Af, const __half* __restrict__ Bf,
    float* __restrict__ Cc, __half* __restrict__ Cf,
    int Nn, int K)
{
    extern __shared__ __align__(1024) char smg[];
    const int tid = threadIdx.x, lane = tid & 31, wid = tid >> 5;
    const int warp_m = wid & 3;
    const int warp_n = wid >> 2;
    const int bm = blockIdx.y, bn = blockIdx.x;
    const uint32_t sb = (uint32_t)__cvta_generic_to_shared(smg);

    float acc[2][8][4];
    #pragma unroll
    for (int i = 0; i < 2; i++)
        #pragma unroll
        for (int j = 0; j < 8; j++)
            #pragma unroll
            for (int e = 0; e < 4; e++) acc[i][j][e] = 0.f;

    auto issue = [&](int s, int k0) {
        const uint32_t st = sb + s * H_STAGE;
        #pragma unroll
        for (int it = 0; it < 4; it++) {
            int j   = tid + it * 256;
            int sub = j >> 9;            // 0=A, 1=B
            int cid = j & 511;
            int r   = cid >> 2;
            int ch  = cid & 3;
            int grow = (sub ? bn : bm) * 128 + r;
            const __half* g = (sub ? Bf : Af) + (size_t)grow * K + k0 + ch * 8;
            cp16(st + sub * H_SUB + swz64((uint32_t)(r * 64 + ch * 16)), g);
        }
        asm volatile("cp.async.commit_group;");
    };

    const int NS = K / 32;   // 64
    issue(0, 0); issue(1, 32); issue(2, 64);

    const int mlane = lane & 15;
    const int aoff  = (lane >> 4) << 3;
    const int nlane = (lane & 7) + ((lane >> 4) << 3);
    const int klBo  = ((lane >> 3) & 1) << 3;

    for (int i = 0; i < NS; i++) {
        if (i + 3 < NS) { asm volatile("cp.async.wait_group 2;"); }
        else            { asm volatile("cp.async.wait_group 0;"); }
        __syncthreads();
        if (i + 3 < NS) issue((i + 3) & 3, (i + 3) * 32);

        const uint32_t st = sb + (i & 3) * H_STAGE;
        #pragma unroll
        for (int kk = 0; kk < 32; kk += 16) {
            uint32_t a[2][4], b[8][2];
            #pragma unroll
            for (int t = 0; t < 2; t++) {
                uint32_t rb = (uint32_t)((warp_m * 32 + t * 16 + mlane) * 64 + (kk + aoff) * 2);
                ldmx4(a[t][0], a[t][1], a[t][2], a[t][3], st + swz64(rb));
            }
            #pragma unroll
            for (int jt = 0; jt < 4; jt++) {
                uint32_t rb = (uint32_t)((warp_n * 64 + jt * 16 + nlane) * 64 + (kk + klBo) * 2);
                ldmx4(b[2*jt][0], b[2*jt][1], b[2*jt+1][0], b[2*jt+1][1], st + H_SUB + swz64(rb));
            }
            #pragma unroll
            for (int t = 0; t < 2; t++)
                #pragma unroll
                for (int j = 0; j < 8; j++) mmah16(acc[t][j], a[t], b[j]);
        }
        __syncthreads();
    }

    #pragma unroll
    for (int t = 0; t < 2; t++) {
        int row = bm * 128 + warp_m * 32 + t * 16 + (lane >> 2);
        #pragma unroll
        for (int j = 0; j < 8; j++) {
            int col = bn * 128 + warp_n * 64 + j * 8 + ((lane & 3) << 1);
            if (OMODE == 0) {
                *(float2*)&Cc[(size_t)row * Nn + col]       = make_float2(acc[t][j][0], acc[t][j][1]);
                *(float2*)&Cc[(size_t)(row + 8) * Nn + col] = make_float2(acc[t][j][2], acc[t][j][3]);
            } else {
                *(uint32_t*)&Cf[(size_t)row * Nn + col]       = pack_f16(acc[t][j][0], acc[t][j][1]);
                *(uint32_t*)&Cf[(size_t)(row + 8) * Nn + col] = pack_f16(acc[t][j][2], acc[t][j][3]);
            }
        }
    }
}

// ---------------------------------------------------------------------------
// Tensor-core flash attention (causal).
// S = QK^T: bf16 3-term (softmax-sensitive). PV: fp16 single-term.
// Q fragments in registers; KV 4-stage pipeline (kh, kl bf16 + vf fp16).
// ---------------------------------------------------------------------------
#define SQ 136
#define FL_STAGE (3*64*SQ)               // elems per stage (KH, KL, VF)
#define FL_KH 0
#define FL_KL (64*SQ)
#define FL_VF (128*SQ)
#define FLASH_SMEM (4*FL_STAGE*2)        // 208896 bytes

__global__ __launch_bounds__(256, 1) void flash_bf16(
    const __nv_bfloat16* __restrict__ qh, const __nv_bfloat16* __restrict__ ql,
    const __nv_bfloat16* __restrict__ kh, const __nv_bfloat16* __restrict__ kl,
    const __half* __restrict__ vf,
    __half* __restrict__ of)
{
    extern __shared__ __nv_bfloat16 smf[];
    const int tid = threadIdx.x, lane = tid & 31, wid = tid >> 5;
    const int qb = gridDim.x - 1 - blockIdx.x;
    const int b  = blockIdx.y >> 4, h = blockIdx.y & 15;
    const uint32_t sb = (uint32_t)__cvta_generic_to_shared(smf);
    const size_t rowQ = (size_t)b * T_ + (size_t)qb * 128;
    const int colH = h * D_;

    const int wq = wid * 16;
    const int gq0 = qb * 128 + wq;
    const int mlane = lane & 15;
    const int aoff  = (lane >> 4) << 3;
    const int nlane = (lane & 7) + ((lane >> 4) << 3);
    const int klB   = ((lane >> 3) & 1) << 3;

    // ---- stage Q through smem, extract fragments to registers ----
    #pragma unroll
    for (int it = 0; it < 8; it++) {
        int idx = tid + it * 256;
        int r = idx >> 4, c = (idx & 15) << 3;
        size_t g = (rowQ + r) * C_ + colH + c;
        cp16(sb + 2u * (uint32_t)(r * SQ + c), qh + g);
        cp16(sb + 2u * (uint32_t)(128 * SQ + r * SQ + c), ql + g);
    }
    asm volatile("cp.async.commit_group;");
    asm volatile("cp.async.wait_group 0;");
    __syncthreads();

    uint32_t qfh[8][4], qfl[8][4];
    #pragma unroll
    for (int c = 0; c < 8; c++) {
        uint32_t ad = sb + 2u * (uint32_t)((wq + mlane) * SQ + c * 16 + aoff);
        ldmx4(qfh[c][0], qfh[c][1], qfh[c][2], qfh[c][3], ad);
        ldmx4(qfl[c][0], qfl[c][1], qfl[c][2], qfl[c][3], ad + 2u * (uint32_t)(128 * SQ));
    }
    __syncthreads();

    auto issueKV = [&](int s, int kt) {
        uint32_t st = s * FL_STAGE;
        #pragma unroll
        for (int it = 0; it < 4; it++) {
            int idx = tid + it * 256;
            int r = idx >> 4, c = (idx & 15) << 3;
            size_t g = ((size_t)b * T_ + (size_t)kt * 64 + r) * C_ + colH + c;
            uint32_t so = (uint32_t)(st + r * SQ + c);
            cp16(sb + 2u * (so + FL_KH), kh + g);
            cp16(sb + 2u * (so + FL_KL), kl + g);
            cp16(sb + 2u * (so + FL_VF), vf + g);
        }
        asm volatile("cp.async.commit_group;");
    };

    const int nkt = 2 * qb + 2;   // >= 2
    issueKV(0, 0);
    issueKV(1, 1);
    if (nkt > 2) issueKV(2, 2);

    const float scale = 0.088388347648318447f;

    float m0 = -CUDART_INF_F, m1 = -CUDART_INF_F, l0 = 0.f, l1 = 0.f;
    float oacc[16][4];
    #pragma unroll
    for (int j = 0; j < 16; j++)
        #pragma unroll
        for (int e = 0; e < 4; e++) oacc[j][e] = 0.f;

    for (int kt = 0; kt < nkt; kt++) {
        if (kt + 3 < nkt) { asm volatile("cp.async.wait_group 2;"); }
        else              { asm volatile("cp.async.wait_group 0;"); }
        __syncthreads();
        if (kt + 3 < nkt) issueKV((kt + 3) & 3, kt + 3);

        const int kb = kt * 64;
        if (kb <= gq0 + 15) {
            const uint32_t st = (kt & 3) * FL_STAGE;

            float sacc[8][4];
            #pragma unroll
            for (int j = 0; j < 8; j++)
                #pragma unroll
                for (int e = 0; e < 4; e++) sacc[j][e] = 0.f;

            #pragma unroll
            for (int c = 0; c < 8; c++) {
                uint32_t bh2[8][2];
                #pragma unroll
                for (int jt = 0; jt < 4; jt++) {
                    uint32_t ad = sb + 2u * (uint32_t)(st + FL_KH + (jt * 16 + nlane) * SQ + c * 16 + klB);
                    ldmx4(bh2[2*jt][0], bh2[2*jt][1], bh2[2*jt+1][0], bh2[2*jt+1][1], ad);
                }
                #pragma unroll
                for (int j = 0; j < 8; j++) mma16816(sacc[j], qfh[c], bh2[j]);
                #pragma unroll
                for (int j = 0; j < 8; j++) mma16816(sacc[j], qfl[c], bh2[j]);
                #pragma unroll
                for (int jt = 0; jt < 4; jt++) {
                    uint32_t ad = sb + 2u * (uint32_t)(st + FL_KL + (jt * 16 + nlane) * SQ + c * 16 + klB);
                    ldmx4(bh2[2*jt][0], bh2[2*jt][1], bh2[2*jt+1][0], bh2[2*jt+1][1], ad);
                }
                #pragma unroll
                for (int j = 0; j < 8; j++) mma16816(sacc[j], qfh[c], bh2[j]);
            }

            const bool diag = (kb + 63 > gq0);
            const int r0 = gq0 + (lane >> 2), r1 = r0 + 8;
            float tm0 = -CUDART_INF_F, tm1 = -CUDART_INF_F;
            #pragma unroll
            for (int j = 0; j < 8; j++) {
                int cc = kb + j * 8 + ((lane & 3) << 1);
                float v0 = sacc[j][0] * scale, v1 = sacc[j][1] * scale;
                float v2 = sacc[j][2] * scale, v3 = sacc[j][3] * scale;
                if (diag) {
                    if (cc     > r0) v0 = -CUDART_INF_F;
                    if (cc + 1 > r0) v1 = -CUDART_INF_F;
                    if (cc     > r1) v2 = -CUDART_INF_F;
                    if (cc + 1 > r1) v3 = -CUDART_INF_F;
                }
                sacc[j][0] = v0; sacc[j][1] = v1; sacc[j][2] = v2; sacc[j][3] = v3;
                tm0 = fmaxf(tm0, fmaxf(v0, v1));
                tm1 = fmaxf(tm1, fmaxf(v2, v3));
            }
            tm0 = fmaxf(tm0, __shfl_xor_sync(0xffffffffu, tm0, 1));
            tm0 = fmaxf(tm0, __shfl_xor_sync(0xffffffffu, tm0, 2));
            tm1 = fmaxf(tm1, __shfl_xor_sync(0xffffffffu, tm1, 1));
            tm1 = fmaxf(tm1, __shfl_xor_sync(0xffffffffu, tm1, 2));
            float mn0 = fmaxf(m0, tm0), mn1 = fmaxf(m1, tm1);
            float a0 = __expf(m0 - mn0), a1 = __expf(m1 - mn1);
            float rs0 = 0.f, rs1 = 0.f;
            #pragma unroll
            for (int j = 0; j < 8; j++) {
                float p0 = __expf(sacc[j][0] - mn0);
                float p1 = __expf(sacc[j][1] - mn0);
                float p2 = __expf(sacc[j][2] - mn1);
                float p3 = __expf(sacc[j][3] - mn1);
                sacc[j][0] = p0; sacc[j][1] = p1; sacc[j][2] = p2; sacc[j][3] = p3;
                rs0 += p0 + p1; rs1 += p2 + p3;
            }
            rs0 += __shfl_xor_sync(0xffffffffu, rs0, 1);
            rs0 += __shfl_xor_sync(0xffffffffu, rs0, 2);
            rs1 += __shfl_xor_sync(0xffffffffu, rs1, 1);
            rs1 += __shfl_xor_sync(0xffffffffu, rs1, 2);
            l0 = l0 * a0 + rs0; l1 = l1 * a1 + rs1;
            m0 = mn0; m1 = mn1;
            #pragma unroll
            for (int j = 0; j < 16; j++) {
                oacc[j][0] *= a0; oacc[j][1] *= a0;
                oacc[j][2] *= a1; oacc[j][3] *= a1;
            }

            // ---- P fragments (fp16 single) ----
            uint32_t pf[4][4];
            #pragma unroll
            for (int c = 0; c < 4; c++) {
                pf[c][0] = pack_f16(sacc[2*c][0],   sacc[2*c][1]);
                pf[c][1] = pack_f16(sacc[2*c][2],   sacc[2*c][3]);
                pf[c][2] = pack_f16(sacc[2*c+1][0], sacc[2*c+1][1]);
                pf[c][3] = pack_f16(sacc[2*c+1][2], sacc[2*c+1][3]);
            }

            // ---- O += P V (fp16 single-term), V via ldmatrix.trans ----
            const int vrow = ((lane >> 3) & 1) * 8 + (lane & 7);
            const int vcol = (lane >> 4) << 3;
            #pragma unroll
            for (int c = 0; c < 4; c++) {
                #pragma unroll
                for (int dt = 0; dt < 8; dt++) {
                    uint32_t bv[4];
                    uint32_t ad = sb + 2u * (uint32_t)(st + FL_VF + (c * 16 + vrow) * SQ + dt * 16 + vcol);
                    ldmx4t(bv[0], bv[1], bv[2], bv[3], ad);
                    mmah16(oacc[2*dt],   pf[c], bv);
                    mmah16(oacc[2*dt+1], pf[c], bv + 2);
                }
            }
        }
    }

    float inv0 = 1.0f / l0, inv1 = 1.0f / l1;
    size_t grow0 = (rowQ + wq + (lane >> 2)) * C_;
    size_t grow1 = grow0 + 8 * C_;
    #pragma unroll
    for (int j = 0; j < 16; j++) {
        int col = colH + j * 8 + ((lane & 3) << 1);
        *(uint32_t*)&of[grow0 + col] = pack_f16(oacc[j][0] * inv0, oacc[j][1] * inv0);
        *(uint32_t*)&of[grow1 + col] = pack_f16(oacc[j][2] * inv1, oacc[j][3] * inv1);
    }
}

// ---------------------------------------------------------------------------
extern "C" void kernel_launch(void* const* d_in, const int* in_sizes, int n_in,
                              void* d_out, int out_size)
{
    (void)in_sizes; (void)n_in; (void)out_size;
    const float* x  = (const float*)d_in[0];
    const float* cs = (const float*)d_in[1];
    const float* sn = (const float*)d_in[2];
    float* out = (float*)d_out;

    __nv_bfloat16 *xh, *xl, *qh, *ql, *kh, *kl, *wh, *wl;
    __half *xf, *vf, *of, *w2f, *w3f;
    cudaGetSymbolAddress((void**)&xh, g_xh);
    cudaGetSymbolAddress((void**)&xl, g_xl);
    cudaGetSymbolAddress((void**)&xf, g_xf);
    cudaGetSymbolAddress((void**)&qh, g_qh);
    cudaGetSymbolAddress((void**)&ql, g_ql);
    cudaGetSymbolAddress((void**)&kh, g_kh);
    cudaGetSymbolAddress((void**)&kl, g_kl);
    cudaGetSymbolAddress((void**)&vf, g_vf);
    cudaGetSymbolAddress((void**)&of, g_of);
    cudaGetSymbolAddress((void**)&wh, g_wh);
    cudaGetSymbolAddress((void**)&wl, g_wl);
    cudaGetSymbolAddress((void**)&w2f, g_w2f);
    cudaGetSymbolAddress((void**)&w3f, g_w3f);

    cudaFuncSetAttribute(qk_gemm,  cudaFuncAttributeMaxDynamicSharedMemorySize, G3_SMEM);
    cudaFuncSetAttribute(hgemm<0>, cudaFuncAttributeMaxDynamicSharedMemorySize, H_SMEM);
    cudaFuncSetAttribute(hgemm<1>, cudaFuncAttributeMaxDynamicSharedMemorySize, H_SMEM);
    cudaFuncSetAttribute(flash_bf16, cudaFuncAttributeMaxDynamicSharedMemorySize, FLASH_SMEM);

    const int ntot = NX4 + 4 * NW4;
    split_all<<<ntot / 256, 256>>>((const float4*)x,
        (const float4*)d_in[3], (const float4*)d_in[4],
        (const float4*)d_in[5], (const float4*)d_in[6],
        (uint2*)xh, (uint2*)xl, (uint2*)xf,
        (uint2*)wh, (uint2*)wl, (uint2*)w2f, (uint2*)w3f);

    // V projection (fp16 single-term) — independent of q/k, launch first
    hgemm<1><<<dim3(16, 32), 256, H_SMEM>>>(xf, w2f, nullptr, vf, C_, C_);

    // Q/K projections (bf16 3-term) + rmsnorm/rope
    qk_gemm<<<dim3(32, 32), 256, G3_SMEM>>>(xh, xl, wh, wl, cs, sn, qh, ql, kh, kl);

    flash_bf16<<<dim3(T_/128, B_*H_), 256, FLASH_SMEM>>>(qh, ql, kh, kl, vf, of);

    // O projection (fp16 single-term)
    hgemm<0><<<dim3(16, 32), 256, H_SMEM>>>(of, w3f, out, nullptr, C_, C_);
}

// round 11
// speedup vs baseline: 2.2393x; 1.6171x over previous
#include <cuda_runtime.h>
#include <cuda_bf16.h>
#include <cuda_fp16.h>
#include <math_constants.h>
#include <cstdint>

#define B_ 2
#define T_ 2048
#define C_ 2048
#define H_ 16
#define D_ 128
#define M_ (B_*T_)   // 4096 rows

// ---------------- scratch (static device globals) ----------------
__device__ __half g_xf[(size_t)M_ * C_];
__device__ __half g_qf[(size_t)M_ * C_];
__device__ __half g_kf[(size_t)M_ * C_];
__device__ __half g_vf[(size_t)M_ * C_];
__device__ __half g_of[(size_t)M_ * C_];
__device__ __half g_wf[4][(size_t)C_ * C_];   // Wq, Wk, Wv, Wo fp16

union HU { __half2 h; uint32_t u; };

__device__ __forceinline__ uint32_t pack_f16(float x, float y) {
    HU u; u.h = __floats2half2_rn(x, y); return u.u;
}

// ---------------------------------------------------------------------------
// split kernel: x, W0..W3 -> fp16
// ---------------------------------------------------------------------------
#define NX4 ((M_*C_)/4)
#define NW4 ((C_*C_)/4)

__global__ __launch_bounds__(256) void split_all(
    const float4* __restrict__ x,
    const float4* __restrict__ w0, const float4* __restrict__ w1,
    const float4* __restrict__ w2, const float4* __restrict__ w3,
    uint2* __restrict__ xf, uint2* __restrict__ wf)
{
    int i = blockIdx.x * blockDim.x + threadIdx.x;
    const float4* src;
    uint2* dst;
    int off;
    if (i < NX4) {
        src = x; off = i; dst = xf;
    } else {
        int j = i - NX4;
        int w = j / NW4;
        off = j - w * NW4;
        src = (w == 0) ? w0 : (w == 1) ? w1 : (w == 2) ? w2 : w3;
        dst = wf + (size_t)w * NW4;
    }
    float4 v = src[off];
    dst[off] = make_uint2(pack_f16(v.x, v.y), pack_f16(v.z, v.w));
}

// ---------------------------------------------------------------------------
// primitives
// ---------------------------------------------------------------------------
__device__ __forceinline__ void ldmx4(uint32_t &r0, uint32_t &r1, uint32_t &r2, uint32_t &r3, uint32_t addr) {
    asm volatile("ldmatrix.sync.aligned.m8n8.x4.shared.b16 {%0,%1,%2,%3}, [%4];"
                 : "=r"(r0), "=r"(r1), "=r"(r2), "=r"(r3) : "r"(addr));
}
__device__ __forceinline__ void ldmx4t(uint32_t &r0, uint32_t &r1, uint32_t &r2, uint32_t &r3, uint32_t addr) {
    asm volatile("ldmatrix.sync.aligned.m8n8.x4.trans.shared.b16 {%0,%1,%2,%3}, [%4];"
                 : "=r"(r0), "=r"(r1), "=r"(r2), "=r"(r3) : "r"(addr));
}
__device__ __forceinline__ void mmah16(float* d, const uint32_t* a, const uint32_t* b) {
    asm volatile("mma.sync.aligned.m16n8k16.row.col.f32.f16.f16.f32 "
                 "{%0,%1,%2,%3},{%4,%5,%6,%7},{%8,%9},{%0,%1,%2,%3};"
                 : "+f"(d[0]), "+f"(d[1]), "+f"(d[2]), "+f"(d[3])
                 : "r"(a[0]), "r"(a[1]), "r"(a[2]), "r"(a[3]), "r"(b[0]), "r"(b[1]));
}
__device__ __forceinline__ void cp16(uint32_t saddr, const void* g) {
    asm volatile("cp.async.cg.shared.global [%0], [%1], 16;" :: "r"(saddr), "l"(g));
}
__device__ __forceinline__ uint32_t swz64(uint32_t off) { return off ^ ((off >> 3) & 0x30); }

// ---------------------------------------------------------------------------
// fp16 GEMM core geometry: 128x128 CTA tile, BK=32, 8 warps (32x64), 4 stages.
// ---------------------------------------------------------------------------
#define H_SUB 8192
#define H_STAGE (2*H_SUB)                // 16384 B
#define H_SMEM (4*H_STAGE)               // 65536 B
#define FTS 133
#define QKV_SMEM (128*FTS*4)             // 68096 B (>= H_SMEM)

// ---------------------------------------------------------------------------
// Fused QKV fp16 GEMM + (rmsnorm+RoPE | passthrough) epilogue.
// grid (48, 32): bx>>4 = kind (0=q 1=k 2=v), bx&15 = head.
// ---------------------------------------------------------------------------
__global__ __launch_bounds__(256, 2) void qkv_gemm(
    const __half* __restrict__ xf, const __half* __restrict__ wf,
    const float* __restrict__ cs, const float* __restrict__ sn,
    __half* __restrict__ qf, __half* __restrict__ kf, __half* __restrict__ vf)
{
    extern __shared__ __align__(1024) char smg[];
    const int tid = threadIdx.x, lane = tid & 31, wid = tid >> 5;
    const int warp_m = wid & 3;
    const int warp_n = wid >> 2;
    const int bm = blockIdx.y;
    const int kind = blockIdx.x >> 4;
    const int lbn  = blockIdx.x & 15;
    const uint32_t sb = (uint32_t)__cvta_generic_to_shared(smg);

    const __half* Bf = wf + (size_t)kind * C_ * C_;

    float acc[2][8][4];
    #pragma unroll
    for (int i = 0; i < 2; i++)
        #pragma unroll
        for (int j = 0; j < 8; j++)
            #pragma unroll
            for (int e = 0; e < 4; e++) acc[i][j][e] = 0.f;

    auto issue = [&](int s, int k0) {
        const uint32_t st = sb + s * H_STAGE;
        #pragma unroll
        for (int it = 0; it < 4; it++) {
            int j   = tid + it * 256;
            int sub = j >> 9;            // 0=A, 1=B
            int cid = j & 511;
            int r   = cid >> 2;
            int ch  = cid & 3;
            int grow = (sub ? lbn : bm) * 128 + r;
            const __half* g = (sub ? Bf : xf) + (size_t)grow * C_ + k0 + ch * 8;
            cp16(st + sub * H_SUB + swz64((uint32_t)(r * 64 + ch * 16)), g);
        }
        asm volatile("cp.async.commit_group;");
    };

    const int NS = C_ / 32;   // 64
    issue(0, 0); issue(1, 32); issue(2, 64);

    const int mlane = lane & 15;
    const int aoff  = (lane >> 4) << 3;
    const int nlane = (lane & 7) + ((lane >> 4) << 3);
    const int klBo  = ((lane >> 3) & 1) << 3;

    for (int i = 0; i < NS; i++) {
        if (i + 3 < NS) { asm volatile("cp.async.wait_group 2;"); }
        else            { asm volatile("cp.async.wait_group 0;"); }
        __syncthreads();
        if (i + 3 < NS) issue((i + 3) & 3, (i + 3) * 32);

        const uint32_t st = sb + (i & 3) * H_STAGE;
        #pragma unroll
        for (int kk = 0; kk < 32; kk += 16) {
            uint32_t a[2][4], b[8][2];
            #pragma unroll
            for (int t = 0; t < 2; t++) {
                uint32_t rb = (uint32_t)((warp_m * 32 + t * 16 + mlane) * 64 + (kk + aoff) * 2);
                ldmx4(a[t][0], a[t][1], a[t][2], a[t][3], st + swz64(rb));
            }
            #pragma unroll
            for (int jt = 0; jt < 4; jt++) {
                uint32_t rb = (uint32_t)((warp_n * 64 + jt * 16 + nlane) * 64 + (kk + klBo) * 2);
                ldmx4(b[2*jt][0], b[2*jt][1], b[2*jt+1][0], b[2*jt+1][1], st + H_SUB + swz64(rb));
            }
            #pragma unroll
            for (int t = 0; t < 2; t++)
                #pragma unroll
                for (int j = 0; j < 8; j++) mmah16(acc[t][j], a[t], b[j]);
        }
        __syncthreads();
    }

    if (kind == 2) {
        // V: passthrough fp16
        #pragma unroll
        for (int t = 0; t < 2; t++) {
            int row = bm * 128 + warp_m * 32 + t * 16 + (lane >> 2);
            #pragma unroll
            for (int j = 0; j < 8; j++) {
                int col = lbn * 128 + warp_n * 64 + j * 8 + ((lane & 3) << 1);
                *(uint32_t*)&vf[(size_t)row * C_ + col]       = pack_f16(acc[t][j][0], acc[t][j][1]);
                *(uint32_t*)&vf[(size_t)(row + 8) * C_ + col] = pack_f16(acc[t][j][2], acc[t][j][3]);
            }
        }
    } else {
        // Q/K: rmsnorm + rope epilogue via fp32 smem staging
        float* ft = (float*)smg;
        #pragma unroll
        for (int t = 0; t < 2; t++) {
            int rl0 = warp_m * 32 + t * 16 + (lane >> 2);
            #pragma unroll
            for (int j = 0; j < 8; j++) {
                int cl = warp_n * 64 + j * 8 + ((lane & 3) << 1);
                ft[rl0 * FTS + cl]           = acc[t][j][0];
                ft[rl0 * FTS + cl + 1]       = acc[t][j][1];
                ft[(rl0 + 8) * FTS + cl]     = acc[t][j][2];
                ft[(rl0 + 8) * FTS + cl + 1] = acc[t][j][3];
            }
        }
        __syncthreads();

        const int r  = tid >> 1;
        const int hh = tid & 1;
        const int cb = hh * 32;
        const float* fr = ft + r * FTS;

        float ss = 0.f;
        #pragma unroll
        for (int i2 = 0; i2 < 32; i2++) {
            float a = fr[cb + i2];
            float b = fr[cb + 64 + i2];
            ss += a * a + b * b;
        }
        ss += __shfl_xor_sync(0xffffffffu, ss, 1);
        float rms = rsqrtf(ss * (1.0f / 128.0f) + 1.1920929e-7f);

        const int grow = bm * 128 + r;
        const int t    = grow & (T_ - 1);
        __half* Of = kind ? kf : qf;
        const size_t rb = (size_t)grow * C_ + lbn * 128;

        #pragma unroll
        for (int i2 = 0; i2 < 32; i2 += 2) {
            int c0 = cb + i2;
            float a0 = fr[c0] * rms,     b0 = fr[c0 + 64] * rms;
            float a1 = fr[c0 + 1] * rms, b1 = fr[c0 + 65] * rms;
            float co0 = cs[t * 64 + c0], si0 = sn[t * 64 + c0];
            float co1 = cs[t * 64 + c0 + 1], si1 = sn[t * 64 + c0 + 1];
            float y10 =  a0 * co0 + b0 * si0;
            float y11 =  a1 * co1 + b1 * si1;
            float y20 = -a0 * si0 + b0 * co0;
            float y21 = -a1 * si1 + b1 * co1;
            *(uint32_t*)&Of[rb + c0]      = pack_f16(y10, y11);
            *(uint32_t*)&Of[rb + c0 + 64] = pack_f16(y20, y21);
        }
    }
}

// ---------------------------------------------------------------------------
// O-projection fp16 GEMM (fp32 out). grid (16, 32).
// ---------------------------------------------------------------------------
__global__ __launch_bounds__(256, 2) void hgemm_o(
    const __half* __restrict__ Af, const __half* __restrict__ Bf,
    float* __restrict__ Cc, int Nn, int K)
{
    extern __shared__ __align__(1024) char smg[];
    const int tid = threadIdx.x, lane = tid & 31, wid = tid >> 5;
    const int warp_m = wid & 3;
    const int warp_n = wid >> 2;
    const int bm = blockIdx.y, bn = blockIdx.x;
    const uint32_t sb = (uint32_t)__cvta_generic_to_shared(smg);

    float acc[2][8][4];
    #pragma unroll
    for (int i = 0; i < 2; i++)
        #pragma unroll
        for (int j = 0; j < 8; j++)
            #pragma unroll
            for (int e = 0; e < 4; e++) acc[i][j][e] = 0.f;

    auto issue = [&](int s, int k0) {
        const uint32_t st = sb + s * H_STAGE;
        #pragma unroll
        for (int it = 0; it < 4; it++) {
            int j   = tid + it * 256;
            int sub = j >> 9;
            int cid = j & 511;
            int r   = cid >> 2;
            int ch  = cid & 3;
            int grow = (sub ? bn : bm) * 128 + r;
            const __half* g = (sub ? Bf : Af) + (size_t)grow * K + k0 + ch * 8;
            cp16(st + sub * H_SUB + swz64((uint32_t)(r * 64 + ch * 16)), g);
        }
        asm volatile("cp.async.commit_group;");
    };

    const int NS = K / 32;
    issue(0, 0); issue(1, 32); issue(2, 64);

    const int mlane = lane & 15;
    const int aoff  = (lane >> 4) << 3;
    const int nlane = (lane & 7) + ((lane >> 4) << 3);
    const int klBo  = ((lane >> 3) & 1) << 3;

    for (int i = 0; i < NS; i++) {
        if (i + 3 < NS) { asm volatile("cp.async.wait_group 2;"); }
        else            { asm volatile("cp.async.wait_group 0;"); }
        __syncthreads();
        if (i + 3 < NS) issue((i + 3) & 3, (i + 3) * 32);

        const uint32_t st = sb + (i & 3) * H_STAGE;
        #pragma unroll
        for (int kk = 0; kk < 32; kk += 16) {
            uint32_t a[2][4], b[8][2];
            #pragma unroll
            for (int t = 0; t < 2; t++) {
                uint32_t rb = (uint32_t)((warp_m * 32 + t * 16 + mlane) * 64 + (kk + aoff) * 2);
                ldmx4(a[t][0], a[t][1], a[t][2], a[t][3], st + swz64(rb));
            }
            #pragma unroll
            for (int jt = 0; jt < 4; jt++) {
                uint32_t rb = (uint32_t)((warp_n * 64 + jt * 16 + nlane) * 64 + (kk + klBo) * 2);
                ldmx4(b[2*jt][0], b[2*jt][1], b[2*jt+1][0], b[2*jt+1][1], st + H_SUB + swz64(rb));
            }
            #pragma unroll
            for (int t = 0; t < 2; t++)
                #pragma unroll
                for (int j = 0; j < 8; j++) mmah16(acc[t][j], a[t], b[j]);
        }
        __syncthreads();
    }

    #pragma unroll
    for (int t = 0; t < 2; t++) {
        int row = bm * 128 + warp_m * 32 + t * 16 + (lane >> 2);
        #pragma unroll
        for (int j = 0; j < 8; j++) {
            int col = bn * 128 + warp_n * 64 + j * 8 + ((lane & 3) << 1);
            *(float2*)&Cc[(size_t)row * Nn + col]       = make_float2(acc[t][j][0], acc[t][j][1]);
            *(float2*)&Cc[(size_t)(row + 8) * Nn + col] = make_float2(acc[t][j][2], acc[t][j][3]);
        }
    }
}

// ---------------------------------------------------------------------------
// Tensor-core flash attention (causal), full fp16 mma, fp32 softmax/accum.
// Q fragments in registers; KV (kf + vf) 4-stage pipeline.
// ---------------------------------------------------------------------------
#define SQ 136
#define FL_STAGE (2*64*SQ)               // elems per stage (KF, VF)
#define FL_KF 0
#define FL_VF (64*SQ)
#define FLASH_SMEM (4*FL_STAGE*2)        // 139264 bytes

__global__ __launch_bounds__(256, 1) void flash_f16(
    const __half* __restrict__ qf, const __half* __restrict__ kf,
    const __half* __restrict__ vf, __half* __restrict__ of)
{
    extern __shared__ __half smf[];
    const int tid = threadIdx.x, lane = tid & 31, wid = tid >> 5;
    const int qb = gridDim.x - 1 - blockIdx.x;
    const int b  = blockIdx.y >> 4, h = blockIdx.y & 15;
    const uint32_t sb = (uint32_t)__cvta_generic_to_shared(smf);
    const size_t rowQ = (size_t)b * T_ + (size_t)qb * 128;
    const int colH = h * D_;

    const int wq = wid * 16;
    const int gq0 = qb * 128 + wq;
    const int mlane = lane & 15;
    const int aoff  = (lane >> 4) << 3;
    const int nlane = (lane & 7) + ((lane >> 4) << 3);
    const int klB   = ((lane >> 3) & 1) << 3;

    // ---- stage Q through smem, extract fragments to registers ----
    #pragma unroll
    for (int it = 0; it < 8; it++) {
        int idx = tid + it * 256;
        int r = idx >> 4, c = (idx & 15) << 3;
        cp16(sb + 2u * (uint32_t)(r * SQ + c), qf + (rowQ + r) * C_ + colH + c);
    }
    asm volatile("cp.async.commit_group;");
    asm volatile("cp.async.wait_group 0;");
    __syncthreads();

    uint32_t qr[8][4];
    #pragma unroll
    for (int c = 0; c < 8; c++) {
        uint32_t ad = sb + 2u * (uint32_t)((wq + mlane) * SQ + c * 16 + aoff);
        ldmx4(qr[c][0], qr[c][1], qr[c][2], qr[c][3], ad);
    }
    __syncthreads();

    auto issueKV = [&](int s, int kt) {
        uint32_t st = s * FL_STAGE;
        #pragma unroll
        for (int it = 0; it < 4; it++) {
            int idx = tid + it * 256;
            int r = idx >> 4, c = (idx & 15) << 3;
            size_t g = ((size_t)b * T_ + (size_t)kt * 64 + r) * C_ + colH + c;
            uint32_t so = (uint32_t)(st + r * SQ + c);
            cp16(sb + 2u * (so + FL_KF), kf + g);
            cp16(sb + 2u * (so + FL_VF), vf + g);
        }
        asm volatile("cp.async.commit_group;");
    };

    const int nkt = 2 * qb + 2;   // >= 2
    issueKV(0, 0);
    if (nkt > 1) issueKV(1, 1);
    if (nkt > 2) issueKV(2, 2);

    const float scale = 0.088388347648318447f;

    float m0 = -CUDART_INF_F, m1 = -CUDART_INF_F, l0 = 0.f, l1 = 0.f;
    float oacc[16][4];
    #pragma unroll
    for (int j = 0; j < 16; j++)
        #pragma unroll
        for (int e = 0; e < 4; e++) oacc[j][e] = 0.f;

    for (int kt = 0; kt < nkt; kt++) {
        if (kt + 3 < nkt) { asm volatile("cp.async.wait_group 2;"); }
        else              { asm volatile("cp.async.wait_group 0;"); }
        __syncthreads();
        if (kt + 3 < nkt) issueKV((kt + 3) & 3, kt + 3);

        const int kb = kt * 64;
        if (kb <= gq0 + 15) {
            const uint32_t st = (kt & 3) * FL_STAGE;

            // ---- S = Q K^T (fp16 single) ----
            float sacc[8][4];
            #pragma unroll
            for (int j = 0; j < 8; j++)
                #pragma unroll
                for (int e = 0; e < 4; e++) sacc[j][e] = 0.f;

            #pragma unroll
            for (int c = 0; c < 8; c++) {
                uint32_t bkv[8][2];
                #pragma unroll
                for (int jt = 0; jt < 4; jt++) {
                    uint32_t ad = sb + 2u * (uint32_t)(st + FL_KF + (jt * 16 + nlane) * SQ + c * 16 + klB);
                    ldmx4(bkv[2*jt][0], bkv[2*jt][1], bkv[2*jt+1][0], bkv[2*jt+1][1], ad);
                }
                #pragma unroll
                for (int j = 0; j < 8; j++) mmah16(sacc[j], qr[c], bkv[j]);
            }

            // ---- mask + scale + online softmax ----
            const bool diag = (kb + 63 > gq0);
            const int r0 = gq0 + (lane >> 2), r1 = r0 + 8;
            float tm0 = -CUDART_INF_F, tm1 = -CUDART_INF_F;
            #pragma unroll
            for (int j = 0; j < 8; j++) {
                int cc = kb + j * 8 + ((lane & 3) << 1);
                float v0 = sacc[j][0] * scale, v1 = sacc[j][1] * scale;
                float v2 = sacc[j][2] * scale, v3 = sacc[j][3] * scale;
                if (diag) {
                    if (cc     > r0) v0 = -CUDART_INF_F;
                    if (cc + 1 > r0) v1 = -CUDART_INF_F;
                    if (cc     > r1) v2 = -CUDART_INF_F;
                    if (cc + 1 > r1) v3 = -CUDART_INF_F;
                }
                sacc[j][0] = v0; sacc[j][1] = v1; sacc[j][2] = v2; sacc[j][3] = v3;
                tm0 = fmaxf(tm0, fmaxf(v0, v1));
                tm1 = fmaxf(tm1, fmaxf(v2, v3));
            }
            tm0 = fmaxf(tm0, __shfl_xor_sync(0xffffffffu, tm0, 1));
            tm0 = fmaxf(tm0, __shfl_xor_sync(0xffffffffu, tm0, 2));
            tm1 = fmaxf(tm1, __shfl_xor_sync(0xffffffffu, tm1, 1));
            tm1 = fmaxf(tm1, __shfl_xor_sync(0xffffffffu, tm1, 2));
            float mn0 = fmaxf(m0, tm0), mn1 = fmaxf(m1, tm1);
            float a0 = __expf(m0 - mn0), a1 = __expf(m1 - mn1);
            float rs0 = 0.f, rs1 = 0.f;
            #pragma unroll
            for (int j = 0; j < 8; j++) {
                float p0 = __expf(sacc[j][0] - mn0);
                float p1 = __expf(sacc[j][1] - mn0);
                float p2 = __expf(sacc[j][2] - mn1);
                float p3 = __expf(sacc[j][3] - mn1);
                sacc[j][0] = p0; sacc[j][1] = p1; sacc[j][2] = p2; sacc[j][3] = p3;
                rs0 += p0 + p1; rs1 += p2 + p3;
            }
            rs0 += __shfl_xor_sync(0xffffffffu, rs0, 1);
            rs0 += __shfl_xor_sync(0xffffffffu, rs0, 2);
            rs1 += __shfl_xor_sync(0xffffffffu, rs1, 1);
            rs1 += __shfl_xor_sync(0xffffffffu, rs1, 2);
            l0 = l0 * a0 + rs0; l1 = l1 * a1 + rs1;
            m0 = mn0; m1 = mn1;
            #pragma unroll
            for (int j = 0; j < 16; j++) {
                oacc[j][0] *= a0; oacc[j][1] *= a0;
                oacc[j][2] *= a1; oacc[j][3] *= a1;
            }

            // ---- P fragments (fp16) ----
            uint32_t pf[4][4];
            #pragma unroll
            for (int c = 0; c < 4; c++) {
                pf[c][0] = pack_f16(sacc[2*c][0],   sacc[2*c][1]);
                pf[c][1] = pack_f16(sacc[2*c][2],   sacc[2*c][3]);
                pf[c][2] = pack_f16(sacc[2*c+1][0], sacc[2*c+1][1]);
                pf[c][3] = pack_f16(sacc[2*c+1][2], sacc[2*c+1][3]);
            }

            // ---- O += P V (fp16), V via ldmatrix.trans ----
            const int vrow = ((lane >> 3) & 1) * 8 + (lane & 7);
            const int vcol = (lane >> 4) << 3;
            #pragma unroll
            for (int c = 0; c < 4; c++) {
                #pragma unroll
                for (int dt = 0; dt < 8; dt++) {
                    uint32_t bv[4];
                    uint32_t ad = sb + 2u * (uint32_t)(st + FL_VF + (c * 16 + vrow) * SQ + dt * 16 + vcol);
                    ldmx4t(bv[0], bv[1], bv[2], bv[3], ad);
                    mmah16(oacc[2*dt],   pf[c], bv);
                    mmah16(oacc[2*dt+1], pf[c], bv + 2);
                }
            }
        }
    }

    float inv0 = 1.0f / l0, inv1 = 1.0f / l1;
    size_t grow0 = (rowQ + wq + (lane >> 2)) * C_;
    size_t grow1 = grow0 + 8 * C_;
    #pragma unroll
    for (int j = 0; j < 16; j++) {
        int col = colH + j * 8 + ((lane & 3) << 1);
        *(uint32_t*)&of[grow0 + col] = pack_f16(oacc[j][0] * inv0, oacc[j][1] * inv0);
        *(uint32_t*)&of[grow1 + col] = pack_f16(oacc[j][2] * inv1, oacc[j][3] * inv1);
    }
}

// ---------------------------------------------------------------------------
extern "C" void kernel_launch(void* const* d_in, const int* in_sizes, int n_in,
                              void* d_out, int out_size)
{
    (void)in_sizes; (void)n_in; (void)out_size;
    const float* x  = (const float*)d_in[0];
    const float* cs = (const float*)d_in[1];
    const float* sn = (const float*)d_in[2];
    float* out = (float*)d_out;

    __half *xf, *qf, *kf, *vf, *of, *wf;
    cudaGetSymbolAddress((void**)&xf, g_xf);
    cudaGetSymbolAddress((void**)&qf, g_qf);
    cudaGetSymbolAddress((void**)&kf, g_kf);
    cudaGetSymbolAddress((void**)&vf, g_vf);
    cudaGetSymbolAddress((void**)&of, g_of);
    cudaGetSymbolAddress((void**)&wf, g_wf);

    cudaFuncSetAttribute(qkv_gemm, cudaFuncAttributeMaxDynamicSharedMemorySize, QKV_SMEM);
    cudaFuncSetAttribute(hgemm_o,  cudaFuncAttributeMaxDynamicSharedMemorySize, H_SMEM);
    cudaFuncSetAttribute(flash_f16, cudaFuncAttributeMaxDynamicSharedMemorySize, FLASH_SMEM);

    const int ntot = NX4 + 4 * NW4;
    split_all<<<ntot / 256, 256>>>((const float4*)x,
        (const float4*)d_in[3], (const float4*)d_in[4],
        (const float4*)d_in[5], (const float4*)d_in[6],
        (uint2*)xf, (uint2*)wf);

    qkv_gemm<<<dim3(48, 32), 256, QKV_SMEM>>>(xf, wf, cs, sn, qf, kf, vf);

    flash_f16<<<dim3(T_/128, B_*H_), 256, FLASH_SMEM>>>(qf, kf, vf, of);

    hgemm_o<<<dim3(16, 32), 256, H_SMEM>>>(of, wf + 3*(size_t)C_*C_, out, C_, C_);
}

// round 12
// speedup vs baseline: 2.2849x; 1.0203x over previous
#include <cuda_runtime.h>
#include <cuda_bf16.h>
#include <cuda_fp16.h>
#include <math_constants.h>
#include <cstdint>

#define B_ 2
#define T_ 2048
#define C_ 2048
#define H_ 16
#define D_ 128
#define M_ (B_*T_)   // 4096 rows

// ---------------- scratch (static device globals) ----------------
__device__ __half g_xf[(size_t)M_ * C_];
__device__ __half g_qf[(size_t)M_ * C_];
__device__ __half g_kf[(size_t)M_ * C_];
__device__ __half g_vf[(size_t)M_ * C_];
__device__ __half g_of[(size_t)M_ * C_];
__device__ __half g_wf[4][(size_t)C_ * C_];   // Wq, Wk, Wv, Wo fp16

union HU { __half2 h; uint32_t u; };

__device__ __forceinline__ uint32_t pack_f16(float x, float y) {
    HU u; u.h = __floats2half2_rn(x, y); return u.u;
}

// ---------------------------------------------------------------------------
// split kernel: x, W0..W3 -> fp16
// ---------------------------------------------------------------------------
#define NX4 ((M_*C_)/4)
#define NW4 ((C_*C_)/4)

__global__ __launch_bounds__(256) void split_all(
    const float4* __restrict__ x,
    const float4* __restrict__ w0, const float4* __restrict__ w1,
    const float4* __restrict__ w2, const float4* __restrict__ w3,
    uint2* __restrict__ xf, uint2* __restrict__ wf)
{
    int i = blockIdx.x * blockDim.x + threadIdx.x;
    const float4* src;
    uint2* dst;
    int off;
    if (i < NX4) {
        src = x; off = i; dst = xf;
    } else {
        int j = i - NX4;
        int w = j / NW4;
        off = j - w * NW4;
        src = (w == 0) ? w0 : (w == 1) ? w1 : (w == 2) ? w2 : w3;
        dst = wf + (size_t)w * NW4;
    }
    float4 v = src[off];
    dst[off] = make_uint2(pack_f16(v.x, v.y), pack_f16(v.z, v.w));
}

// ---------------------------------------------------------------------------
// primitives
// ---------------------------------------------------------------------------
__device__ __forceinline__ void ldmx4(uint32_t &r0, uint32_t &r1, uint32_t &r2, uint32_t &r3, uint32_t addr) {
    asm volatile("ldmatrix.sync.aligned.m8n8.x4.shared.b16 {%0,%1,%2,%3}, [%4];"
                 : "=r"(r0), "=r"(r1), "=r"(r2), "=r"(r3) : "r"(addr));
}
__device__ __forceinline__ void ldmx4t(uint32_t &r0, uint32_t &r1, uint32_t &r2, uint32_t &r3, uint32_t addr) {
    asm volatile("ldmatrix.sync.aligned.m8n8.x4.trans.shared.b16 {%0,%1,%2,%3}, [%4];"
                 : "=r"(r0), "=r"(r1), "=r"(r2), "=r"(r3) : "r"(addr));
}
__device__ __forceinline__ void mmah16(float* d, const uint32_t* a, const uint32_t* b) {
    asm volatile("mma.sync.aligned.m16n8k16.row.col.f32.f16.f16.f32 "
                 "{%0,%1,%2,%3},{%4,%5,%6,%7},{%8,%9},{%0,%1,%2,%3};"
                 : "+f"(d[0]), "+f"(d[1]), "+f"(d[2]), "+f"(d[3])
                 : "r"(a[0]), "r"(a[1]), "r"(a[2]), "r"(a[3]), "r"(b[0]), "r"(b[1]));
}
__device__ __forceinline__ void cp16(uint32_t saddr, const void* g) {
    asm volatile("cp.async.cg.shared.global [%0], [%1], 16;" :: "r"(saddr), "l"(g));
}
__device__ __forceinline__ uint32_t swz128(uint32_t off) { return off ^ ((off >> 3) & 0x70); }

// ---------------------------------------------------------------------------
// fp16 GEMM geometry: 128x128 CTA tile, BK=64, 8 warps (32x64), 3 stages.
// Subtile = 128 rows x 128 B (SW128). Stage = A + B = 32 KB.
// ---------------------------------------------------------------------------
#define K_SUB 16384
#define K_STAGE (2*K_SUB)                // 32768 B
#define K_SMEM (3*K_STAGE)               // 98304 B
#define FTS 133
#define QKV_SMEM (K_SMEM)                // 98304 (> 128*FTS*4 = 68096)

// One BK=64 compute block: 4 kk-steps, 24 ldsm, 64 mma.
#define HG_STAGE_BODY(st)                                                             \
    _Pragma("unroll")                                                                 \
    for (int kk = 0; kk < 64; kk += 16) {                                             \
        uint32_t a[2][4], b[8][2];                                                    \
        _Pragma("unroll")                                                             \
        for (int t = 0; t < 2; t++) {                                                 \
            uint32_t rb = (uint32_t)((warp_m * 32 + t * 16 + mlane) * 128 + (kk + aoff) * 2); \
            ldmx4(a[t][0], a[t][1], a[t][2], a[t][3], (st) + swz128(rb));             \
        }                                                                             \
        _Pragma("unroll")                                                             \
        for (int jt = 0; jt < 4; jt++) {                                              \
            uint32_t rb = (uint32_t)((warp_n * 64 + jt * 16 + nlane) * 128 + (kk + klBo) * 2); \
            ldmx4(b[2*jt][0], b[2*jt][1], b[2*jt+1][0], b[2*jt+1][1], (st) + K_SUB + swz128(rb)); \
        }                                                                             \
        _Pragma("unroll")                                                             \
        for (int t = 0; t < 2; t++)                                                   \
            _Pragma("unroll")                                                         \
            for (int j = 0; j < 8; j++) mmah16(acc[t][j], a[t], b[j]);                \
    }

// ---------------------------------------------------------------------------
// Fused QKV fp16 GEMM + (rmsnorm+RoPE | passthrough) epilogue.
// grid (48, 32): bx>>4 = kind (0=q 1=k 2=v), bx&15 = head.
// ---------------------------------------------------------------------------
__global__ __launch_bounds__(256, 2) void qkv_gemm(
    const __half* __restrict__ xf, const __half* __restrict__ wf,
    const float* __restrict__ cs, const float* __restrict__ sn,
    __half* __restrict__ qf, __half* __restrict__ kf, __half* __restrict__ vf)
{
    extern __shared__ __align__(1024) char smg[];
    const int tid = threadIdx.x, lane = tid & 31, wid = tid >> 5;
    const int warp_m = wid & 3;
    const int warp_n = wid >> 2;
    const int bm = blockIdx.y;
    const int kind = blockIdx.x >> 4;
    const int lbn  = blockIdx.x & 15;
    const uint32_t sb = (uint32_t)__cvta_generic_to_shared(smg);

    const __half* Bf = wf + (size_t)kind * C_ * C_;

    float acc[2][8][4];
    #pragma unroll
    for (int i = 0; i < 2; i++)
        #pragma unroll
        for (int j = 0; j < 8; j++)
            #pragma unroll
            for (int e = 0; e < 4; e++) acc[i][j][e] = 0.f;

    auto issue = [&](int s, int k0) {
        const uint32_t st = sb + s * K_STAGE;
        #pragma unroll
        for (int it = 0; it < 8; it++) {
            int j   = tid + it * 256;
            int sub = j >> 10;           // 0=A, 1=B
            int cid = j & 1023;
            int r   = cid >> 3;
            int ch  = cid & 7;
            int grow = (sub ? lbn : bm) * 128 + r;
            const __half* g = (sub ? Bf : xf) + (size_t)grow * C_ + k0 + ch * 8;
            cp16(st + sub * K_SUB + swz128((uint32_t)(r * 128 + ch * 16)), g);
        }
        asm volatile("cp.async.commit_group;");
    };

    const int NS = C_ / 64;   // 32
    issue(0, 0);
    issue(1, 64);

    const int mlane = lane & 15;
    const int aoff  = (lane >> 4) << 3;
    const int nlane = (lane & 7) + ((lane >> 4) << 3);
    const int klBo  = ((lane >> 3) & 1) << 3;

    for (int i = 0; i < NS; i++) {
        if (i == NS - 1) { asm volatile("cp.async.wait_group 0;"); }
        else             { asm volatile("cp.async.wait_group 1;"); }
        __syncthreads();
        if (i + 2 < NS) issue((i + 2) % 3, (i + 2) * 64);

        const uint32_t st = sb + (i % 3) * K_STAGE;
        HG_STAGE_BODY(st)
    }
    __syncthreads();   // protect smem before epilogue staging reuse

    if (kind == 2) {
        // V: passthrough fp16
        #pragma unroll
        for (int t = 0; t < 2; t++) {
            int row = bm * 128 + warp_m * 32 + t * 16 + (lane >> 2);
            #pragma unroll
            for (int j = 0; j < 8; j++) {
                int col = lbn * 128 + warp_n * 64 + j * 8 + ((lane & 3) << 1);
                *(uint32_t*)&vf[(size_t)row * C_ + col]       = pack_f16(acc[t][j][0], acc[t][j][1]);
                *(uint32_t*)&vf[(size_t)(row + 8) * C_ + col] = pack_f16(acc[t][j][2], acc[t][j][3]);
            }
        }
    } else {
        // Q/K: rmsnorm + rope epilogue via fp32 smem staging
        float* ft = (float*)smg;
        #pragma unroll
        for (int t = 0; t < 2; t++) {
            int rl0 = warp_m * 32 + t * 16 + (lane >> 2);
            #pragma unroll
            for (int j = 0; j < 8; j++) {
                int cl = warp_n * 64 + j * 8 + ((lane & 3) << 1);
                ft[rl0 * FTS + cl]           = acc[t][j][0];
                ft[rl0 * FTS + cl + 1]       = acc[t][j][1];
                ft[(rl0 + 8) * FTS + cl]     = acc[t][j][2];
                ft[(rl0 + 8) * FTS + cl + 1] = acc[t][j][3];
            }
        }
        __syncthreads();

        const int r  = tid >> 1;
        const int hh = tid & 1;
        const int cb = hh * 32;
        const float* fr = ft + r * FTS;

        float ss = 0.f;
        #pragma unroll
        for (int i2 = 0; i2 < 32; i2++) {
            float a = fr[cb + i2];
            float b = fr[cb + 64 + i2];
            ss += a * a + b * b;
        }
        ss += __shfl_xor_sync(0xffffffffu, ss, 1);
        float rms = rsqrtf(ss * (1.0f / 128.0f) + 1.1920929e-7f);

        const int grow = bm * 128 + r;
        const int t    = grow & (T_ - 1);
        __half* Of = kind ? kf : qf;
        const size_t rb = (size_t)grow * C_ + lbn * 128;

        #pragma unroll
        for (int i2 = 0; i2 < 32; i2 += 2) {
            int c0 = cb + i2;
            float a0 = fr[c0] * rms,     b0 = fr[c0 + 64] * rms;
            float a1 = fr[c0 + 1] * rms, b1 = fr[c0 + 65] * rms;
            float co0 = cs[t * 64 + c0], si0 = sn[t * 64 + c0];
            float co1 = cs[t * 64 + c0 + 1], si1 = sn[t * 64 + c0 + 1];
            float y10 =  a0 * co0 + b0 * si0;
            float y11 =  a1 * co1 + b1 * si1;
            float y20 = -a0 * si0 + b0 * co0;
            float y21 = -a1 * si1 + b1 * co1;
            *(uint32_t*)&Of[rb + c0]      = pack_f16(y10, y11);
            *(uint32_t*)&Of[rb + c0 + 64] = pack_f16(y20, y21);
        }
    }
}

// ---------------------------------------------------------------------------
// O-projection fp16 GEMM (fp32 out). grid (16, 32).
// ---------------------------------------------------------------------------
__global__ __launch_bounds__(256, 2) void hgemm_o(
    const __half* __restrict__ Af, const __half* __restrict__ Bf,
    float* __restrict__ Cc, int Nn, int K)
{
    extern __shared__ __align__(1024) char smg[];
    const int tid = threadIdx.x, lane = tid & 31, wid = tid >> 5;
    const int warp_m = wid & 3;
    const int warp_n = wid >> 2;
    const int bm = blockIdx.y, bn = blockIdx.x;
    const uint32_t sb = (uint32_t)__cvta_generic_to_shared(smg);

    float acc[2][8][4];
    #pragma unroll
    for (int i = 0; i < 2; i++)
        #pragma unroll
        for (int j = 0; j < 8; j++)
            #pragma unroll
            for (int e = 0; e < 4; e++) acc[i][j][e] = 0.f;

    auto issue = [&](int s, int k0) {
        const uint32_t st = sb + s * K_STAGE;
        #pragma unroll
        for (int it = 0; it < 8; it++) {
            int j   = tid + it * 256;
            int sub = j >> 10;
            int cid = j & 1023;
            int r   = cid >> 3;
            int ch  = cid & 7;
            int grow = (sub ? bn : bm) * 128 + r;
            const __half* g = (sub ? Bf : Af) + (size_t)grow * K + k0 + ch * 8;
            cp16(st + sub * K_SUB + swz128((uint32_t)(r * 128 + ch * 16)), g);
        }
        asm volatile("cp.async.commit_group;");
    };

    const int NS = K / 64;   // 32
    issue(0, 0);
    issue(1, 64);

    const int mlane = lane & 15;
    const int aoff  = (lane >> 4) << 3;
    const int nlane = (lane & 7) + ((lane >> 4) << 3);
    const int klBo  = ((lane >> 3) & 1) << 3;

    for (int i = 0; i < NS; i++) {
        if (i == NS - 1) { asm volatile("cp.async.wait_group 0;"); }
        else             { asm volatile("cp.async.wait_group 1;"); }
        __syncthreads();
        if (i + 2 < NS) issue((i + 2) % 3, (i + 2) * 64);

        const uint32_t st = sb + (i % 3) * K_STAGE;
        HG_STAGE_BODY(st)
    }

    #pragma unroll
    for (int t = 0; t < 2; t++) {
        int row = bm * 128 + warp_m * 32 + t * 16 + (lane >> 2);
        #pragma unroll
        for (int j = 0; j < 8; j++) {
            int col = bn * 128 + warp_n * 64 + j * 8 + ((lane & 3) << 1);
            *(float2*)&Cc[(size_t)row * Nn + col]       = make_float2(acc[t][j][0], acc[t][j][1]);
            *(float2*)&Cc[(size_t)(row + 8) * Nn + col] = make_float2(acc[t][j][2], acc[t][j][3]);
        }
    }
}

// ---------------------------------------------------------------------------
// Tensor-core flash attention (causal), full fp16 mma, fp32 softmax/accum.
// Q fragments in registers; KV (kf + vf) 4-stage pipeline.
// ---------------------------------------------------------------------------
#define SQ 136
#define FL_STAGE (2*64*SQ)               // elems per stage (KF, VF)
#define FL_KF 0
#define FL_VF (64*SQ)
#define FLASH_SMEM (4*FL_STAGE*2)        // 139264 bytes

__global__ __launch_bounds__(256, 1) void flash_f16(
    const __half* __restrict__ qf, const __half* __restrict__ kf,
    const __half* __restrict__ vf, __half* __restrict__ of)
{
    extern __shared__ __half smf[];
    const int tid = threadIdx.x, lane = tid & 31, wid = tid >> 5;
    const int qb = gridDim.x - 1 - blockIdx.x;
    const int b  = blockIdx.y >> 4, h = blockIdx.y & 15;
    const uint32_t sb = (uint32_t)__cvta_generic_to_shared(smf);
    const size_t rowQ = (size_t)b * T_ + (size_t)qb * 128;
    const int colH = h * D_;

    const int wq = wid * 16;
    const int gq0 = qb * 128 + wq;
    const int mlane = lane & 15;
    const int aoff  = (lane >> 4) << 3;
    const int nlane = (lane & 7) + ((lane >> 4) << 3);
    const int klB   = ((lane >> 3) & 1) << 3;

    // ---- stage Q through smem, extract fragments to registers ----
    #pragma unroll
    for (int it = 0; it < 8; it++) {
        int idx = tid + it * 256;
        int r = idx >> 4, c = (idx & 15) << 3;
        cp16(sb + 2u * (uint32_t)(r * SQ + c), qf + (rowQ + r) * C_ + colH + c);
    }
    asm volatile("cp.async.commit_group;");
    asm volatile("cp.async.wait_group 0;");
    __syncthreads();

    uint32_t qr[8][4];
    #pragma unroll
    for (int c = 0; c < 8; c++) {
        uint32_t ad = sb + 2u * (uint32_t)((wq + mlane) * SQ + c * 16 + aoff);
        ldmx4(qr[c][0], qr[c][1], qr[c][2], qr[c][3], ad);
    }
    __syncthreads();

    auto issueKV = [&](int s, int kt) {
        uint32_t st = s * FL_STAGE;
        #pragma unroll
        for (int it = 0; it < 4; it++) {
            int idx = tid + it * 256;
            int r = idx >> 4, c = (idx & 15) << 3;
            size_t g = ((size_t)b * T_ + (size_t)kt * 64 + r) * C_ + colH + c;
            uint32_t so = (uint32_t)(st + r * SQ + c);
            cp16(sb + 2u * (so + FL_KF), kf + g);
            cp16(sb + 2u * (so + FL_VF), vf + g);
        }
        asm volatile("cp.async.commit_group;");
    };

    const int nkt = 2 * qb + 2;   // >= 2
    issueKV(0, 0);
    if (nkt > 1) issueKV(1, 1);
    if (nkt > 2) issueKV(2, 2);

    const float scale = 0.088388347648318447f;

    float m0 = -CUDART_INF_F, m1 = -CUDART_INF_F, l0 = 0.f, l1 = 0.f;
    float oacc[16][4];
    #pragma unroll
    for (int j = 0; j < 16; j++)
        #pragma unroll
        for (int e = 0; e < 4; e++) oacc[j][e] = 0.f;

    for (int kt = 0; kt < nkt; kt++) {
        if (kt + 3 < nkt) { asm volatile("cp.async.wait_group 2;"); }
        else              { asm volatile("cp.async.wait_group 0;"); }
        __syncthreads();
        if (kt + 3 < nkt) issueKV((kt + 3) & 3, kt + 3);

        const int kb = kt * 64;
        if (kb <= gq0 + 15) {
            const uint32_t st = (kt & 3) * FL_STAGE;

            float sacc[8][4];
            #pragma unroll
            for (int j = 0; j < 8; j++)
                #pragma unroll
                for (int e = 0; e < 4; e++) sacc[j][e] = 0.f;

            #pragma unroll
            for (int c = 0; c < 8; c++) {
                uint32_t bkv[8][2];
                #pragma unroll
                for (int jt = 0; jt < 4; jt++) {
                    uint32_t ad = sb + 2u * (uint32_t)(st + FL_KF + (jt * 16 + nlane) * SQ + c * 16 + klB);
                    ldmx4(bkv[2*jt][0], bkv[2*jt][1], bkv[2*jt+1][0], bkv[2*jt+1][1], ad);
                }
                #pragma unroll
                for (int j = 0; j < 8; j++) mmah16(sacc[j], qr[c], bkv[j]);
            }

            const bool diag = (kb + 63 > gq0);
            const int r0 = gq0 + (lane >> 2), r1 = r0 + 8;
            float tm0 = -CUDART_INF_F, tm1 = -CUDART_INF_F;
            #pragma unroll
            for (int j = 0; j < 8; j++) {
                int cc = kb + j * 8 + ((lane & 3) << 1);
                float v0 = sacc[j][0] * scale, v1 = sacc[j][1] * scale;
                float v2 = sacc[j][2] * scale, v3 = sacc[j][3] * scale;
                if (diag) {
                    if (cc     > r0) v0 = -CUDART_INF_F;
                    if (cc + 1 > r0) v1 = -CUDART_INF_F;
                    if (cc     > r1) v2 = -CUDART_INF_F;
                    if (cc + 1 > r1) v3 = -CUDART_INF_F;
                }
                sacc[j][0] = v0; sacc[j][1] = v1; sacc[j][2] = v2; sacc[j][3] = v3;
                tm0 = fmaxf(tm0, fmaxf(v0, v1));
                tm1 = fmaxf(tm1, fmaxf(v2, v3));
            }
            tm0 = fmaxf(tm0, __shfl_xor_sync(0xffffffffu, tm0, 1));
            tm0 = fmaxf(tm0, __shfl_xor_sync(0xffffffffu, tm0, 2));
            tm1 = fmaxf(tm1, __shfl_xor_sync(0xffffffffu, tm1, 1));
            tm1 = fmaxf(tm1, __shfl_xor_sync(0xffffffffu, tm1, 2));
            float mn0 = fmaxf(m0, tm0), mn1 = fmaxf(m1, tm1);
            float a0 = __expf(m0 - mn0), a1 = __expf(m1 - mn1);
            float rs0 = 0.f, rs1 = 0.f;
            #pragma unroll
            for (int j = 0; j < 8; j++) {
                float p0 = __expf(sacc[j][0] - mn0);
                float p1 = __expf(sacc[j][1] - mn0);
                float p2 = __expf(sacc[j][2] - mn1);
                float p3 = __expf(sacc[j][3] - mn1);
                sacc[j][0] = p0; sacc[j][1] = p1; sacc[j][2] = p2; sacc[j][3] = p3;
                rs0 += p0 + p1; rs1 += p2 + p3;
            }
            rs0 += __shfl_xor_sync(0xffffffffu, rs0, 1);
            rs0 += __shfl_xor_sync(0xffffffffu, rs0, 2);
            rs1 += __shfl_xor_sync(0xffffffffu, rs1, 1);
            rs1 += __shfl_xor_sync(0xffffffffu, rs1, 2);
            l0 = l0 * a0 + rs0; l1 = l1 * a1 + rs1;
            m0 = mn0; m1 = mn1;
            #pragma unroll
            for (int j = 0; j < 16; j++) {
                oacc[j][0] *= a0; oacc[j][1] *= a0;
                oacc[j][2] *= a1; oacc[j][3] *= a1;
            }

            uint32_t pf[4][4];
            #pragma unroll
            for (int c = 0; c < 4; c++) {
                pf[c][0] = pack_f16(sacc[2*c][0],   sacc[2*c][1]);
                pf[c][1] = pack_f16(sacc[2*c][2],   sacc[2*c][3]);
                pf[c][2] = pack_f16(sacc[2*c+1][0], sacc[2*c+1][1]);
                pf[c][3] = pack_f16(sacc[2*c+1][2], sacc[2*c+1][3]);
            }

            const int vrow = ((lane >> 3) & 1) * 8 + (lane & 7);
            const int vcol = (lane >> 4) << 3;
            #pragma unroll
            for (int c = 0; c < 4; c++) {
                #pragma unroll
                for (int dt = 0; dt < 8; dt++) {
                    uint32_t bv[4];
                    uint32_t ad = sb + 2u * (uint32_t)(st + FL_VF + (c * 16 + vrow) * SQ + dt * 16 + vcol);
                    ldmx4t(bv[0], bv[1], bv[2], bv[3], ad);
                    mmah16(oacc[2*dt],   pf[c], bv);
                    mmah16(oacc[2*dt+1], pf[c], bv + 2);
                }
            }
        }
    }

    float inv0 = 1.0f / l0, inv1 = 1.0f / l1;
    size_t grow0 = (rowQ + wq + (lane >> 2)) * C_;
    size_t grow1 = grow0 + 8 * C_;
    #pragma unroll
    for (int j = 0; j < 16; j++) {
        int col = colH + j * 8 + ((lane & 3) << 1);
        *(uint32_t*)&of[grow0 + col] = pack_f16(oacc[j][0] * inv0, oacc[j][1] * inv0);
        *(uint32_t*)&of[grow1 + col] = pack_f16(oacc[j][2] * inv1, oacc[j][3] * inv1);
    }
}

// ---------------------------------------------------------------------------
extern "C" void kernel_launch(void* const* d_in, const int* in_sizes, int n_in,
                              void* d_out, int out_size)
{
    (void)in_sizes; (void)n_in; (void)out_size;
    const float* x  = (const float*)d_in[0];
    const float* cs = (const float*)d_in[1];
    const float* sn = (const float*)d_in[2];
    float* out = (float*)d_out;

    __half *xf, *qf, *kf, *vf, *of, *wf;
    cudaGetSymbolAddress((void**)&xf, g_xf);
    cudaGetSymbolAddress((void**)&qf, g_qf);
    cudaGetSymbolAddress((void**)&kf, g_kf);
    cudaGetSymbolAddress((void**)&vf, g_vf);
    cudaGetSymbolAddress((void**)&of, g_of);
    cudaGetSymbolAddress((void**)&wf, g_wf);

    cudaFuncSetAttribute(qkv_gemm, cudaFuncAttributeMaxDynamicSharedMemorySize, QKV_SMEM);
    cudaFuncSetAttribute(hgemm_o,  cudaFuncAttributeMaxDynamicSharedMemorySize, K_SMEM);
    cudaFuncSetAttribute(flash_f16, cudaFuncAttributeMaxDynamicSharedMemorySize, FLASH_SMEM);

    const int ntot = NX4 + 4 * NW4;
    split_all<<<ntot / 256, 256>>>((const float4*)x,
        (const float4*)d_in[3], (const float4*)d_in[4],
        (const float4*)d_in[5], (const float4*)d_in[6],
        (uint2*)xf, (uint2*)wf);

    qkv_gemm<<<dim3(48, 32), 256, QKV_SMEM>>>(xf, wf, cs, sn, qf, kf, vf);

    flash_f16<<<dim3(T_/128, B_*H_), 256, FLASH_SMEM>>>(qf, kf, vf, of);

    hgemm_o<<<dim3(16, 32), 256, K_SMEM>>>(of, wf + 3*(size_t)C_*C_, out, C_, C_);
}

// round 13
// speedup vs baseline: 2.2932x; 1.0036x over previous
#include <cuda_runtime.h>
#include <cuda_bf16.h>
#include <cuda_fp16.h>
#include <math_constants.h>
#include <cstdint>

#define B_ 2
#define T_ 2048
#define C_ 2048
#define H_ 16
#define D_ 128
#define M_ (B_*T_)   // 4096 rows

// ---------------- scratch (static device globals) ----------------
__device__ __half g_xf[(size_t)M_ * C_];
__device__ __half g_qf[(size_t)M_ * C_];
__device__ __half g_kf[(size_t)M_ * C_];
__device__ __half g_vf[(size_t)M_ * C_];
__device__ __half g_of[(size_t)M_ * C_];
__device__ __half g_wf[4][(size_t)C_ * C_];   // Wq, Wk, Wv, Wo fp16

union HU { __half2 h; uint32_t u; };

__device__ __forceinline__ uint32_t pack_f16(float x, float y) {
    HU u; u.h = __floats2half2_rn(x, y); return u.u;
}

// ---------------------------------------------------------------------------
// split kernel: x, W0..W3 -> fp16. 4 float4 per thread for MLP.
// total elems4 = NX4 + 4*NW4 = 6291456; threads = that/4 = 1572864
// ---------------------------------------------------------------------------
#define NX4 ((M_*C_)/4)
#define NW4 ((C_*C_)/4)
#define NTOT4 (NX4 + 4*NW4)

__global__ __launch_bounds__(512) void split_all(
    const float4* __restrict__ x,
    const float4* __restrict__ w0, const float4* __restrict__ w1,
    const float4* __restrict__ w2, const float4* __restrict__ w3,
    uint2* __restrict__ xf, uint2* __restrict__ wf)
{
    int base = (blockIdx.x * blockDim.x + threadIdx.x) * 4;
    float4 v[4];
    uint2* dsts[4];
    int offs[4];
    #pragma unroll
    for (int e = 0; e < 4; e++) {
        int i = base + e;
        const float4* src;
        uint2* dst;
        int off;
        if (i < NX4) { src = x; off = i; dst = xf; }
        else {
            int j = i - NX4;
            int w = j >> 20;             // NW4 = 1048576 = 2^20
            off = j & (NW4 - 1);
            src = (w == 0) ? w0 : (w == 1) ? w1 : (w == 2) ? w2 : w3;
            dst = wf + (size_t)w * NW4;
        }
        v[e] = src[off];
        dsts[e] = dst; offs[e] = off;
    }
    #pragma unroll
    for (int e = 0; e < 4; e++)
        dsts[e][offs[e]] = make_uint2(pack_f16(v[e].x, v[e].y), pack_f16(v[e].z, v[e].w));
}

// ---------------------------------------------------------------------------
// primitives
// ---------------------------------------------------------------------------
__device__ __forceinline__ void ldmx4(uint32_t &r0, uint32_t &r1, uint32_t &r2, uint32_t &r3, uint32_t addr) {
    asm volatile("ldmatrix.sync.aligned.m8n8.x4.shared.b16 {%0,%1,%2,%3}, [%4];"
                 : "=r"(r0), "=r"(r1), "=r"(r2), "=r"(r3) : "r"(addr));
}
__device__ __forceinline__ void ldmx4t(uint32_t &r0, uint32_t &r1, uint32_t &r2, uint32_t &r3, uint32_t addr) {
    asm volatile("ldmatrix.sync.aligned.m8n8.x4.trans.shared.b16 {%0,%1,%2,%3}, [%4];"
                 : "=r"(r0), "=r"(r1), "=r"(r2), "=r"(r3) : "r"(addr));
}
__device__ __forceinline__ void mmah16(float* d, const uint32_t* a, const uint32_t* b) {
    asm volatile("mma.sync.aligned.m16n8k16.row.col.f32.f16.f16.f32 "
                 "{%0,%1,%2,%3},{%4,%5,%6,%7},{%8,%9},{%0,%1,%2,%3};"
                 : "+f"(d[0]), "+f"(d[1]), "+f"(d[2]), "+f"(d[3])
                 : "r"(a[0]), "r"(a[1]), "r"(a[2]), "r"(a[3]), "r"(b[0]), "r"(b[1]));
}
__device__ __forceinline__ void cp16(uint32_t saddr, const void* g) {
    asm volatile("cp.async.cg.shared.global [%0], [%1], 16;" :: "r"(saddr), "l"(g));
}
__device__ __forceinline__ uint32_t swz128(uint32_t off) { return off ^ ((off >> 3) & 0x70); }

// ---------------------------------------------------------------------------
// fp16 GEMM geometry: 128x128 CTA tile, BK=64, 8 warps (32x64), 3 stages.
// ---------------------------------------------------------------------------
#define K_SUB 16384
#define K_STAGE (2*K_SUB)                // 32768 B
#define K_SMEM (3*K_STAGE)               // 98304 B
#define FTS 133
#define QKV_SMEM (K_SMEM)

#define HG_STAGE_BODY(st)                                                             \
    _Pragma("unroll")                                                                 \
    for (int kk = 0; kk < 64; kk += 16) {                                             \
        uint32_t a[2][4], b[8][2];                                                    \
        _Pragma("unroll")                                                             \
        for (int t = 0; t < 2; t++) {                                                 \
            uint32_t rb = (uint32_t)((warp_m * 32 + t * 16 + mlane) * 128 + (kk + aoff) * 2); \
            ldmx4(a[t][0], a[t][1], a[t][2], a[t][3], (st) + swz128(rb));             \
        }                                                                             \
        _Pragma("unroll")                                                             \
        for (int jt = 0; jt < 4; jt++) {                                              \
            uint32_t rb = (uint32_t)((warp_n * 64 + jt * 16 + nlane) * 128 + (kk + klBo) * 2); \
            ldmx4(b[2*jt][0], b[2*jt][1], b[2*jt+1][0], b[2*jt+1][1], (st) + K_SUB + swz128(rb)); \
        }                                                                             \
        _Pragma("unroll")                                                             \
        for (int t = 0; t < 2; t++)                                                   \
            _Pragma("unroll")                                                         \
            for (int j = 0; j < 8; j++) mmah16(acc[t][j], a[t], b[j]);                \
    }

// ---------------------------------------------------------------------------
// Fused QKV fp16 GEMM + (rmsnorm+RoPE | passthrough) epilogue.
// Q output is PRE-SCALED by 1/sqrt(D).
// ---------------------------------------------------------------------------
__global__ __launch_bounds__(256, 2) void qkv_gemm(
    const __half* __restrict__ xf, const __half* __restrict__ wf,
    const float* __restrict__ cs, const float* __restrict__ sn,
    __half* __restrict__ qf, __half* __restrict__ kf, __half* __restrict__ vf)
{
    extern __shared__ __align__(1024) char smg[];
    const int tid = threadIdx.x, lane = tid & 31, wid = tid >> 5;
    const int warp_m = wid & 3;
    const int warp_n = wid >> 2;
    const int bm = blockIdx.y;
    const int kind = blockIdx.x >> 4;
    const int lbn  = blockIdx.x & 15;
    const uint32_t sb = (uint32_t)__cvta_generic_to_shared(smg);

    const __half* Bf = wf + (size_t)kind * C_ * C_;

    float acc[2][8][4];
    #pragma unroll
    for (int i = 0; i < 2; i++)
        #pragma unroll
        for (int j = 0; j < 8; j++)
            #pragma unroll
            for (int e = 0; e < 4; e++) acc[i][j][e] = 0.f;

    auto issue = [&](int s, int k0) {
        const uint32_t st = sb + s * K_STAGE;
        #pragma unroll
        for (int it = 0; it < 8; it++) {
            int j   = tid + it * 256;
            int sub = j >> 10;
            int cid = j & 1023;
            int r   = cid >> 3;
            int ch  = cid & 7;
            int grow = (sub ? lbn : bm) * 128 + r;
            const __half* g = (sub ? Bf : xf) + (size_t)grow * C_ + k0 + ch * 8;
            cp16(st + sub * K_SUB + swz128((uint32_t)(r * 128 + ch * 16)), g);
        }
        asm volatile("cp.async.commit_group;");
    };

    const int NS = C_ / 64;   // 32
    issue(0, 0);
    issue(1, 64);

    const int mlane = lane & 15;
    const int aoff  = (lane >> 4) << 3;
    const int nlane = (lane & 7) + ((lane >> 4) << 3);
    const int klBo  = ((lane >> 3) & 1) << 3;

    for (int i = 0; i < NS; i++) {
        if (i == NS - 1) { asm volatile("cp.async.wait_group 0;"); }
        else             { asm volatile("cp.async.wait_group 1;"); }
        __syncthreads();
        if (i + 2 < NS) issue((i + 2) % 3, (i + 2) * 64);

        const uint32_t st = sb + (i % 3) * K_STAGE;
        HG_STAGE_BODY(st)
    }
    __syncthreads();

    if (kind == 2) {
        #pragma unroll
        for (int t = 0; t < 2; t++) {
            int row = bm * 128 + warp_m * 32 + t * 16 + (lane >> 2);
            #pragma unroll
            for (int j = 0; j < 8; j++) {
                int col = lbn * 128 + warp_n * 64 + j * 8 + ((lane & 3) << 1);
                *(uint32_t*)&vf[(size_t)row * C_ + col]       = pack_f16(acc[t][j][0], acc[t][j][1]);
                *(uint32_t*)&vf[(size_t)(row + 8) * C_ + col] = pack_f16(acc[t][j][2], acc[t][j][3]);
            }
        }
    } else {
        float* ft = (float*)smg;
        #pragma unroll
        for (int t = 0; t < 2; t++) {
            int rl0 = warp_m * 32 + t * 16 + (lane >> 2);
            #pragma unroll
            for (int j = 0; j < 8; j++) {
                int cl = warp_n * 64 + j * 8 + ((lane & 3) << 1);
                ft[rl0 * FTS + cl]           = acc[t][j][0];
                ft[rl0 * FTS + cl + 1]       = acc[t][j][1];
                ft[(rl0 + 8) * FTS + cl]     = acc[t][j][2];
                ft[(rl0 + 8) * FTS + cl + 1] = acc[t][j][3];
            }
        }
        __syncthreads();

        const int r  = tid >> 1;
        const int hh = tid & 1;
        const int cb = hh * 32;
        const float* fr = ft + r * FTS;

        float ss = 0.f;
        #pragma unroll
        for (int i2 = 0; i2 < 32; i2++) {
            float a = fr[cb + i2];
            float b = fr[cb + 64 + i2];
            ss += a * a + b * b;
        }
        ss += __shfl_xor_sync(0xffffffffu, ss, 1);
        float rms = rsqrtf(ss * (1.0f / 128.0f) + 1.1920929e-7f);
        if (kind == 0) rms *= 0.088388347648318447f;   // fold 1/sqrt(D) into Q

        const int grow = bm * 128 + r;
        const int t    = grow & (T_ - 1);
        __half* Of = kind ? kf : qf;
        const size_t rb = (size_t)grow * C_ + lbn * 128;

        #pragma unroll
        for (int i2 = 0; i2 < 32; i2 += 2) {
            int c0 = cb + i2;
            float a0 = fr[c0] * rms,     b0 = fr[c0 + 64] * rms;
            float a1 = fr[c0 + 1] * rms, b1 = fr[c0 + 65] * rms;
            float co0 = cs[t * 64 + c0], si0 = sn[t * 64 + c0];
            float co1 = cs[t * 64 + c0 + 1], si1 = sn[t * 64 + c0 + 1];
            float y10 =  a0 * co0 + b0 * si0;
            float y11 =  a1 * co1 + b1 * si1;
            float y20 = -a0 * si0 + b0 * co0;
            float y21 = -a1 * si1 + b1 * co1;
            *(uint32_t*)&Of[rb + c0]      = pack_f16(y10, y11);
            *(uint32_t*)&Of[rb + c0 + 64] = pack_f16(y20, y21);
        }
    }
}

// ---------------------------------------------------------------------------
// O-projection fp16 GEMM (fp32 out). grid (16, 32).
// ---------------------------------------------------------------------------
__global__ __launch_bounds__(256, 2) void hgemm_o(
    const __half* __restrict__ Af, const __half* __restrict__ Bf,
    float* __restrict__ Cc, int Nn, int K)
{
    extern __shared__ __align__(1024) char smg[];
    const int tid = threadIdx.x, lane = tid & 31, wid = tid >> 5;
    const int warp_m = wid & 3;
    const int warp_n = wid >> 2;
    const int bm = blockIdx.y, bn = blockIdx.x;
    const uint32_t sb = (uint32_t)__cvta_generic_to_shared(smg);

    float acc[2][8][4];
    #pragma unroll
    for (int i = 0; i < 2; i++)
        #pragma unroll
        for (int j = 0; j < 8; j++)
            #pragma unroll
            for (int e = 0; e < 4; e++) acc[i][j][e] = 0.f;

    auto issue = [&](int s, int k0) {
        const uint32_t st = sb + s * K_STAGE;
        #pragma unroll
        for (int it = 0; it < 8; it++) {
            int j   = tid + it * 256;
            int sub = j >> 10;
            int cid = j & 1023;
            int r   = cid >> 3;
            int ch  = cid & 7;
            int grow = (sub ? bn : bm) * 128 + r;
            const __half* g = (sub ? Bf : Af) + (size_t)grow * K + k0 + ch * 8;
            cp16(st + sub * K_SUB + swz128((uint32_t)(r * 128 + ch * 16)), g);
        }
        asm volatile("cp.async.commit_group;");
    };

    const int NS = K / 64;
    issue(0, 0);
    issue(1, 64);

    const int mlane = lane & 15;
    const int aoff  = (lane >> 4) << 3;
    const int nlane = (lane & 7) + ((lane >> 4) << 3);
    const int klBo  = ((lane >> 3) & 1) << 3;

    for (int i = 0; i < NS; i++) {
        if (i == NS - 1) { asm volatile("cp.async.wait_group 0;"); }
        else             { asm volatile("cp.async.wait_group 1;"); }
        __syncthreads();
        if (i + 2 < NS) issue((i + 2) % 3, (i + 2) * 64);

        const uint32_t st = sb + (i % 3) * K_STAGE;
        HG_STAGE_BODY(st)
    }

    #pragma unroll
    for (int t = 0; t < 2; t++) {
        int row = bm * 128 + warp_m * 32 + t * 16 + (lane >> 2);
        #pragma unroll
        for (int j = 0; j < 8; j++) {
            int col = bn * 128 + warp_n * 64 + j * 8 + ((lane & 3) << 1);
            *(float2*)&Cc[(size_t)row * Nn + col]       = make_float2(acc[t][j][0], acc[t][j][1]);
            *(float2*)&Cc[(size_t)(row + 8) * Nn + col] = make_float2(acc[t][j][2], acc[t][j][3]);
        }
    }
}

// ---------------------------------------------------------------------------
// Tensor-core flash attention (causal), fp16 mma, fp32 softmax/accum.
// Q pre-scaled by 1/sqrt(D). Q fragments in registers; KV 4-stage pipeline.
// ---------------------------------------------------------------------------
#define SQ 136
#define FL_STAGE (2*64*SQ)
#define FL_KF 0
#define FL_VF (64*SQ)
#define FLASH_SMEM (4*FL_STAGE*2)        // 139264 bytes

__global__ __launch_bounds__(256, 1) void flash_f16(
    const __half* __restrict__ qf, const __half* __restrict__ kf,
    const __half* __restrict__ vf, __half* __restrict__ of)
{
    extern __shared__ __half smf[];
    const int tid = threadIdx.x, lane = tid & 31, wid = tid >> 5;
    const int qb = gridDim.x - 1 - blockIdx.x;
    const int b  = blockIdx.y >> 4, h = blockIdx.y & 15;
    const uint32_t sb = (uint32_t)__cvta_generic_to_shared(smf);
    const size_t rowQ = (size_t)b * T_ + (size_t)qb * 128;
    const int colH = h * D_;

    const int wq = wid * 16;
    const int gq0 = qb * 128 + wq;
    const int mlane = lane & 15;
    const int aoff  = (lane >> 4) << 3;
    const int nlane = (lane & 7) + ((lane >> 4) << 3);
    const int klB   = ((lane >> 3) & 1) << 3;

    // ---- stage Q, extract fragments ----
    #pragma unroll
    for (int it = 0; it < 8; it++) {
        int idx = tid + it * 256;
        int r = idx >> 4, c = (idx & 15) << 3;
        cp16(sb + 2u * (uint32_t)(r * SQ + c), qf + (rowQ + r) * C_ + colH + c);
    }
    asm volatile("cp.async.commit_group;");
    asm volatile("cp.async.wait_group 0;");
    __syncthreads();

    uint32_t qr[8][4];
    #pragma unroll
    for (int c = 0; c < 8; c++) {
        uint32_t ad = sb + 2u * (uint32_t)((wq + mlane) * SQ + c * 16 + aoff);
        ldmx4(qr[c][0], qr[c][1], qr[c][2], qr[c][3], ad);
    }
    __syncthreads();

    // hoisted per-warp fragment base offsets (bytes, stage-relative)
    uint32_t kbase[4], vbase[4];
    {
        const int vrow = ((lane >> 3) & 1) * 8 + (lane & 7);
        const int vcol = (lane >> 4) << 3;
        #pragma unroll
        for (int jt = 0; jt < 4; jt++)
            kbase[jt] = 2u * (uint32_t)(FL_KF + (jt * 16 + nlane) * SQ + klB);
        #pragma unroll
        for (int c = 0; c < 4; c++)
            vbase[c] = 2u * (uint32_t)(FL_VF + (c * 16 + vrow) * SQ + vcol);
    }

    auto issueKV = [&](int s, int kt) {
        uint32_t st = s * FL_STAGE;
        #pragma unroll
        for (int it = 0; it < 4; it++) {
            int idx = tid + it * 256;
            int r = idx >> 4, c = (idx & 15) << 3;
            size_t g = ((size_t)b * T_ + (size_t)kt * 64 + r) * C_ + colH + c;
            uint32_t so = (uint32_t)(st + r * SQ + c);
            cp16(sb + 2u * (so + FL_KF), kf + g);
            cp16(sb + 2u * (so + FL_VF), vf + g);
        }
        asm volatile("cp.async.commit_group;");
    };

    const int nkt = 2 * qb + 2;
    issueKV(0, 0);
    if (nkt > 1) issueKV(1, 1);
    if (nkt > 2) issueKV(2, 2);

    float m0 = -CUDART_INF_F, m1 = -CUDART_INF_F, l0 = 0.f, l1 = 0.f;
    float oacc[16][4];
    #pragma unroll
    for (int j = 0; j < 16; j++)
        #pragma unroll
        for (int e = 0; e < 4; e++) oacc[j][e] = 0.f;

    for (int kt = 0; kt < nkt; kt++) {
        if (kt + 3 < nkt) { asm volatile("cp.async.wait_group 2;"); }
        else              { asm volatile("cp.async.wait_group 0;"); }
        __syncthreads();
        if (kt + 3 < nkt) issueKV((kt + 3) & 3, kt + 3);

        const int kb = kt * 64;
        if (kb <= gq0 + 15) {
            const uint32_t stB = sb + 2u * (uint32_t)((kt & 3) * FL_STAGE);

            // ---- S = Q K^T ----  (Q pre-scaled: sacc is already s*scale)
            float sacc[8][4];
            #pragma unroll
            for (int j = 0; j < 8; j++)
                #pragma unroll
                for (int e = 0; e < 4; e++) sacc[j][e] = 0.f;

            #pragma unroll
            for (int c = 0; c < 8; c++) {
                uint32_t bkv[8][2];
                #pragma unroll
                for (int jt = 0; jt < 4; jt++) {
                    ldmx4(bkv[2*jt][0], bkv[2*jt][1], bkv[2*jt+1][0], bkv[2*jt+1][1],
                          stB + kbase[jt] + 2u * (uint32_t)(c * 16));
                }
                #pragma unroll
                for (int j = 0; j < 8; j++) mmah16(sacc[j], qr[c], bkv[j]);
            }

            // ---- mask + online softmax ----
            const bool diag = (kb + 63 > gq0);
            const int r0 = gq0 + (lane >> 2), r1 = r0 + 8;
            float tm0 = -CUDART_INF_F, tm1 = -CUDART_INF_F;
            #pragma unroll
            for (int j = 0; j < 8; j++) {
                if (diag) {
                    int cc = kb + j * 8 + ((lane & 3) << 1);
                    if (cc     > r0) sacc[j][0] = -CUDART_INF_F;
                    if (cc + 1 > r0) sacc[j][1] = -CUDART_INF_F;
                    if (cc     > r1) sacc[j][2] = -CUDART_INF_F;
                    if (cc + 1 > r1) sacc[j][3] = -CUDART_INF_F;
                }
                tm0 = fmaxf(tm0, fmaxf(sacc[j][0], sacc[j][1]));
                tm1 = fmaxf(tm1, fmaxf(sacc[j][2], sacc[j][3]));
            }
            tm0 = fmaxf(tm0, __shfl_xor_sync(0xffffffffu, tm0, 1));
            tm0 = fmaxf(tm0, __shfl_xor_sync(0xffffffffu, tm0, 2));
            tm1 = fmaxf(tm1, __shfl_xor_sync(0xffffffffu, tm1, 1));
            tm1 = fmaxf(tm1, __shfl_xor_sync(0xffffffffu, tm1, 2));
            float mn0 = fmaxf(m0, tm0), mn1 = fmaxf(m1, tm1);
            float a0 = __expf(m0 - mn0), a1 = __expf(m1 - mn1);
            float rs0 = 0.f, rs1 = 0.f;
            #pragma unroll
            for (int j = 0; j < 8; j++) {
                float p0 = __expf(sacc[j][0] - mn0);
                float p1 = __expf(sacc[j][1] - mn0);
                float p2 = __expf(sacc[j][2] - mn1);
                float p3 = __expf(sacc[j][3] - mn1);
                sacc[j][0] = p0; sacc[j][1] = p1; sacc[j][2] = p2; sacc[j][3] = p3;
                rs0 += p0 + p1; rs1 += p2 + p3;
            }
            rs0 += __shfl_xor_sync(0xffffffffu, rs0, 1);
            rs0 += __shfl_xor_sync(0xffffffffu, rs0, 2);
            rs1 += __shfl_xor_sync(0xffffffffu, rs1, 1);
            rs1 += __shfl_xor_sync(0xffffffffu, rs1, 2);
            l0 = l0 * a0 + rs0; l1 = l1 * a1 + rs1;
            m0 = mn0; m1 = mn1;
            #pragma unroll
            for (int j = 0; j < 16; j++) {
                oacc[j][0] *= a0; oacc[j][1] *= a0;
                oacc[j][2] *= a1; oacc[j][3] *= a1;
            }

            uint32_t pf[4][4];
            #pragma unroll
            for (int c = 0; c < 4; c++) {
                pf[c][0] = pack_f16(sacc[2*c][0],   sacc[2*c][1]);
                pf[c][1] = pack_f16(sacc[2*c][2],   sacc[2*c][3]);
                pf[c][2] = pack_f16(sacc[2*c+1][0], sacc[2*c+1][1]);
                pf[c][3] = pack_f16(sacc[2*c+1][2], sacc[2*c+1][3]);
            }

            // ---- O += P V ----
            #pragma unroll
            for (int c = 0; c < 4; c++) {
                #pragma unroll
                for (int dt = 0; dt < 8; dt++) {
                    uint32_t bv[4];
                    ldmx4t(bv[0], bv[1], bv[2], bv[3],
                           stB + vbase[c] + 2u * (uint32_t)(dt * 16));
                    mmah16(oacc[2*dt],   pf[c], bv);
                    mmah16(oacc[2*dt+1], pf[c], bv + 2);
                }
            }
        }
    }

    float inv0 = 1.0f / l0, inv1 = 1.0f / l1;
    size_t grow0 = (rowQ + wq + (lane >> 2)) * C_;
    size_t grow1 = grow0 + 8 * C_;
    #pragma unroll
    for (int j = 0; j < 16; j++) {
        int col = colH + j * 8 + ((lane & 3) << 1);
        *(uint32_t*)&of[grow0 + col] = pack_f16(oacc[j][0] * inv0, oacc[j][1] * inv0);
        *(uint32_t*)&of[grow1 + col] = pack_f16(oacc[j][2] * inv1, oacc[j][3] * inv1);
    }
}

// ---------------------------------------------------------------------------
extern "C" void kernel_launch(void* const* d_in, const int* in_sizes, int n_in,
                              void* d_out, int out_size)
{
    (void)in_sizes; (void)n_in; (void)out_size;
    const float* x  = (const float*)d_in[0];
    const float* cs = (const float*)d_in[1];
    const float* sn = (const float*)d_in[2];
    float* out = (float*)d_out;

    __half *xf, *qf, *kf, *vf, *of, *wf;
    cudaGetSymbolAddress((void**)&xf, g_xf);
    cudaGetSymbolAddress((void**)&qf, g_qf);
    cudaGetSymbolAddress((void**)&kf, g_kf);
    cudaGetSymbolAddress((void**)&vf, g_vf);
    cudaGetSymbolAddress((void**)&of, g_of);
    cudaGetSymbolAddress((void**)&wf, g_wf);

    cudaFuncSetAttribute(qkv_gemm, cudaFuncAttributeMaxDynamicSharedMemorySize, QKV_SMEM);
    cudaFuncSetAttribute(hgemm_o,  cudaFuncAttributeMaxDynamicSharedMemorySize, K_SMEM);
    cudaFuncSetAttribute(flash_f16, cudaFuncAttributeMaxDynamicSharedMemorySize, FLASH_SMEM);

    split_all<<<NTOT4 / (512 * 4), 512>>>((const float4*)x,
        (const float4*)d_in[3], (const float4*)d_in[4],
        (const float4*)d_in[5], (const float4*)d_in[6],
        (uint2*)xf, (uint2*)wf);

    qkv_gemm<<<dim3(48, 32), 256, QKV_SMEM>>>(xf, wf, cs, sn, qf, kf, vf);

    flash_f16<<<dim3(T_/128, B_*H_), 256, FLASH_SMEM>>>(qf, kf, vf, of);

    hgemm_o<<<dim3(16, 32), 256, K_SMEM>>>(of, wf + 3*(size_t)C_*C_, out, C_, C_);
}

// round 15
// speedup vs baseline: 2.3528x; 1.0260x over previous
#include <cuda_runtime.h>
#include <cuda_bf16.h>
#include <cuda_fp16.h>
#include <math_constants.h>
#include <cstdint>

#define B_ 2
#define T_ 2048
#define C_ 2048
#define H_ 16
#define D_ 128
#define M_ (B_*T_)   // 4096 rows

// ---------------- scratch (static device globals) ----------------
__device__ __half g_xf[(size_t)M_ * C_];
__device__ __half g_qf[(size_t)M_ * C_];
__device__ __half g_kf[(size_t)M_ * C_];
__device__ __half g_vf[(size_t)M_ * C_];
__device__ __half g_of[(size_t)M_ * C_];
__device__ __half g_wf[4][(size_t)C_ * C_];   // Wq, Wk, Wv, Wo fp16

union HU { __half2 h; uint32_t u; };

__device__ __forceinline__ uint32_t pack_f16(float x, float y) {
    HU u; u.h = __floats2half2_rn(x, y); return u.u;
}

// ---------------------------------------------------------------------------
// split kernel: x, W0..W3 -> fp16. 4 float4 per thread for MLP.
// ---------------------------------------------------------------------------
#define NX4 ((M_*C_)/4)
#define NW4 ((C_*C_)/4)
#define NTOT4 (NX4 + 4*NW4)

__global__ __launch_bounds__(512) void split_all(
    const float4* __restrict__ x,
    const float4* __restrict__ w0, const float4* __restrict__ w1,
    const float4* __restrict__ w2, const float4* __restrict__ w3,
    uint2* __restrict__ xf, uint2* __restrict__ wf)
{
    int base = (blockIdx.x * blockDim.x + threadIdx.x) * 4;
    float4 v[4];
    uint2* dsts[4];
    int offs[4];
    #pragma unroll
    for (int e = 0; e < 4; e++) {
        int i = base + e;
        const float4* src;
        uint2* dst;
        int off;
        if (i < NX4) { src = x; off = i; dst = xf; }
        else {
            int j = i - NX4;
            int w = j >> 20;             // NW4 = 2^20
            off = j & (NW4 - 1);
            src = (w == 0) ? w0 : (w == 1) ? w1 : (w == 2) ? w2 : w3;
            dst = wf + (size_t)w * NW4;
        }
        v[e] = src[off];
        dsts[e] = dst; offs[e] = off;
    }
    #pragma unroll
    for (int e = 0; e < 4; e++)
        dsts[e][offs[e]] = make_uint2(pack_f16(v[e].x, v[e].y), pack_f16(v[e].z, v[e].w));
}

// ---------------------------------------------------------------------------
// primitives
// ---------------------------------------------------------------------------
__device__ __forceinline__ void ldmx4(uint32_t &r0, uint32_t &r1, uint32_t &r2, uint32_t &r3, uint32_t addr) {
    asm volatile("ldmatrix.sync.aligned.m8n8.x4.shared.b16 {%0,%1,%2,%3}, [%4];"
                 : "=r"(r0), "=r"(r1), "=r"(r2), "=r"(r3) : "r"(addr));
}
__device__ __forceinline__ void ldmx4t(uint32_t &r0, uint32_t &r1, uint32_t &r2, uint32_t &r3, uint32_t addr) {
    asm volatile("ldmatrix.sync.aligned.m8n8.x4.trans.shared.b16 {%0,%1,%2,%3}, [%4];"
                 : "=r"(r0), "=r"(r1), "=r"(r2), "=r"(r3) : "r"(addr));
}
__device__ __forceinline__ void mmah16(float* d, const uint32_t* a, const uint32_t* b) {
    asm volatile("mma.sync.aligned.m16n8k16.row.col.f32.f16.f16.f32 "
                 "{%0,%1,%2,%3},{%4,%5,%6,%7},{%8,%9},{%0,%1,%2,%3};"
                 : "+f"(d[0]), "+f"(d[1]), "+f"(d[2]), "+f"(d[3])
                 : "r"(a[0]), "r"(a[1]), "r"(a[2]), "r"(a[3]), "r"(b[0]), "r"(b[1]));
}
__device__ __forceinline__ void cp16(uint32_t saddr, const void* g) {
    asm volatile("cp.async.cg.shared.global [%0], [%1], 16;" :: "r"(saddr), "l"(g));
}
__device__ __forceinline__ uint32_t swz128(uint32_t off) { return off ^ ((off >> 3) & 0x70); }

// ---------------------------------------------------------------------------
// fp16 GEMM geometry: 128x128 CTA tile, BK=64, 8 warps (32x64), 3 stages.
// ---------------------------------------------------------------------------
#define K_SUB 16384
#define K_STAGE (2*K_SUB)                // 32768 B
#define K_SMEM (3*K_STAGE)               // 98304 B
#define FTS 133
#define QKV_SMEM (K_SMEM)

#define HG_STAGE_BODY(st)                                                             \
    _Pragma("unroll")                                                                 \
    for (int kk = 0; kk < 64; kk += 16) {                                             \
        uint32_t a[2][4], b[8][2];                                                    \
        _Pragma("unroll")                                                             \
        for (int t = 0; t < 2; t++) {                                                 \
            uint32_t rb = (uint32_t)((warp_m * 32 + t * 16 + mlane) * 128 + (kk + aoff) * 2); \
            ldmx4(a[t][0], a[t][1], a[t][2], a[t][3], (st) + swz128(rb));             \
        }                                                                             \
        _Pragma("unroll")                                                             \
        for (int jt = 0; jt < 4; jt++) {                                              \
            uint32_t rb = (uint32_t)((warp_n * 64 + jt * 16 + nlane) * 128 + (kk + klBo) * 2); \
            ldmx4(b[2*jt][0], b[2*jt][1], b[2*jt+1][0], b[2*jt+1][1], (st) + K_SUB + swz128(rb)); \
        }                                                                             \
        _Pragma("unroll")                                                             \
        for (int t = 0; t < 2; t++)                                                   \
            _Pragma("unroll")                                                         \
            for (int j = 0; j < 8; j++) mmah16(acc[t][j], a[t], b[j]);                \
    }

// ---------------------------------------------------------------------------
// Fused QKV fp16 GEMM + (rmsnorm+RoPE | passthrough) epilogue.
// Q output is PRE-SCALED by 1/sqrt(D).
// ---------------------------------------------------------------------------
__global__ __launch_bounds__(256, 2) void qkv_gemm(
    const __half* __restrict__ xf, const __half* __restrict__ wf,
    const float* __restrict__ cs, const float* __restrict__ sn,
    __half* __restrict__ qf, __half* __restrict__ kf, __half* __restrict__ vf)
{
    extern __shared__ __align__(1024) char smg[];
    const int tid = threadIdx.x, lane = tid & 31, wid = tid >> 5;
    const int warp_m = wid & 3;
    const int warp_n = wid >> 2;
    const int bm = blockIdx.y;
    const int kind = blockIdx.x >> 4;
    const int lbn  = blockIdx.x & 15;
    const uint32_t sb = (uint32_t)__cvta_generic_to_shared(smg);

    const __half* Bf = wf + (size_t)kind * C_ * C_;

    float acc[2][8][4];
    #pragma unroll
    for (int i = 0; i < 2; i++)
        #pragma unroll
        for (int j = 0; j < 8; j++)
            #pragma unroll
            for (int e = 0; e < 4; e++) acc[i][j][e] = 0.f;

    auto issue = [&](int s, int k0) {
        const uint32_t st = sb + s * K_STAGE;
        #pragma unroll
        for (int it = 0; it < 8; it++) {
            int j   = tid + it * 256;
            int sub = j >> 10;
            int cid = j & 1023;
            int r   = cid >> 3;
            int ch  = cid & 7;
            int grow = (sub ? lbn : bm) * 128 + r;
            const __half* g = (sub ? Bf : xf) + (size_t)grow * C_ + k0 + ch * 8;
            cp16(st + sub * K_SUB + swz128((uint32_t)(r * 128 + ch * 16)), g);
        }
        asm volatile("cp.async.commit_group;");
    };

    const int NS = C_ / 64;   // 32
    issue(0, 0);
    issue(1, 64);

    const int mlane = lane & 15;
    const int aoff  = (lane >> 4) << 3;
    const int nlane = (lane & 7) + ((lane >> 4) << 3);
    const int klBo  = ((lane >> 3) & 1) << 3;

    for (int i = 0; i < NS; i++) {
        if (i == NS - 1) { asm volatile("cp.async.wait_group 0;"); }
        else             { asm volatile("cp.async.wait_group 1;"); }
        __syncthreads();
        if (i + 2 < NS) issue((i + 2) % 3, (i + 2) * 64);

        const uint32_t st = sb + (i % 3) * K_STAGE;
        HG_STAGE_BODY(st)
    }
    __syncthreads();

    if (kind == 2) {
        #pragma unroll
        for (int t = 0; t < 2; t++) {
            int row = bm * 128 + warp_m * 32 + t * 16 + (lane >> 2);
            #pragma unroll
            for (int j = 0; j < 8; j++) {
                int col = lbn * 128 + warp_n * 64 + j * 8 + ((lane & 3) << 1);
                *(uint32_t*)&vf[(size_t)row * C_ + col]       = pack_f16(acc[t][j][0], acc[t][j][1]);
                *(uint32_t*)&vf[(size_t)(row + 8) * C_ + col] = pack_f16(acc[t][j][2], acc[t][j][3]);
            }
        }
    } else {
        float* ft = (float*)smg;
        #pragma unroll
        for (int t = 0; t < 2; t++) {
            int rl0 = warp_m * 32 + t * 16 + (lane >> 2);
            #pragma unroll
            for (int j = 0; j < 8; j++) {
                int cl = warp_n * 64 + j * 8 + ((lane & 3) << 1);
                ft[rl0 * FTS + cl]           = acc[t][j][0];
                ft[rl0 * FTS + cl + 1]       = acc[t][j][1];
                ft[(rl0 + 8) * FTS + cl]     = acc[t][j][2];
                ft[(rl0 + 8) * FTS + cl + 1] = acc[t][j][3];
            }
        }
        __syncthreads();

        const int r  = tid >> 1;
        const int hh = tid & 1;
        const int cb = hh * 32;
        const float* fr = ft + r * FTS;

        float ss = 0.f;
        #pragma unroll
        for (int i2 = 0; i2 < 32; i2++) {
            float a = fr[cb + i2];
            float b = fr[cb + 64 + i2];
            ss += a * a + b * b;
        }
        ss += __shfl_xor_sync(0xffffffffu, ss, 1);
        float rms = rsqrtf(ss * (1.0f / 128.0f) + 1.1920929e-7f);
        if (kind == 0) rms *= 0.088388347648318447f;   // fold 1/sqrt(D) into Q

        const int grow = bm * 128 + r;
        const int t    = grow & (T_ - 1);
        __half* Of = kind ? kf : qf;
        const size_t rb = (size_t)grow * C_ + lbn * 128;

        #pragma unroll
        for (int i2 = 0; i2 < 32; i2 += 2) {
            int c0 = cb + i2;
            float a0 = fr[c0] * rms,     b0 = fr[c0 + 64] * rms;
            float a1 = fr[c0 + 1] * rms, b1 = fr[c0 + 65] * rms;
            float co0 = cs[t * 64 + c0], si0 = sn[t * 64 + c0];
            float co1 = cs[t * 64 + c0 + 1], si1 = sn[t * 64 + c0 + 1];
            float y10 =  a0 * co0 + b0 * si0;
            float y11 =  a1 * co1 + b1 * si1;
            float y20 = -a0 * si0 + b0 * co0;
            float y21 = -a1 * si1 + b1 * co1;
            *(uint32_t*)&Of[rb + c0]      = pack_f16(y10, y11);
            *(uint32_t*)&Of[rb + c0 + 64] = pack_f16(y20, y21);
        }
    }
}

// ---------------------------------------------------------------------------
// O-projection fp16 GEMM (fp32 out). grid (16, 32).
// ---------------------------------------------------------------------------
__global__ __launch_bounds__(256, 2) void hgemm_o(
    const __half* __restrict__ Af, const __half* __restrict__ Bf,
    float* __restrict__ Cc, int Nn, int K)
{
    extern __shared__ __align__(1024) char smg[];
    const int tid = threadIdx.x, lane = tid & 31, wid = tid >> 5;
    const int warp_m = wid & 3;
    const int warp_n = wid >> 2;
    const int bm = blockIdx.y, bn = blockIdx.x;
    const uint32_t sb = (uint32_t)__cvta_generic_to_shared(smg);

    float acc[2][8][4];
    #pragma unroll
    for (int i = 0; i < 2; i++)
        #pragma unroll
        for (int j = 0; j < 8; j++)
            #pragma unroll
            for (int e = 0; e < 4; e++) acc[i][j][e] = 0.f;

    auto issue = [&](int s, int k0) {
        const uint32_t st = sb + s * K_STAGE;
        #pragma unroll
        for (int it = 0; it < 8; it++) {
            int j   = tid + it * 256;
            int sub = j >> 10;
            int cid = j & 1023;
            int r   = cid >> 3;
            int ch  = cid & 7;
            int grow = (sub ? bn : bm) * 128 + r;
            const __half* g = (sub ? Bf : Af) + (size_t)grow * K + k0 + ch * 8;
            cp16(st + sub * K_SUB + swz128((uint32_t)(r * 128 + ch * 16)), g);
        }
        asm volatile("cp.async.commit_group;");
    };

    const int NS = K / 64;
    issue(0, 0);
    issue(1, 64);

    const int mlane = lane & 15;
    const int aoff  = (lane >> 4) << 3;
    const int nlane = (lane & 7) + ((lane >> 4) << 3);
    const int klBo  = ((lane >> 3) & 1) << 3;

    for (int i = 0; i < NS; i++) {
        if (i == NS - 1) { asm volatile("cp.async.wait_group 0;"); }
        else             { asm volatile("cp.async.wait_group 1;"); }
        __syncthreads();
        if (i + 2 < NS) issue((i + 2) % 3, (i + 2) * 64);

        const uint32_t st = sb + (i % 3) * K_STAGE;
        HG_STAGE_BODY(st)
    }

    #pragma unroll
    for (int t = 0; t < 2; t++) {
        int row = bm * 128 + warp_m * 32 + t * 16 + (lane >> 2);
        #pragma unroll
        for (int j = 0; j < 8; j++) {
            int col = bn * 128 + warp_n * 64 + j * 8 + ((lane & 3) << 1);
            *(float2*)&Cc[(size_t)row * Nn + col]       = make_float2(acc[t][j][0], acc[t][j][1]);
            *(float2*)&Cc[(size_t)(row + 8) * Nn + col] = make_float2(acc[t][j][2], acc[t][j][3]);
        }
    }
}

// ---------------------------------------------------------------------------
// Tensor-core flash attention (causal), fp16 mma, fp32 softmax/accum.
// 64-row q tiles, 128 threads (4 warps x 16 rows), 2 CTAs/SM.
// Q pre-scaled by 1/sqrt(D). KV 3-stage pipeline, PREFETCH DISTANCE 2.
// ---------------------------------------------------------------------------
#define SQ 136
#define FL_STAGE (2*64*SQ)               // elems per stage (KF, VF)
#define FL_KF 0
#define FL_VF (64*SQ)
#define FLASH_SMEM (3*FL_STAGE*2)        // 104448 bytes -> 2 CTAs/SM

__global__ __launch_bounds__(128, 2) void flash_f16(
    const __half* __restrict__ qf, const __half* __restrict__ kf,
    const __half* __restrict__ vf, __half* __restrict__ of)
{
    extern __shared__ __half smf[];
    const int tid = threadIdx.x, lane = tid & 31, wid = tid >> 5;   // 4 warps
    const int qb = gridDim.x - 1 - blockIdx.x;   // heavy first
    const int b  = blockIdx.y >> 4, h = blockIdx.y & 15;
    const uint32_t sb = (uint32_t)__cvta_generic_to_shared(smf);
    const size_t rowQ = (size_t)b * T_ + (size_t)qb * 64;
    const int colH = h * D_;

    const int wq = wid * 16;
    const int gq0 = qb * 64 + wq;
    const int mlane = lane & 15;
    const int aoff  = (lane >> 4) << 3;
    const int nlane = (lane & 7) + ((lane >> 4) << 3);
    const int klB   = ((lane >> 3) & 1) << 3;

    // ---- stage Q (64 rows), extract fragments ----
    #pragma unroll
    for (int it = 0; it < 8; it++) {
        int idx = tid + it * 128;
        int r = idx >> 4, c = (idx & 15) << 3;
        cp16(sb + 2u * (uint32_t)(r * SQ + c), qf + (rowQ + r) * C_ + colH + c);
    }
    asm volatile("cp.async.commit_group;");
    asm volatile("cp.async.wait_group 0;");
    __syncthreads();

    uint32_t qr[8][4];
    #pragma unroll
    for (int c = 0; c < 8; c++) {
        uint32_t ad = sb + 2u * (uint32_t)((wq + mlane) * SQ + c * 16 + aoff);
        ldmx4(qr[c][0], qr[c][1], qr[c][2], qr[c][3], ad);
    }
    __syncthreads();

    // hoisted per-warp fragment base offsets (bytes, stage-relative)
    uint32_t kbase[4], vbase[4];
    {
        const int vrow = ((lane >> 3) & 1) * 8 + (lane & 7);
        const int vcol = (lane >> 4) << 3;
        #pragma unroll
        for (int jt = 0; jt < 4; jt++)
            kbase[jt] = 2u * (uint32_t)(FL_KF + (jt * 16 + nlane) * SQ + klB);
        #pragma unroll
        for (int c = 0; c < 4; c++)
            vbase[c] = 2u * (uint32_t)(FL_VF + (c * 16 + vrow) * SQ + vcol);
    }

    auto issueKV = [&](int s, int kt) {
        uint32_t st = s * FL_STAGE;
        #pragma unroll
        for (int it = 0; it < 16; it++) {
            int idx = tid + it * 128;
            int sub = idx >> 10;           // 0=K, 1=V
            int cid = idx & 1023;
            int r = cid >> 4, c = (cid & 15) << 3;
            size_t g = ((size_t)b * T_ + (size_t)kt * 64 + r) * C_ + colH + c;
            cp16(sb + 2u * (uint32_t)(st + (sub ? FL_VF : FL_KF) + r * SQ + c),
                 (sub ? vf : kf) + g);
        }
        asm volatile("cp.async.commit_group;");
    };

    const int nkt = qb + 1;   // exact causal coverage
    issueKV(0, 0);
    if (nkt > 1) issueKV(1, 1);

    float m0 = -CUDART_INF_F, m1 = -CUDART_INF_F, l0 = 0.f, l1 = 0.f;
    float oacc[16][4];
    #pragma unroll
    for (int j = 0; j < 16; j++)
        #pragma unroll
        for (int e = 0; e < 4; e++) oacc[j][e] = 0.f;

    for (int kt = 0; kt < nkt; kt++) {
        if (kt + 2 < nkt) { asm volatile("cp.async.wait_group 1;"); }
        else              { asm volatile("cp.async.wait_group 0;"); }
        __syncthreads();
        if (kt + 2 < nkt) issueKV((kt + 2) % 3, kt + 2);

        const int kb = kt * 64;
        const uint32_t stB = sb + 2u * (uint32_t)((kt % 3) * FL_STAGE);

        // ---- S = Q K^T (Q pre-scaled) ----
        float sacc[8][4];
        #pragma unroll
        for (int j = 0; j < 8; j++)
            #pragma unroll
            for (int e = 0; e < 4; e++) sacc[j][e] = 0.f;

        #pragma unroll
        for (int c = 0; c < 8; c++) {
            uint32_t bkv[8][2];
            #pragma unroll
            for (int jt = 0; jt < 4; jt++) {
                ldmx4(bkv[2*jt][0], bkv[2*jt][1], bkv[2*jt+1][0], bkv[2*jt+1][1],
                      stB + kbase[jt] + 2u * (uint32_t)(c * 16));
            }
            #pragma unroll
            for (int j = 0; j < 8; j++) mmah16(sacc[j], qr[c], bkv[j]);
        }

        // ---- mask + online softmax ----
        const bool diag = (kb + 63 > gq0);
        const int r0 = gq0 + (lane >> 2), r1 = r0 + 8;
        float tm0 = -CUDART_INF_F, tm1 = -CUDART_INF_F;
        #pragma unroll
        for (int j = 0; j < 8; j++) {
            if (diag) {
                int cc = kb + j * 8 + ((lane & 3) << 1);
                if (cc     > r0) sacc[j][0] = -CUDART_INF_F;
                if (cc + 1 > r0) sacc[j][1] = -CUDART_INF_F;
                if (cc     > r1) sacc[j][2] = -CUDART_INF_F;
                if (cc + 1 > r1) sacc[j][3] = -CUDART_INF_F;
            }
            tm0 = fmaxf(tm0, fmaxf(sacc[j][0], sacc[j][1]));
            tm1 = fmaxf(tm1, fmaxf(sacc[j][2], sacc[j][3]));
        }
        tm0 = fmaxf(tm0, __shfl_xor_sync(0xffffffffu, tm0, 1));
        tm0 = fmaxf(tm0, __shfl_xor_sync(0xffffffffu, tm0, 2));
        tm1 = fmaxf(tm1, __shfl_xor_sync(0xffffffffu, tm1, 1));
        tm1 = fmaxf(tm1, __shfl_xor_sync(0xffffffffu, tm1, 2));
        float mn0 = fmaxf(m0, tm0), mn1 = fmaxf(m1, tm1);
        float a0 = __expf(m0 - mn0), a1 = __expf(m1 - mn1);
        float rs0 = 0.f, rs1 = 0.f;
        #pragma unroll
        for (int j = 0; j < 8; j++) {
            float p0 = __expf(sacc[j][0] - mn0);
            float p1 = __expf(sacc[j][1] - mn0);
            float p2 = __expf(sacc[j][2] - mn1);
            float p3 = __expf(sacc[j][3] - mn1);
            sacc[j][0] = p0; sacc[j][1] = p1; sacc[j][2] = p2; sacc[j][3] = p3;
            rs0 += p0 + p1; rs1 += p2 + p3;
        }
        rs0 += __shfl_xor_sync(0xffffffffu, rs0, 1);
        rs0 += __shfl_xor_sync(0xffffffffu, rs0, 2);
        rs1 += __shfl_xor_sync(0xffffffffu, rs1, 1);
        rs1 += __shfl_xor_sync(0xffffffffu, rs1, 2);
        l0 = l0 * a0 + rs0; l1 = l1 * a1 + rs1;
        m0 = mn0; m1 = mn1;
        #pragma unroll
        for (int j = 0; j < 16; j++) {
            oacc[j][0] *= a0; oacc[j][1] *= a0;
            oacc[j][2] *= a1; oacc[j][3] *= a1;
        }

        uint32_t pf[4][4];
        #pragma unroll
        for (int c = 0; c < 4; c++) {
            pf[c][0] = pack_f16(sacc[2*c][0],   sacc[2*c][1]);
            pf[c][1] = pack_f16(sacc[2*c][2],   sacc[2*c][3]);
            pf[c][2] = pack_f16(sacc[2*c+1][0], sacc[2*c+1][1]);
            pf[c][3] = pack_f16(sacc[2*c+1][2], sacc[2*c+1][3]);
        }

        // ---- O += P V ----
        #pragma unroll
        for (int c = 0; c < 4; c++) {
            #pragma unroll
            for (int dt = 0; dt < 8; dt++) {
                uint32_t bv[4];
                ldmx4t(bv[0], bv[1], bv[2], bv[3],
                       stB + vbase[c] + 2u * (uint32_t)(dt * 16));
                mmah16(oacc[2*dt],   pf[c], bv);
                mmah16(oacc[2*dt+1], pf[c], bv + 2);
            }
        }
    }

    float inv0 = 1.0f / l0, inv1 = 1.0f / l1;
    size_t grow0 = (rowQ + wq + (lane >> 2)) * C_;
    size_t grow1 = grow0 + 8 * C_;
    #pragma unroll
    for (int j = 0; j < 16; j++) {
        int col = colH + j * 8 + ((lane & 3) << 1);
        *(uint32_t*)&of[grow0 + col] = pack_f16(oacc[j][0] * inv0, oacc[j][1] * inv0);
        *(uint32_t*)&of[grow1 + col] = pack_f16(oacc[j][2] * inv1, oacc[j][3] * inv1);
    }
}

// ---------------------------------------------------------------------------
extern "C" void kernel_launch(void* const* d_in, const int* in_sizes, int n_in,
                              void* d_out, int out_size)
{
    (void)in_sizes; (void)n_in; (void)out_size;
    const float* x  = (const float*)d_in[0];
    const float* cs = (const float*)d_in[1];
    const float* sn = (const float*)d_in[2];
    float* out = (float*)d_out;

    __half *xf, *qf, *kf, *vf, *of, *wf;
    cudaGetSymbolAddress((void**)&xf, g_xf);
    cudaGetSymbolAddress((void**)&qf, g_qf);
    cudaGetSymbolAddress((void**)&kf, g_kf);
    cudaGetSymbolAddress((void**)&vf, g_vf);
    cudaGetSymbolAddress((void**)&of, g_of);
    cudaGetSymbolAddress((void**)&wf, g_wf);

    cudaFuncSetAttribute(qkv_gemm, cudaFuncAttributeMaxDynamicSharedMemorySize, QKV_SMEM);
    cudaFuncSetAttribute(hgemm_o,  cudaFuncAttributeMaxDynamicSharedMemorySize, K_SMEM);
    cudaFuncSetAttribute(flash_f16, cudaFuncAttributeMaxDynamicSharedMemorySize, FLASH_SMEM);

    split_all<<<NTOT4 / (512 * 4), 512>>>((const float4*)x,
        (const float4*)d_in[3], (const float4*)d_in[4],
        (const float4*)d_in[5], (const float4*)d_in[6],
        (uint2*)xf, (uint2*)wf);

    qkv_gemm<<<dim3(48, 32), 256, QKV_SMEM>>>(xf, wf, cs, sn, qf, kf, vf);

    flash_f16<<<dim3(T_/64, B_*H_), 128, FLASH_SMEM>>>(qf, kf, vf, of);

    hgemm_o<<<dim3(16, 32), 256, K_SMEM>>>(of, wf + 3*(size_t)C_*C_, out, C_, C_);
}

// round 16
// speedup vs baseline: 2.5513x; 1.0844x over previous
#include <cuda_runtime.h>
#include <cuda_bf16.h>
#include <cuda_fp16.h>
#include <math_constants.h>
#include <cstdint>

#define B_ 2
#define T_ 2048
#define C_ 2048
#define H_ 16
#define D_ 128
#define M_ (B_*T_)   // 4096 rows

// ---------------- scratch (static device globals) ----------------
__device__ __half g_xf[(size_t)M_ * C_];
__device__ __half g_qf[(size_t)M_ * C_];
__device__ __half g_kf[(size_t)M_ * C_];
__device__ __half g_vf[(size_t)M_ * C_];
__device__ __half g_of[(size_t)M_ * C_];
__device__ __half g_wf[4][(size_t)C_ * C_];   // Wq, Wk, Wv, Wo fp16

union HU { __half2 h; uint32_t u; };

__device__ __forceinline__ uint32_t pack_f16(float x, float y) {
    HU u; u.h = __floats2half2_rn(x, y); return u.u;
}

// ---------------------------------------------------------------------------
// split kernel: x, W0..W3 -> fp16. 4 float4 per thread for MLP.
// ---------------------------------------------------------------------------
#define NX4 ((M_*C_)/4)
#define NW4 ((C_*C_)/4)
#define NTOT4 (NX4 + 4*NW4)

__global__ __launch_bounds__(512) void split_all(
    const float4* __restrict__ x,
    const float4* __restrict__ w0, const float4* __restrict__ w1,
    const float4* __restrict__ w2, const float4* __restrict__ w3,
    uint2* __restrict__ xf, uint2* __restrict__ wf)
{
    int base = (blockIdx.x * blockDim.x + threadIdx.x) * 4;
    float4 v[4];
    uint2* dsts[4];
    int offs[4];
    #pragma unroll
    for (int e = 0; e < 4; e++) {
        int i = base + e;
        const float4* src;
        uint2* dst;
        int off;
        if (i < NX4) { src = x; off = i; dst = xf; }
        else {
            int j = i - NX4;
            int w = j >> 20;             // NW4 = 2^20
            off = j & (NW4 - 1);
            src = (w == 0) ? w0 : (w == 1) ? w1 : (w == 2) ? w2 : w3;
            dst = wf + (size_t)w * NW4;
        }
        v[e] = src[off];
        dsts[e] = dst; offs[e] = off;
    }
    #pragma unroll
    for (int e = 0; e < 4; e++)
        dsts[e][offs[e]] = make_uint2(pack_f16(v[e].x, v[e].y), pack_f16(v[e].z, v[e].w));
}

// ---------------------------------------------------------------------------
// primitives
// ---------------------------------------------------------------------------
__device__ __forceinline__ void ldmx4(uint32_t &r0, uint32_t &r1, uint32_t &r2, uint32_t &r3, uint32_t addr) {
    asm volatile("ldmatrix.sync.aligned.m8n8.x4.shared.b16 {%0,%1,%2,%3}, [%4];"
                 : "=r"(r0), "=r"(r1), "=r"(r2), "=r"(r3) : "r"(addr));
}
__device__ __forceinline__ void ldmx4t(uint32_t &r0, uint32_t &r1, uint32_t &r2, uint32_t &r3, uint32_t addr) {
    asm volatile("ldmatrix.sync.aligned.m8n8.x4.trans.shared.b16 {%0,%1,%2,%3}, [%4];"
                 : "=r"(r0), "=r"(r1), "=r"(r2), "=r"(r3) : "r"(addr));
}
__device__ __forceinline__ void mmah16(float* d, const uint32_t* a, const uint32_t* b) {
    asm volatile("mma.sync.aligned.m16n8k16.row.col.f32.f16.f16.f32 "
                 "{%0,%1,%2,%3},{%4,%5,%6,%7},{%8,%9},{%0,%1,%2,%3};"
                 : "+f"(d[0]), "+f"(d[1]), "+f"(d[2]), "+f"(d[3])
                 : "r"(a[0]), "r"(a[1]), "r"(a[2]), "r"(a[3]), "r"(b[0]), "r"(b[1]));
}
__device__ __forceinline__ void cp16(uint32_t saddr, const void* g) {
    asm volatile("cp.async.cg.shared.global [%0], [%1], 16;" :: "r"(saddr), "l"(g));
}
__device__ __forceinline__ uint32_t swz128(uint32_t off) { return off ^ ((off >> 3) & 0x70); }

// ---------------------------------------------------------------------------
// fp16 GEMM geometry: 64x128 CTA tile, BK=64, 8 warps (32x32 warp tiles),
// 3 stages, 3 CTAs/SM (24 warps).
// Stage: A 64x128B (8KB) + B 128x128B (16KB) = 24KB.
// ---------------------------------------------------------------------------
#define G_ASUB 8192
#define G_STAGE 24576
#define G_SMEM (3*G_STAGE)               // 73728 B
#define FTS 133                          // 64*133*4 = 34048 < G_SMEM

// One BK=64 compute block: 4 kk-steps, 16 ldsm, 32 mma per warp.
#define HG2_STAGE_BODY(st)                                                            \
    _Pragma("unroll")                                                                 \
    for (int kk = 0; kk < 64; kk += 16) {                                             \
        uint32_t a[2][4], b[4][2];                                                    \
        _Pragma("unroll")                                                             \
        for (int t = 0; t < 2; t++) {                                                 \
            uint32_t rb = (uint32_t)((warp_m * 32 + t * 16 + mlane) * 128 + (kk + aoff) * 2); \
            ldmx4(a[t][0], a[t][1], a[t][2], a[t][3], (st) + swz128(rb));             \
        }                                                                             \
        _Pragma("unroll")                                                             \
        for (int jt = 0; jt < 2; jt++) {                                              \
            uint32_t rb = (uint32_t)((warp_n * 32 + jt * 16 + nlane) * 128 + (kk + klBo) * 2); \
            ldmx4(b[2*jt][0], b[2*jt][1], b[2*jt+1][0], b[2*jt+1][1], (st) + G_ASUB + swz128(rb)); \
        }                                                                             \
        _Pragma("unroll")                                                             \
        for (int t = 0; t < 2; t++)                                                   \
            _Pragma("unroll")                                                         \
            for (int j = 0; j < 4; j++) mmah16(acc[t][j], a[t], b[j]);                \
    }

// ---------------------------------------------------------------------------
// Fused QKV fp16 GEMM + (rmsnorm+RoPE | passthrough) epilogue.
// grid (48, 64): bx>>4 = kind (0=q 1=k 2=v), bx&15 = head; by = 64-row block.
// Q output PRE-SCALED by 1/sqrt(D).
// ---------------------------------------------------------------------------
__global__ __launch_bounds__(256, 3) void qkv_gemm(
    const __half* __restrict__ xf, const __half* __restrict__ wf,
    const float* __restrict__ cs, const float* __restrict__ sn,
    __half* __restrict__ qf, __half* __restrict__ kf, __half* __restrict__ vf)
{
    extern __shared__ __align__(1024) char smg[];
    const int tid = threadIdx.x, lane = tid & 31, wid = tid >> 5;
    const int warp_m = wid & 1;          // 2 -> 32 rows each
    const int warp_n = wid >> 1;         // 4 -> 32 cols each
    const int bm = blockIdx.y;
    const int kind = blockIdx.x >> 4;
    const int lbn  = blockIdx.x & 15;
    const uint32_t sb = (uint32_t)__cvta_generic_to_shared(smg);

    const __half* Bf = wf + (size_t)kind * C_ * C_;

    float acc[2][4][4];
    #pragma unroll
    for (int i = 0; i < 2; i++)
        #pragma unroll
        for (int j = 0; j < 4; j++)
            #pragma unroll
            for (int e = 0; e < 4; e++) acc[i][j][e] = 0.f;

    auto issue = [&](int s, int k0) {
        const uint32_t st = sb + s * G_STAGE;
        #pragma unroll
        for (int it = 0; it < 6; it++) {
            int idx = tid + it * 256;         // 0..1535
            if (idx < 512) {                  // A: 64 rows x 8 chunks
                int r = idx >> 3, ch = idx & 7;
                cp16(st + swz128((uint32_t)(r * 128 + ch * 16)),
                     xf + (size_t)(bm * 64 + r) * C_ + k0 + ch * 8);
            } else {                          // B: 128 rows x 8 chunks
                int j = idx - 512;
                int r = j >> 3, ch = j & 7;
                cp16(st + G_ASUB + swz128((uint32_t)(r * 128 + ch * 16)),
                     Bf + (size_t)(lbn * 128 + r) * C_ + k0 + ch * 8);
            }
        }
        asm volatile("cp.async.commit_group;");
    };

    const int NS = C_ / 64;   // 32
    issue(0, 0);
    issue(1, 64);

    const int mlane = lane & 15;
    const int aoff  = (lane >> 4) << 3;
    const int nlane = (lane & 7) + ((lane >> 4) << 3);
    const int klBo  = ((lane >> 3) & 1) << 3;

    for (int i = 0; i < NS; i++) {
        if (i == NS - 1) { asm volatile("cp.async.wait_group 0;"); }
        else             { asm volatile("cp.async.wait_group 1;"); }
        __syncthreads();
        if (i + 2 < NS) issue((i + 2) % 3, (i + 2) * 64);

        const uint32_t st = sb + (i % 3) * G_STAGE;
        HG2_STAGE_BODY(st)
    }
    __syncthreads();

    if (kind == 2) {
        // V: passthrough fp16
        #pragma unroll
        for (int t = 0; t < 2; t++) {
            int row = bm * 64 + warp_m * 32 + t * 16 + (lane >> 2);
            #pragma unroll
            for (int j = 0; j < 4; j++) {
                int col = lbn * 128 + warp_n * 32 + j * 8 + ((lane & 3) << 1);
                *(uint32_t*)&vf[(size_t)row * C_ + col]       = pack_f16(acc[t][j][0], acc[t][j][1]);
                *(uint32_t*)&vf[(size_t)(row + 8) * C_ + col] = pack_f16(acc[t][j][2], acc[t][j][3]);
            }
        }
    } else {
        // Q/K: rmsnorm + rope epilogue via fp32 smem staging (64 rows)
        float* ft = (float*)smg;
        #pragma unroll
        for (int t = 0; t < 2; t++) {
            int rl0 = warp_m * 32 + t * 16 + (lane >> 2);
            #pragma unroll
            for (int j = 0; j < 4; j++) {
                int cl = warp_n * 32 + j * 8 + ((lane & 3) << 1);
                ft[rl0 * FTS + cl]           = acc[t][j][0];
                ft[rl0 * FTS + cl + 1]       = acc[t][j][1];
                ft[(rl0 + 8) * FTS + cl]     = acc[t][j][2];
                ft[(rl0 + 8) * FTS + cl + 1] = acc[t][j][3];
            }
        }
        __syncthreads();

        const int r  = tid >> 2;           // 0..63
        const int hh = tid & 3;
        const int cb = hh * 16;            // 0,16,32,48
        const float* fr = ft + r * FTS;

        float ss = 0.f;
        #pragma unroll
        for (int i2 = 0; i2 < 16; i2++) {
            float a = fr[cb + i2];
            float b = fr[cb + 64 + i2];
            ss += a * a + b * b;
        }
        ss += __shfl_xor_sync(0xffffffffu, ss, 1);
        ss += __shfl_xor_sync(0xffffffffu, ss, 2);
        float rms = rsqrtf(ss * (1.0f / 128.0f) + 1.1920929e-7f);
        if (kind == 0) rms *= 0.088388347648318447f;   // fold 1/sqrt(D) into Q

        const int grow = bm * 64 + r;
        const int t    = grow & (T_ - 1);
        __half* Of = kind ? kf : qf;
        const size_t rb = (size_t)grow * C_ + lbn * 128;

        #pragma unroll
        for (int i2 = 0; i2 < 16; i2 += 2) {
            int c0 = cb + i2;
            float a0 = fr[c0] * rms,     b0 = fr[c0 + 64] * rms;
            float a1 = fr[c0 + 1] * rms, b1 = fr[c0 + 65] * rms;
            float co0 = cs[t * 64 + c0], si0 = sn[t * 64 + c0];
            float co1 = cs[t * 64 + c0 + 1], si1 = sn[t * 64 + c0 + 1];
            float y10 =  a0 * co0 + b0 * si0;
            float y11 =  a1 * co1 + b1 * si1;
            float y20 = -a0 * si0 + b0 * co0;
            float y21 = -a1 * si1 + b1 * co1;
            *(uint32_t*)&Of[rb + c0]      = pack_f16(y10, y11);
            *(uint32_t*)&Of[rb + c0 + 64] = pack_f16(y20, y21);
        }
    }
}

// ---------------------------------------------------------------------------
// O-projection fp16 GEMM (fp32 out). 64x128 tile, grid (16, 64).
// ---------------------------------------------------------------------------
__global__ __launch_bounds__(256, 3) void hgemm_o(
    const __half* __restrict__ Af, const __half* __restrict__ Bf,
    float* __restrict__ Cc, int Nn, int K)
{
    extern __shared__ __align__(1024) char smg[];
    const int tid = threadIdx.x, lane = tid & 31, wid = tid >> 5;
    const int warp_m = wid & 1;
    const int warp_n = wid >> 1;
    const int bm = blockIdx.y, bn = blockIdx.x;
    const uint32_t sb = (uint32_t)__cvta_generic_to_shared(smg);

    float acc[2][4][4];
    #pragma unroll
    for (int i = 0; i < 2; i++)
        #pragma unroll
        for (int j = 0; j < 4; j++)
            #pragma unroll
            for (int e = 0; e < 4; e++) acc[i][j][e] = 0.f;

    auto issue = [&](int s, int k0) {
        const uint32_t st = sb + s * G_STAGE;
        #pragma unroll
        for (int it = 0; it < 6; it++) {
            int idx = tid + it * 256;
            if (idx < 512) {
                int r = idx >> 3, ch = idx & 7;
                cp16(st + swz128((uint32_t)(r * 128 + ch * 16)),
                     Af + (size_t)(bm * 64 + r) * K + k0 + ch * 8);
            } else {
                int j = idx - 512;
                int r = j >> 3, ch = j & 7;
                cp16(st + G_ASUB + swz128((uint32_t)(r * 128 + ch * 16)),
                     Bf + (size_t)(bn * 128 + r) * K + k0 + ch * 8);
            }
        }
        asm volatile("cp.async.commit_group;");
    };

    const int NS = K / 64;   // 32
    issue(0, 0);
    issue(1, 64);

    const int mlane = lane & 15;
    const int aoff  = (lane >> 4) << 3;
    const int nlane = (lane & 7) + ((lane >> 4) << 3);
    const int klBo  = ((lane >> 3) & 1) << 3;

    for (int i = 0; i < NS; i++) {
        if (i == NS - 1) { asm volatile("cp.async.wait_group 0;"); }
        else             { asm volatile("cp.async.wait_group 1;"); }
        __syncthreads();
        if (i + 2 < NS) issue((i + 2) % 3, (i + 2) * 64);

        const uint32_t st = sb + (i % 3) * G_STAGE;
        HG2_STAGE_BODY(st)
    }

    #pragma unroll
    for (int t = 0; t < 2; t++) {
        int row = bm * 64 + warp_m * 32 + t * 16 + (lane >> 2);
        #pragma unroll
        for (int j = 0; j < 4; j++) {
            int col = bn * 128 + warp_n * 32 + j * 8 + ((lane & 3) << 1);
            *(float2*)&Cc[(size_t)row * Nn + col]       = make_float2(acc[t][j][0], acc[t][j][1]);
            *(float2*)&Cc[(size_t)(row + 8) * Nn + col] = make_float2(acc[t][j][2], acc[t][j][3]);
        }
    }
}

// ---------------------------------------------------------------------------
// Tensor-core flash attention (causal), fp16 mma, fp32 softmax/accum.
// 64-row q tiles, 128 threads (4 warps x 16 rows), 2 CTAs/SM.
// Q pre-scaled by 1/sqrt(D). KV 3-stage pipeline, prefetch distance 2.
// ---------------------------------------------------------------------------
#define SQ 136
#define FL_STAGE (2*64*SQ)
#define FL_KF 0
#define FL_VF (64*SQ)
#define FLASH_SMEM (3*FL_STAGE*2)        // 104448 bytes -> 2 CTAs/SM

__global__ __launch_bounds__(128, 2) void flash_f16(
    const __half* __restrict__ qf, const __half* __restrict__ kf,
    const __half* __restrict__ vf, __half* __restrict__ of)
{
    extern __shared__ __half smf[];
    const int tid = threadIdx.x, lane = tid & 31, wid = tid >> 5;
    const int qb = gridDim.x - 1 - blockIdx.x;
    const int b  = blockIdx.y >> 4, h = blockIdx.y & 15;
    const uint32_t sb = (uint32_t)__cvta_generic_to_shared(smf);
    const size_t rowQ = (size_t)b * T_ + (size_t)qb * 64;
    const int colH = h * D_;

    const int wq = wid * 16;
    const int gq0 = qb * 64 + wq;
    const int mlane = lane & 15;
    const int aoff  = (lane >> 4) << 3;
    const int nlane = (lane & 7) + ((lane >> 4) << 3);
    const int klB   = ((lane >> 3) & 1) << 3;

    #pragma unroll
    for (int it = 0; it < 8; it++) {
        int idx = tid + it * 128;
        int r = idx >> 4, c = (idx & 15) << 3;
        cp16(sb + 2u * (uint32_t)(r * SQ + c), qf + (rowQ + r) * C_ + colH + c);
    }
    asm volatile("cp.async.commit_group;");
    asm volatile("cp.async.wait_group 0;");
    __syncthreads();

    uint32_t qr[8][4];
    #pragma unroll
    for (int c = 0; c < 8; c++) {
        uint32_t ad = sb + 2u * (uint32_t)((wq + mlane) * SQ + c * 16 + aoff);
        ldmx4(qr[c][0], qr[c][1], qr[c][2], qr[c][3], ad);
    }
    __syncthreads();

    uint32_t kbase[4], vbase[4];
    {
        const int vrow = ((lane >> 3) & 1) * 8 + (lane & 7);
        const int vcol = (lane >> 4) << 3;
        #pragma unroll
        for (int jt = 0; jt < 4; jt++)
            kbase[jt] = 2u * (uint32_t)(FL_KF + (jt * 16 + nlane) * SQ + klB);
        #pragma unroll
        for (int c = 0; c < 4; c++)
            vbase[c] = 2u * (uint32_t)(FL_VF + (c * 16 + vrow) * SQ + vcol);
    }

    auto issueKV = [&](int s, int kt) {
        uint32_t st = s * FL_STAGE;
        #pragma unroll
        for (int it = 0; it < 16; it++) {
            int idx = tid + it * 128;
            int sub = idx >> 10;
            int cid = idx & 1023;
            int r = cid >> 4, c = (cid & 15) << 3;
            size_t g = ((size_t)b * T_ + (size_t)kt * 64 + r) * C_ + colH + c;
            cp16(sb + 2u * (uint32_t)(st + (sub ? FL_VF : FL_KF) + r * SQ + c),
                 (sub ? vf : kf) + g);
        }
        asm volatile("cp.async.commit_group;");
    };

    const int nkt = qb + 1;
    issueKV(0, 0);
    if (nkt > 1) issueKV(1, 1);

    float m0 = -CUDART_INF_F, m1 = -CUDART_INF_F, l0 = 0.f, l1 = 0.f;
    float oacc[16][4];
    #pragma unroll
    for (int j = 0; j < 16; j++)
        #pragma unroll
        for (int e = 0; e < 4; e++) oacc[j][e] = 0.f;

    for (int kt = 0; kt < nkt; kt++) {
        if (kt + 2 < nkt) { asm volatile("cp.async.wait_group 1;"); }
        else              { asm volatile("cp.async.wait_group 0;"); }
        __syncthreads();
        if (kt + 2 < nkt) issueKV((kt + 2) % 3, kt + 2);

        const int kb = kt * 64;
        const uint32_t stB = sb + 2u * (uint32_t)((kt % 3) * FL_STAGE);

        float sacc[8][4];
        #pragma unroll
        for (int j = 0; j < 8; j++)
            #pragma unroll
            for (int e = 0; e < 4; e++) sacc[j][e] = 0.f;

        #pragma unroll
        for (int c = 0; c < 8; c++) {
            uint32_t bkv[8][2];
            #pragma unroll
            for (int jt = 0; jt < 4; jt++) {
                ldmx4(bkv[2*jt][0], bkv[2*jt][1], bkv[2*jt+1][0], bkv[2*jt+1][1],
                      stB + kbase[jt] + 2u * (uint32_t)(c * 16));
            }
            #pragma unroll
            for (int j = 0; j < 8; j++) mmah16(sacc[j], qr[c], bkv[j]);
        }

        const bool diag = (kb + 63 > gq0);
        const int r0 = gq0 + (lane >> 2), r1 = r0 + 8;
        float tm0 = -CUDART_INF_F, tm1 = -CUDART_INF_F;
        #pragma unroll
        for (int j = 0; j < 8; j++) {
            if (diag) {
                int cc = kb + j * 8 + ((lane & 3) << 1);
                if (cc     > r0) sacc[j][0] = -CUDART_INF_F;
                if (cc + 1 > r0) sacc[j][1] = -CUDART_INF_F;
                if (cc     > r1) sacc[j][2] = -CUDART_INF_F;
                if (cc + 1 > r1) sacc[j][3] = -CUDART_INF_F;
            }
            tm0 = fmaxf(tm0, fmaxf(sacc[j][0], sacc[j][1]));
            tm1 = fmaxf(tm1, fmaxf(sacc[j][2], sacc[j][3]));
        }
        tm0 = fmaxf(tm0, __shfl_xor_sync(0xffffffffu, tm0, 1));
        tm0 = fmaxf(tm0, __shfl_xor_sync(0xffffffffu, tm0, 2));
        tm1 = fmaxf(tm1, __shfl_xor_sync(0xffffffffu, tm1, 1));
        tm1 = fmaxf(tm1, __shfl_xor_sync(0xffffffffu, tm1, 2));
        float mn0 = fmaxf(m0, tm0), mn1 = fmaxf(m1, tm1);
        float a0 = __expf(m0 - mn0), a1 = __expf(m1 - mn1);
        float rs0 = 0.f, rs1 = 0.f;
        #pragma unroll
        for (int j = 0; j < 8; j++) {
            float p0 = __expf(sacc[j][0] - mn0);
            float p1 = __expf(sacc[j][1] - mn0);
            float p2 = __expf(sacc[j][2] - mn1);
            float p3 = __expf(sacc[j][3] - mn1);
            sacc[j][0] = p0; sacc[j][1] = p1; sacc[j][2] = p2; sacc[j][3] = p3;
            rs0 += p0 + p1; rs1 += p2 + p3;
        }
        rs0 += __shfl_xor_sync(0xffffffffu, rs0, 1);
        rs0 += __shfl_xor_sync(0xffffffffu, rs0, 2);
        rs1 += __shfl_xor_sync(0xffffffffu, rs1, 1);
        rs1 += __shfl_xor_sync(0xffffffffu, rs1, 2);
        l0 = l0 * a0 + rs0; l1 = l1 * a1 + rs1;
        m0 = mn0; m1 = mn1;
        #pragma unroll
        for (int j = 0; j < 16; j++) {
            oacc[j][0] *= a0; oacc[j][1] *= a0;
            oacc[j][2] *= a1; oacc[j][3] *= a1;
        }

        uint32_t pf[4][4];
        #pragma unroll
        for (int c = 0; c < 4; c++) {
            pf[c][0] = pack_f16(sacc[2*c][0],   sacc[2*c][1]);
            pf[c][1] = pack_f16(sacc[2*c][2],   sacc[2*c][3]);
            pf[c][2] = pack_f16(sacc[2*c+1][0], sacc[2*c+1][1]);
            pf[c][3] = pack_f16(sacc[2*c+1][2], sacc[2*c+1][3]);
        }

        #pragma unroll
        for (int c = 0; c < 4; c++) {
            #pragma unroll
            for (int dt = 0; dt < 8; dt++) {
                uint32_t bv[4];
                ldmx4t(bv[0], bv[1], bv[2], bv[3],
                       stB + vbase[c] + 2u * (uint32_t)(dt * 16));
                mmah16(oacc[2*dt],   pf[c], bv);
                mmah16(oacc[2*dt+1], pf[c], bv + 2);
            }
        }
    }

    float inv0 = 1.0f / l0, inv1 = 1.0f / l1;
    size_t grow0 = (rowQ + wq + (lane >> 2)) * C_;
    size_t grow1 = grow0 + 8 * C_;
    #pragma unroll
    for (int j = 0; j < 16; j++) {
        int col = colH + j * 8 + ((lane & 3) << 1);
        *(uint32_t*)&of[grow0 + col] = pack_f16(oacc[j][0] * inv0, oacc[j][1] * inv0);
        *(uint32_t*)&of[grow1 + col] = pack_f16(oacc[j][2] * inv1, oacc[j][3] * inv1);
    }
}

// ---------------------------------------------------------------------------
extern "C" void kernel_launch(void* const* d_in, const int* in_sizes, int n_in,
                              void* d_out, int out_size)
{
    (void)in_sizes; (void)n_in; (void)out_size;
    const float* x  = (const float*)d_in[0];
    const float* cs = (const float*)d_in[1];
    const float* sn = (const float*)d_in[2];
    float* out = (float*)d_out;

    __half *xf, *qf, *kf, *vf, *of, *wf;
    cudaGetSymbolAddress((void**)&xf, g_xf);
    cudaGetSymbolAddress((void**)&qf, g_qf);
    cudaGetSymbolAddress((void**)&kf, g_kf);
    cudaGetSymbolAddress((void**)&vf, g_vf);
    cudaGetSymbolAddress((void**)&of, g_of);
    cudaGetSymbolAddress((void**)&wf, g_wf);

    cudaFuncSetAttribute(qkv_gemm, cudaFuncAttributeMaxDynamicSharedMemorySize, G_SMEM);
    cudaFuncSetAttribute(hgemm_o,  cudaFuncAttributeMaxDynamicSharedMemorySize, G_SMEM);
    cudaFuncSetAttribute(flash_f16, cudaFuncAttributeMaxDynamicSharedMemorySize, FLASH_SMEM);

    split_all<<<NTOT4 / (512 * 4), 512>>>((const float4*)x,
        (const float4*)d_in[3], (const float4*)d_in[4],
        (const float4*)d_in[5], (const float4*)d_in[6],
        (uint2*)xf, (uint2*)wf);

    qkv_gemm<<<dim3(48, 64), 256, G_SMEM>>>(xf, wf, cs, sn, qf, kf, vf);

    flash_f16<<<dim3(T_/64, B_*H_), 128, FLASH_SMEM>>>(qf, kf, vf, of);

    hgemm_o<<<dim3(16, 64), 256, G_SMEM>>>(of, wf + 3*(size_t)C_*C_, out, C_, C_);
}